// round 3
// baseline (speedup 1.0000x reference)
#include <cuda_runtime.h>
#include <cstdint>
#include <cstddef>

// ---------------- problem constants ----------------
#define BATCH  2
#define SEQ    2048
#define DMODEL 1024
#define NHEAD  16
#define DK     64
#define MROWS  (BATCH * SEQ)   // 4096
#define KDIM   1024

// ---------------- scratch (no cudaMalloc allowed) ----------------
__device__ float g_q[BATCH * NHEAD * SEQ * DK];
__device__ float g_k[BATCH * NHEAD * SEQ * DK];
__device__ float g_v[BATCH * NHEAD * SEQ * DK];
__device__ float g_attn[MROWS * DMODEL];         // attn out, tf32-rounded
__device__ float g_xr[MROWS * DMODEL];           // x rounded to tf32
__device__ float g_wq[DMODEL * DMODEL];
__device__ float g_wk[DMODEL * DMODEL];
__device__ float g_wv[DMODEL * DMODEL];
__device__ float g_wo[DMODEL * DMODEL];

// ---------------- helpers ----------------
__device__ __forceinline__ uint32_t smem_u32(const void* p) {
    uint32_t a;
    asm("{ .reg .u64 t; cvta.to.shared.u64 t, %1; cvt.u32.u64 %0, t; }"
        : "=r"(a) : "l"(p));
    return a;
}

__device__ __forceinline__ float tf32_round(float x) {
    uint32_t u;
    asm("cvt.rna.tf32.f32 %0, %1;" : "=r"(u) : "f"(x));
    return __uint_as_float(u);
}

#define CP_ASYNC16(dst_u32, src_ptr) \
    asm volatile("cp.async.cg.shared.global [%0], [%1], 16;" \
        :: "r"(dst_u32), "l"((const void*)(src_ptr)) : "memory")
#define CP_COMMIT() asm volatile("cp.async.commit_group;" ::: "memory")
#define CP_WAIT(n)  asm volatile("cp.async.wait_group %0;" :: "n"(n) : "memory")

__device__ __forceinline__ void mma_tf32(float c[4], uint32_t a0, uint32_t a1,
                                         uint32_t a2, uint32_t a3,
                                         uint32_t b0, uint32_t b1) {
    asm volatile(
        "mma.sync.aligned.m16n8k8.row.col.f32.tf32.tf32.f32 "
        "{%0,%1,%2,%3}, {%4,%5,%6,%7}, {%8,%9}, {%0,%1,%2,%3};"
        : "+f"(c[0]), "+f"(c[1]), "+f"(c[2]), "+f"(c[3])
        : "r"(a0), "r"(a1), "r"(a2), "r"(a3), "r"(b0), "r"(b1));
}

// ---------------- tf32 round pre-pass ----------------
__global__ void round_tf32_kernel(const float* __restrict__ in,
                                  float* __restrict__ out, int n4) {
    int i = blockIdx.x * blockDim.x + threadIdx.x;
    if (i < n4) {
        float4 v = ((const float4*)in)[i];
        v.x = tf32_round(v.x); v.y = tf32_round(v.y);
        v.z = tf32_round(v.z); v.w = tf32_round(v.w);
        ((float4*)out)[i] = v;
    }
}

// ---------------- TF32 mma.sync GEMM: C = A(4096xK) * W(NxK)^T + bias -------
// 128x128x32 CTA tile, 256 threads (8 warps, 2x4), warp tile 64x32.
// Padded smem rows (stride 36 floats) -> conflict-free fragment LDS.
// Double-buffered cp.async. A/W must be pre-rounded to tf32.
#define GBK 32
#define GRS 36                        // padded row stride (floats)
#define G_TILE_FLOATS (128 * GRS)     // 4608 floats = 18432 B
#define G_STAGE_FLOATS (2 * G_TILE_FLOATS)
#define G_SMEM_TOTAL (2 * G_STAGE_FLOATS * 4)   // 73728 B

__device__ __forceinline__ void gemm_load_tile(
    const float* __restrict__ A, const float* __restrict__ W,
    int bm, int bn, uint32_t smem_base, int tid, int k0, int s)
{
    const int r = tid >> 1;
    const int cb = (tid & 1) * 16;
    const uint32_t sa = smem_base + (uint32_t)(s * G_STAGE_FLOATS) * 4;
    const uint32_t sb = sa + (uint32_t)G_TILE_FLOATS * 4;
    const float* Ap = A + (size_t)(bm + r) * KDIM + k0 + cb;
    const float* Wp = W + (size_t)(bn + r) * KDIM + k0 + cb;
    const uint32_t so = (uint32_t)(r * GRS + cb) * 4;
#pragma unroll
    for (int j = 0; j < 4; j++) {
        CP_ASYNC16(sa + so + j * 16, Ap + j * 4);
        CP_ASYNC16(sb + so + j * 16, Wp + j * 4);
    }
}

__global__ void __launch_bounds__(256, 2) gemm_tf32(
    const float* __restrict__ A, const float* __restrict__ W,
    const float* __restrict__ bias, float* __restrict__ C, int headLayout)
{
    extern __shared__ float smem[];
    const uint32_t smem_base = smem_u32(smem);
    const int tid = threadIdx.x;
    const int wid = tid >> 5;
    const int lane = tid & 31;
    const int G = lane >> 2;         // group id 0..7
    const int T = lane & 3;          // thread-in-group 0..3
    const int wm = (wid >> 2) * 64;  // warp m offset
    const int wn = (wid & 3) * 32;   // warp n offset
    const int bm = blockIdx.y * 128;
    const int bn = blockIdx.x * 128;

    float c[4][4][4];
#pragma unroll
    for (int mt = 0; mt < 4; mt++)
#pragma unroll
        for (int nt = 0; nt < 4; nt++)
#pragma unroll
            for (int i = 0; i < 4; i++) c[mt][nt][i] = 0.0f;

    gemm_load_tile(A, W, bm, bn, smem_base, tid, 0, 0);
    CP_COMMIT();

    const int NIT = KDIM / GBK;   // 32
    for (int k = 0; k < NIT; k++) {
        if (k + 1 < NIT) {
            gemm_load_tile(A, W, bm, bn, smem_base, tid, (k + 1) * GBK, (k + 1) & 1);
            CP_COMMIT();
            CP_WAIT(1);
        } else {
            CP_WAIT(0);
        }
        __syncthreads();

        const float* As = smem + (k & 1) * G_STAGE_FLOATS;
        const float* Bs = As + G_TILE_FLOATS;

#pragma unroll
        for (int ko = 0; ko < GBK; ko += 8) {
            uint32_t a[4][4], b[4][2];
#pragma unroll
            for (int mt = 0; mt < 4; mt++) {
                const int r0 = wm + mt * 16 + G;
                a[mt][0] = __float_as_uint(As[r0 * GRS + ko + T]);
                a[mt][1] = __float_as_uint(As[(r0 + 8) * GRS + ko + T]);
                a[mt][2] = __float_as_uint(As[r0 * GRS + ko + T + 4]);
                a[mt][3] = __float_as_uint(As[(r0 + 8) * GRS + ko + T + 4]);
            }
#pragma unroll
            for (int nt = 0; nt < 4; nt++) {
                const int n0 = wn + nt * 8 + G;
                b[nt][0] = __float_as_uint(Bs[n0 * GRS + ko + T]);
                b[nt][1] = __float_as_uint(Bs[n0 * GRS + ko + T + 4]);
            }
#pragma unroll
            for (int mt = 0; mt < 4; mt++)
#pragma unroll
                for (int nt = 0; nt < 4; nt++)
                    mma_tf32(c[mt][nt], a[mt][0], a[mt][1], a[mt][2], a[mt][3],
                             b[nt][0], b[nt][1]);
        }
        __syncthreads();
    }

    // epilogue
#pragma unroll
    for (int mt = 0; mt < 4; mt++) {
#pragma unroll
        for (int half = 0; half < 2; half++) {
            const int gm = bm + wm + mt * 16 + G + half * 8;
            const int b_ = gm >> 11;
            const int s_ = gm & 2047;
#pragma unroll
            for (int nt = 0; nt < 4; nt++) {
                const int gn = bn + wn + nt * 8 + 2 * T;
                float2 bv = *(const float2*)&bias[gn];
                float2 v;
                v.x = c[mt][nt][half * 2 + 0] + bv.x;
                v.y = c[mt][nt][half * 2 + 1] + bv.y;
                if (headLayout) {
                    const int h = gn >> 6, d = gn & 63;
                    *(float2*)&C[(((size_t)(b_ * NHEAD + h) * SEQ) + s_) * DK + d] = v;
                } else {
                    *(float2*)&C[(size_t)gm * DMODEL + gn] = v;
                }
            }
        }
    }
}

// ---------------- Flash attention (fp32, 8x4 tile) ----------------
#define AT_QS 0            // Qs[d][r] : 64 x 128 floats, 32KB
#define AT_KV 32768        // KV       : 64 x 64 floats,  16KB
#define AT_PS 49152        // Ps[r][j] : 128 x 64 floats, 32KB
#define AT_SMEM_TOTAL 81920

__global__ void __launch_bounds__(256, 2) attn_kernel(
    const float* __restrict__ Qg, const float* __restrict__ Kg,
    const float* __restrict__ Vg, float* __restrict__ Og)
{
    extern __shared__ char smem_raw[];
    float* Qs = (float*)(smem_raw + AT_QS);
    float* KV = (float*)(smem_raw + AT_KV);
    float* Ps = (float*)(smem_raw + AT_PS);

    const int tid = threadIdx.x;
    const int bh = blockIdx.y;
    const int q0 = blockIdx.x * 128;

    const float* Qb = Qg + ((size_t)bh * SEQ + q0) * DK;
    const float* Kb = Kg + (size_t)bh * SEQ * DK;
    const float* Vb = Vg + (size_t)bh * SEQ * DK;

    // load Q tile transposed: Qs[d*128 + r]
    {
        const int r = tid >> 1;
        const int c0 = (tid & 1) * 32;
        const float* p = Qb + r * DK + c0;
#pragma unroll
        for (int i = 0; i < 32; i += 4) {
            float4 v = *(const float4*)(p + i);
            Qs[(c0 + i + 0) * 128 + r] = v.x;
            Qs[(c0 + i + 1) * 128 + r] = v.y;
            Qs[(c0 + i + 2) * 128 + r] = v.z;
            Qs[(c0 + i + 3) * 128 + r] = v.w;
        }
    }

    const int tx = tid & 15;
    const int ty = tid >> 4;

    float m_i[8], l_i[8], acc[8][4];
#pragma unroll
    for (int i = 0; i < 8; i++) {
        m_i[i] = -1e30f; l_i[i] = 0.0f;
#pragma unroll
        for (int j = 0; j < 4; j++) acc[i][j] = 0.0f;
    }

    for (int kt = 0; kt < SEQ; kt += 64) {
        __syncthreads();
        // K tile transposed: KV[d*64 + c]
        {
            const int c = tid >> 2;
            const int d0 = (tid & 3) * 16;
            const float* p = Kb + (size_t)(kt + c) * DK + d0;
#pragma unroll
            for (int i = 0; i < 16; i += 4) {
                float4 v = *(const float4*)(p + i);
                KV[(d0 + i + 0) * 64 + c] = v.x;
                KV[(d0 + i + 1) * 64 + c] = v.y;
                KV[(d0 + i + 2) * 64 + c] = v.z;
                KV[(d0 + i + 3) * 64 + c] = v.w;
            }
        }
        __syncthreads();

        // phase A: scores 8x4
        float s[8][4];
#pragma unroll
        for (int i = 0; i < 8; i++)
#pragma unroll
            for (int j = 0; j < 4; j++) s[i][j] = 0.0f;

#pragma unroll 8
        for (int d = 0; d < DK; d++) {
            float4 q0v = *(const float4*)&Qs[d * 128 + ty * 8];
            float4 q1v = *(const float4*)&Qs[d * 128 + ty * 8 + 4];
            float4 kv  = *(const float4*)&KV[d * 64 + tx * 4];
            float q[8] = {q0v.x, q0v.y, q0v.z, q0v.w, q1v.x, q1v.y, q1v.z, q1v.w};
            float kk[4] = {kv.x, kv.y, kv.z, kv.w};
#pragma unroll
            for (int i = 0; i < 8; i++)
#pragma unroll
                for (int j = 0; j < 4; j++)
                    s[i][j] = fmaf(q[i], kk[j], s[i][j]);
        }

        // online softmax
        float fac[8];
#pragma unroll
        for (int i = 0; i < 8; i++) {
            float mx = fmaxf(fmaxf(s[i][0], s[i][1]), fmaxf(s[i][2], s[i][3])) * 0.125f;
            mx = fmaxf(mx, __shfl_xor_sync(0xffffffffu, mx, 1));
            mx = fmaxf(mx, __shfl_xor_sync(0xffffffffu, mx, 2));
            mx = fmaxf(mx, __shfl_xor_sync(0xffffffffu, mx, 4));
            mx = fmaxf(mx, __shfl_xor_sync(0xffffffffu, mx, 8));
            const float mn = fmaxf(m_i[i], mx);
            fac[i] = __expf(m_i[i] - mn);
            m_i[i] = mn;
            float ls = 0.0f;
#pragma unroll
            for (int j = 0; j < 4; j++) {
                const float p = __expf(fmaf(s[i][j], 0.125f, -mn));
                s[i][j] = p;
                ls += p;
            }
            ls += __shfl_xor_sync(0xffffffffu, ls, 1);
            ls += __shfl_xor_sync(0xffffffffu, ls, 2);
            ls += __shfl_xor_sync(0xffffffffu, ls, 4);
            ls += __shfl_xor_sync(0xffffffffu, ls, 8);
            l_i[i] = l_i[i] * fac[i] + ls;
        }

        __syncthreads();   // K reads done before KV overwrite

        // store P, load V (KV[j*64 + d])
#pragma unroll
        for (int i = 0; i < 8; i++)
#pragma unroll
            for (int j = 0; j < 4; j++)
                Ps[(ty * 8 + i) * 64 + tx * 4 + j] = s[i][j];
        {
            const int j = tid >> 2;
            const int d0 = (tid & 3) * 16;
            const float* p = Vb + (size_t)(kt + j) * DK + d0;
#pragma unroll
            for (int i = 0; i < 16; i += 4)
                *(float4*)&KV[j * 64 + d0 + i] = *(const float4*)(p + i);
        }
        __syncthreads();

        // phase B: O += P * V
#pragma unroll
        for (int i = 0; i < 8; i++)
#pragma unroll
            for (int j = 0; j < 4; j++) acc[i][j] *= fac[i];

#pragma unroll 4
        for (int j = 0; j < 64; j++) {
            float4 vv = *(const float4*)&KV[j * 64 + tx * 4];
            float v[4] = {vv.x, vv.y, vv.z, vv.w};
            float p[8];
#pragma unroll
            for (int i = 0; i < 8; i++) p[i] = Ps[(ty * 8 + i) * 64 + j];
#pragma unroll
            for (int i = 0; i < 8; i++)
#pragma unroll
                for (int d = 0; d < 4; d++)
                    acc[i][d] = fmaf(p[i], v[d], acc[i][d]);
        }
    }

    // epilogue: normalize, tf32-round (feeds TF32 output GEMM), write [B,S,D]
    const int b = bh >> 4;
    const int h = bh & 15;
#pragma unroll
    for (int i = 0; i < 8; i++) {
        const float inv = 1.0f / l_i[i];
        const int r = q0 + ty * 8 + i;
        float4 o;
        o.x = tf32_round(acc[i][0] * inv);
        o.y = tf32_round(acc[i][1] * inv);
        o.z = tf32_round(acc[i][2] * inv);
        o.w = tf32_round(acc[i][3] * inv);
        float* op = Og + ((size_t)b * SEQ + r) * DMODEL + h * DK + tx * 4;
        *(float4*)op = o;
    }
}

// ---------------- launch ----------------
extern "C" void kernel_launch(void* const* d_in, const int* in_sizes, int n_in,
                              void* d_out, int out_size)
{
    const float* x  = (const float*)d_in[0];
    const float* Wq = (const float*)d_in[1];
    const float* bq = (const float*)d_in[2];
    const float* Wk = (const float*)d_in[3];
    const float* bk = (const float*)d_in[4];
    const float* Wv = (const float*)d_in[5];
    const float* bv = (const float*)d_in[6];
    const float* Wo = (const float*)d_in[7];
    const float* bo = (const float*)d_in[8];
    float* out = (float*)d_out;

    float *gq, *gk, *gv, *ga, *gxr, *gwq, *gwk, *gwv, *gwo;
    cudaGetSymbolAddress((void**)&gq,  g_q);
    cudaGetSymbolAddress((void**)&gk,  g_k);
    cudaGetSymbolAddress((void**)&gv,  g_v);
    cudaGetSymbolAddress((void**)&ga,  g_attn);
    cudaGetSymbolAddress((void**)&gxr, g_xr);
    cudaGetSymbolAddress((void**)&gwq, g_wq);
    cudaGetSymbolAddress((void**)&gwk, g_wk);
    cudaGetSymbolAddress((void**)&gwv, g_wv);
    cudaGetSymbolAddress((void**)&gwo, g_wo);

    cudaFuncSetAttribute(gemm_tf32, cudaFuncAttributeMaxDynamicSharedMemorySize,
                         G_SMEM_TOTAL);
    cudaFuncSetAttribute(attn_kernel, cudaFuncAttributeMaxDynamicSharedMemorySize,
                         AT_SMEM_TOTAL);

    // tf32 pre-rounding (RNA, unbiased)
    {
        const int nx4 = (MROWS * DMODEL) / 4;
        const int nw4 = (DMODEL * DMODEL) / 4;
        round_tf32_kernel<<<(nx4 + 255) / 256, 256>>>(x,  gxr, nx4);
        round_tf32_kernel<<<(nw4 + 255) / 256, 256>>>(Wq, gwq, nw4);
        round_tf32_kernel<<<(nw4 + 255) / 256, 256>>>(Wk, gwk, nw4);
        round_tf32_kernel<<<(nw4 + 255) / 256, 256>>>(Wv, gwv, nw4);
        round_tf32_kernel<<<(nw4 + 255) / 256, 256>>>(Wo, gwo, nw4);
    }

    dim3 gp(DMODEL / 128, MROWS / 128);   // (8, 32)
    gemm_tf32<<<gp, 256, G_SMEM_TOTAL>>>(gxr, gwq, bq, gq, 1);
    gemm_tf32<<<gp, 256, G_SMEM_TOTAL>>>(gxr, gwk, bk, gk, 1);
    gemm_tf32<<<gp, 256, G_SMEM_TOTAL>>>(gxr, gwv, bv, gv, 1);

    attn_kernel<<<dim3(SEQ / 128, BATCH * NHEAD), 256, AT_SMEM_TOTAL>>>(gq, gk, gv, ga);

    gemm_tf32<<<gp, 256, G_SMEM_TOTAL>>>(ga, gwo, bo, out, 0);
}

// round 4
// speedup vs baseline: 1.9257x; 1.9257x over previous
#include <cuda_runtime.h>
#include <cstdint>
#include <cstddef>

// ---------------- problem constants ----------------
#define BATCH  2
#define SEQ    2048
#define DMODEL 1024
#define NHEAD  16
#define DK     64
#define MROWS  (BATCH * SEQ)   // 4096
#define KDIM   1024

// ---------------- scratch (no cudaMalloc allowed) ----------------
__device__ float g_q[BATCH * NHEAD * SEQ * DK];
__device__ float g_k[BATCH * NHEAD * SEQ * DK];
__device__ float g_v[BATCH * NHEAD * SEQ * DK];
__device__ float g_ahi[MROWS * DMODEL];   // attn out hi (tf32)
__device__ float g_alo[MROWS * DMODEL];   // attn out lo (tf32)
__device__ float g_xhi[MROWS * DMODEL];
__device__ float g_xlo[MROWS * DMODEL];
__device__ float g_wqh[DMODEL * DMODEL];
__device__ float g_wql[DMODEL * DMODEL];
__device__ float g_wkh[DMODEL * DMODEL];
__device__ float g_wkl[DMODEL * DMODEL];
__device__ float g_wvh[DMODEL * DMODEL];
__device__ float g_wvl[DMODEL * DMODEL];
__device__ float g_woh[DMODEL * DMODEL];
__device__ float g_wol[DMODEL * DMODEL];

// ---------------- helpers ----------------
__device__ __forceinline__ uint32_t smem_u32(const void* p) {
    uint32_t a;
    asm("{ .reg .u64 t; cvta.to.shared.u64 t, %1; cvt.u32.u64 %0, t; }"
        : "=r"(a) : "l"(p));
    return a;
}

__device__ __forceinline__ float tf32_round(float x) {
    uint32_t u;
    asm("cvt.rna.tf32.f32 %0, %1;" : "=r"(u) : "f"(x));
    return __uint_as_float(u);
}

#define CP_ASYNC16(dst_u32, src_ptr) \
    asm volatile("cp.async.cg.shared.global [%0], [%1], 16;" \
        :: "r"(dst_u32), "l"((const void*)(src_ptr)) : "memory")
#define CP_COMMIT() asm volatile("cp.async.commit_group;" ::: "memory")
#define CP_WAIT(n)  asm volatile("cp.async.wait_group %0;" :: "n"(n) : "memory")

__device__ __forceinline__ void mma_tf32(float c[4], uint32_t a0, uint32_t a1,
                                         uint32_t a2, uint32_t a3,
                                         uint32_t b0, uint32_t b1) {
    asm volatile(
        "mma.sync.aligned.m16n8k8.row.col.f32.tf32.tf32.f32 "
        "{%0,%1,%2,%3}, {%4,%5,%6,%7}, {%8,%9}, {%0,%1,%2,%3};"
        : "+f"(c[0]), "+f"(c[1]), "+f"(c[2]), "+f"(c[3])
        : "r"(a0), "r"(a1), "r"(a2), "r"(a3), "r"(b0), "r"(b1));
}

// ---------------- hi/lo tf32 split pre-pass ----------------
__global__ void round_split_kernel(const float* __restrict__ in,
                                   float* __restrict__ hi,
                                   float* __restrict__ lo, int n4) {
    int i = blockIdx.x * blockDim.x + threadIdx.x;
    if (i < n4) {
        float4 v = ((const float4*)in)[i];
        float4 h, l;
        h.x = tf32_round(v.x); l.x = tf32_round(v.x - h.x);
        h.y = tf32_round(v.y); l.y = tf32_round(v.y - h.y);
        h.z = tf32_round(v.z); l.z = tf32_round(v.z - h.z);
        h.w = tf32_round(v.w); l.w = tf32_round(v.w - h.w);
        ((float4*)hi)[i] = h;
        ((float4*)lo)[i] = l;
    }
}

// ---------------- 3xTF32 GEMM: C = A(4096xK) * W(NxK)^T + bias --------------
// C = Ah*Bh + Al*Bh + Ah*Bl  (inputs pre-split into tf32 hi/lo)
// 128x128x16 CTA tile, 256 threads (8 warps 2x4), warp tile 64x32.
#define GBK2 16
#define GRS2 20                       // padded row stride (floats)
#define G2_TILE (128 * GRS2)          // 2560 floats
#define G2_STAGE (4 * G2_TILE)        // Ah, Al, Bh, Bl
#define G2_SMEM (2 * G2_STAGE * 4)    // 81920 B

__device__ __forceinline__ void gemm3_load(
    const float* __restrict__ Ah, const float* __restrict__ Al,
    const float* __restrict__ Wh, const float* __restrict__ Wl,
    int bm, int bn, uint32_t base, int tid, int k0, int s)
{
    const int c = tid & 3;
    const int r = tid >> 2;           // 0..63
    const uint32_t st = base + (uint32_t)(s * G2_STAGE) * 4;
    const uint32_t so = (uint32_t)(r * GRS2 + c * 4) * 4;
    const uint32_t rowskip = (uint32_t)(64 * GRS2) * 4;
    const float* srcs[4] = {
        Ah + (size_t)(bm + r) * KDIM + k0 + c * 4,
        Al + (size_t)(bm + r) * KDIM + k0 + c * 4,
        Wh + (size_t)(bn + r) * KDIM + k0 + c * 4,
        Wl + (size_t)(bn + r) * KDIM + k0 + c * 4 };
#pragma unroll
    for (int t = 0; t < 4; t++) {
        const uint32_t dst = st + (uint32_t)(t * G2_TILE) * 4 + so;
        CP_ASYNC16(dst, srcs[t]);
        CP_ASYNC16(dst + rowskip, srcs[t] + (size_t)64 * KDIM);
    }
}

__global__ void __launch_bounds__(256) gemm3_tf32(
    const float* __restrict__ Ah, const float* __restrict__ Al,
    const float* __restrict__ Wh, const float* __restrict__ Wl,
    const float* __restrict__ bias, float* __restrict__ C, int headLayout)
{
    extern __shared__ float smem[];
    const uint32_t base = smem_u32(smem);
    const int tid = threadIdx.x;
    const int wid = tid >> 5;
    const int lane = tid & 31;
    const int G = lane >> 2;
    const int T = lane & 3;
    const int wm = (wid >> 2) * 64;
    const int wn = (wid & 3) * 32;
    const int bm = blockIdx.y * 128;
    const int bn = blockIdx.x * 128;

    float c[4][4][4];
#pragma unroll
    for (int mt = 0; mt < 4; mt++)
#pragma unroll
        for (int nt = 0; nt < 4; nt++)
#pragma unroll
            for (int i = 0; i < 4; i++) c[mt][nt][i] = 0.0f;

    gemm3_load(Ah, Al, Wh, Wl, bm, bn, base, tid, 0, 0);
    CP_COMMIT();

    const int NIT = KDIM / GBK2;   // 64
    for (int k = 0; k < NIT; k++) {
        if (k + 1 < NIT) {
            gemm3_load(Ah, Al, Wh, Wl, bm, bn, base, tid, (k + 1) * GBK2, (k + 1) & 1);
            CP_COMMIT();
            CP_WAIT(1);
        } else {
            CP_WAIT(0);
        }
        __syncthreads();

        const float* Ahs = smem + (k & 1) * G2_STAGE;
        const float* Als = Ahs + G2_TILE;
        const float* Bhs = Als + G2_TILE;
        const float* Bls = Bhs + G2_TILE;

#pragma unroll
        for (int ko = 0; ko < GBK2; ko += 8) {
            uint32_t bh_[4][2], bl_[4][2];
#pragma unroll
            for (int nt = 0; nt < 4; nt++) {
                const int n0 = (wn + nt * 8 + G) * GRS2 + ko + T;
                bh_[nt][0] = __float_as_uint(Bhs[n0]);
                bh_[nt][1] = __float_as_uint(Bhs[n0 + 4]);
                bl_[nt][0] = __float_as_uint(Bls[n0]);
                bl_[nt][1] = __float_as_uint(Bls[n0 + 4]);
            }
#pragma unroll
            for (int mt = 0; mt < 4; mt++) {
                const int r0 = (wm + mt * 16 + G) * GRS2 + ko + T;
                const int r1 = (wm + mt * 16 + G + 8) * GRS2 + ko + T;
                uint32_t ah0 = __float_as_uint(Ahs[r0]);
                uint32_t ah1 = __float_as_uint(Ahs[r1]);
                uint32_t ah2 = __float_as_uint(Ahs[r0 + 4]);
                uint32_t ah3 = __float_as_uint(Ahs[r1 + 4]);
                uint32_t al0 = __float_as_uint(Als[r0]);
                uint32_t al1 = __float_as_uint(Als[r1]);
                uint32_t al2 = __float_as_uint(Als[r0 + 4]);
                uint32_t al3 = __float_as_uint(Als[r1 + 4]);
#pragma unroll
                for (int nt = 0; nt < 4; nt++) {
                    mma_tf32(c[mt][nt], ah0, ah1, ah2, ah3, bh_[nt][0], bh_[nt][1]);
                    mma_tf32(c[mt][nt], al0, al1, al2, al3, bh_[nt][0], bh_[nt][1]);
                    mma_tf32(c[mt][nt], ah0, ah1, ah2, ah3, bl_[nt][0], bl_[nt][1]);
                }
            }
        }
        __syncthreads();
    }

    // epilogue (fragment layout: rows G,G+8 ; cols 2T,2T+1 per n-tile)
#pragma unroll
    for (int mt = 0; mt < 4; mt++) {
#pragma unroll
        for (int half = 0; half < 2; half++) {
            const int gm = bm + wm + mt * 16 + G + half * 8;
            const int b_ = gm >> 11;
            const int s_ = gm & 2047;
#pragma unroll
            for (int nt = 0; nt < 4; nt++) {
                const int gn = bn + wn + nt * 8 + 2 * T;
                float2 bv = *(const float2*)&bias[gn];
                float2 v;
                v.x = c[mt][nt][half * 2 + 0] + bv.x;
                v.y = c[mt][nt][half * 2 + 1] + bv.y;
                if (headLayout) {
                    const int h = gn >> 6, d = gn & 63;
                    *(float2*)&C[(((size_t)(b_ * NHEAD + h) * SEQ) + s_) * DK + d] = v;
                } else {
                    *(float2*)&C[(size_t)gm * DMODEL + gn] = v;
                }
            }
        }
    }
}

// ---------------- TF32 mma flash attention ----------------
// grid (SEQ/128, B*H), 256 threads, 8 warps x m16 row tiles. BKV = 64.
// smem stride 68 floats -> all fragment LDS conflict-free (bank = 4G+T).
#define AST 68
#define A_QS 0
#define A_KS (128 * AST)
#define A_VS (A_KS + 64 * AST)
#define A_PS (A_VS + 64 * AST)
#define A_SMEM ((A_PS + 128 * AST) * 4)   // 104448 B

__global__ void __launch_bounds__(256) attn_mma(
    const float* __restrict__ Qg, const float* __restrict__ Kg,
    const float* __restrict__ Vg, float* __restrict__ Ohi,
    float* __restrict__ Olo)
{
    extern __shared__ float sm[];
    float* Qs = sm + A_QS;    // [128][AST]  q rows, pre-scaled by 1/8, tf32
    float* Ks = sm + A_KS;    // [64][AST]   kv rows x d, tf32
    float* Vs = sm + A_VS;    // [64][AST]   d rows x kv (transposed), tf32
    float* Ps = sm + A_PS;    // [128][AST]  probabilities, tf32

    const int tid = threadIdx.x;
    const int w = tid >> 5;
    const int lane = tid & 31;
    const int G = lane >> 2;
    const int T = lane & 3;
    const int bh = blockIdx.y;
    const int q0 = blockIdx.x * 128;
    const int wrow = w * 16;

    const float* Qb = Qg + ((size_t)bh * SEQ + q0) * DK;
    const float* Kb = Kg + (size_t)bh * SEQ * DK;
    const float* Vb = Vg + (size_t)bh * SEQ * DK;

    // load Q tile: Qs[r][d], scaled by 0.125, tf32-rounded
    {
        const int r = tid >> 1;
        const int dh = (tid & 1) * 32;
        const float* p = Qb + r * DK + dh;
#pragma unroll
        for (int i = 0; i < 32; i += 4) {
            float4 v = *(const float4*)(p + i);
            float4 o;
            o.x = tf32_round(v.x * 0.125f);
            o.y = tf32_round(v.y * 0.125f);
            o.z = tf32_round(v.z * 0.125f);
            o.w = tf32_round(v.w * 0.125f);
            *(float4*)&Qs[r * AST + dh + i] = o;
        }
    }

    float m_i[2] = {-1e30f, -1e30f};
    float l_i[2] = {0.0f, 0.0f};
    float acc[8][4];
#pragma unroll
    for (int dt = 0; dt < 8; dt++)
#pragma unroll
        for (int i = 0; i < 4; i++) acc[dt][i] = 0.0f;

    for (int kt = 0; kt < SEQ; kt += 64) {
        __syncthreads();   // prior iteration's Ks/Vs reads complete
        // K loader: thread d = tid&63, rows kv0..kv0+15 (conflict-free STS)
        {
            const int d = tid & 63;
            const int kv0 = (tid >> 6) << 4;
            const float* kp = Kb + (size_t)(kt + kv0) * DK + d;
#pragma unroll
            for (int j = 0; j < 16; j++)
                Ks[(kv0 + j) * AST + d] = tf32_round(kp[(size_t)j * DK]);
        }
        // V loader (transposed): thread kv = tid&63, d0..d0+15 (conflict-free STS)
        {
            const int kv = tid & 63;
            const int d0 = (tid >> 6) << 4;
            const float* vp = Vb + (size_t)(kt + kv) * DK + d0;
#pragma unroll
            for (int j = 0; j < 16; j += 4) {
                float4 v = *(const float4*)(vp + j);
                Vs[(d0 + j + 0) * AST + kv] = tf32_round(v.x);
                Vs[(d0 + j + 1) * AST + kv] = tf32_round(v.y);
                Vs[(d0 + j + 2) * AST + kv] = tf32_round(v.z);
                Vs[(d0 + j + 3) * AST + kv] = tf32_round(v.w);
            }
        }
        __syncthreads();

        // ---- QK^T: scores s[nt][4], rows wrow+G / wrow+G+8, cols nt*8+2T(+1)
        float s[8][4];
#pragma unroll
        for (int nt = 0; nt < 8; nt++)
#pragma unroll
            for (int i = 0; i < 4; i++) s[nt][i] = 0.0f;

#pragma unroll
        for (int ko = 0; ko < DK; ko += 8) {
            const int r0 = (wrow + G) * AST + ko + T;
            const int r1 = (wrow + G + 8) * AST + ko + T;
            uint32_t a0 = __float_as_uint(Qs[r0]);
            uint32_t a1 = __float_as_uint(Qs[r1]);
            uint32_t a2 = __float_as_uint(Qs[r0 + 4]);
            uint32_t a3 = __float_as_uint(Qs[r1 + 4]);
#pragma unroll
            for (int nt = 0; nt < 8; nt++) {
                const int n0 = (nt * 8 + G) * AST + ko + T;
                uint32_t b0 = __float_as_uint(Ks[n0]);
                uint32_t b1 = __float_as_uint(Ks[n0 + 4]);
                mma_tf32(s[nt], a0, a1, a2, a3, b0, b1);
            }
        }

        // ---- online softmax (2 rows per thread; quad = lanes sharing G)
        float fac[2];
#pragma unroll
        for (int r = 0; r < 2; r++) {
            float mx = -1e30f;
#pragma unroll
            for (int nt = 0; nt < 8; nt++)
                mx = fmaxf(mx, fmaxf(s[nt][2 * r], s[nt][2 * r + 1]));
            mx = fmaxf(mx, __shfl_xor_sync(0xffffffffu, mx, 1));
            mx = fmaxf(mx, __shfl_xor_sync(0xffffffffu, mx, 2));
            const float mn = fmaxf(m_i[r], mx);
            fac[r] = __expf(m_i[r] - mn);
            m_i[r] = mn;
            float ls = 0.0f;
#pragma unroll
            for (int nt = 0; nt < 8; nt++) {
                float p0 = tf32_round(__expf(s[nt][2 * r + 0] - mn));
                float p1 = tf32_round(__expf(s[nt][2 * r + 1] - mn));
                s[nt][2 * r + 0] = p0;
                s[nt][2 * r + 1] = p1;
                ls += p0 + p1;
            }
            ls += __shfl_xor_sync(0xffffffffu, ls, 1);
            ls += __shfl_xor_sync(0xffffffffu, ls, 2);
            l_i[r] = l_i[r] * fac[r] + ls;
        }

        // ---- store P (warp-private rows)
#pragma unroll
        for (int nt = 0; nt < 8; nt++) {
            *(float2*)&Ps[(wrow + G) * AST + nt * 8 + 2 * T] =
                make_float2(s[nt][0], s[nt][1]);
            *(float2*)&Ps[(wrow + G + 8) * AST + nt * 8 + 2 * T] =
                make_float2(s[nt][2], s[nt][3]);
        }
        __syncwarp();

        // ---- rescale accumulators
#pragma unroll
        for (int dt = 0; dt < 8; dt++) {
            acc[dt][0] *= fac[0];
            acc[dt][1] *= fac[0];
            acc[dt][2] *= fac[1];
            acc[dt][3] *= fac[1];
        }

        // ---- PV: acc += P[16x64] * V^T  (B = Vs[d][kv])
#pragma unroll
        for (int ko = 0; ko < 64; ko += 8) {
            const int r0 = (wrow + G) * AST + ko + T;
            const int r1 = (wrow + G + 8) * AST + ko + T;
            uint32_t a0 = __float_as_uint(Ps[r0]);
            uint32_t a1 = __float_as_uint(Ps[r1]);
            uint32_t a2 = __float_as_uint(Ps[r0 + 4]);
            uint32_t a3 = __float_as_uint(Ps[r1 + 4]);
#pragma unroll
            for (int dt = 0; dt < 8; dt++) {
                const int n0 = (dt * 8 + G) * AST + ko + T;
                uint32_t b0 = __float_as_uint(Vs[n0]);
                uint32_t b1 = __float_as_uint(Vs[n0 + 4]);
                mma_tf32(acc[dt], a0, a1, a2, a3, b0, b1);
            }
        }
    }

    // ---- epilogue: normalize, split hi/lo (feeds 3xTF32 output GEMM)
    const int b = bh >> 4;
    const int h = bh & 15;
    const float inv0 = 1.0f / l_i[0];
    const float inv1 = 1.0f / l_i[1];
    const int r0 = q0 + wrow + G;
    const int r1 = r0 + 8;
    const size_t o0 = ((size_t)b * SEQ + r0) * DMODEL + h * DK;
    const size_t o1 = ((size_t)b * SEQ + r1) * DMODEL + h * DK;
#pragma unroll
    for (int dt = 0; dt < 8; dt++) {
        const int d = dt * 8 + 2 * T;
        float x0 = acc[dt][0] * inv0, y0 = acc[dt][1] * inv0;
        float x1 = acc[dt][2] * inv1, y1 = acc[dt][3] * inv1;
        float2 h0, l0, h1, l1;
        h0.x = tf32_round(x0); l0.x = tf32_round(x0 - h0.x);
        h0.y = tf32_round(y0); l0.y = tf32_round(y0 - h0.y);
        h1.x = tf32_round(x1); l1.x = tf32_round(x1 - h1.x);
        h1.y = tf32_round(y1); l1.y = tf32_round(y1 - h1.y);
        *(float2*)&Ohi[o0 + d] = h0;
        *(float2*)&Olo[o0 + d] = l0;
        *(float2*)&Ohi[o1 + d] = h1;
        *(float2*)&Olo[o1 + d] = l1;
    }
}

// ---------------- launch ----------------
extern "C" void kernel_launch(void* const* d_in, const int* in_sizes, int n_in,
                              void* d_out, int out_size)
{
    const float* x  = (const float*)d_in[0];
    const float* Wq = (const float*)d_in[1];
    const float* bq = (const float*)d_in[2];
    const float* Wk = (const float*)d_in[3];
    const float* bk = (const float*)d_in[4];
    const float* Wv = (const float*)d_in[5];
    const float* bv = (const float*)d_in[6];
    const float* Wo = (const float*)d_in[7];
    const float* bo = (const float*)d_in[8];
    float* out = (float*)d_out;

    float *gq, *gk, *gv, *gah, *gal, *gxh, *gxl;
    float *wqh, *wql, *wkh, *wkl, *wvh, *wvl, *woh, *wol;
    cudaGetSymbolAddress((void**)&gq,  g_q);
    cudaGetSymbolAddress((void**)&gk,  g_k);
    cudaGetSymbolAddress((void**)&gv,  g_v);
    cudaGetSymbolAddress((void**)&gah, g_ahi);
    cudaGetSymbolAddress((void**)&gal, g_alo);
    cudaGetSymbolAddress((void**)&gxh, g_xhi);
    cudaGetSymbolAddress((void**)&gxl, g_xlo);
    cudaGetSymbolAddress((void**)&wqh, g_wqh);
    cudaGetSymbolAddress((void**)&wql, g_wql);
    cudaGetSymbolAddress((void**)&wkh, g_wkh);
    cudaGetSymbolAddress((void**)&wkl, g_wkl);
    cudaGetSymbolAddress((void**)&wvh, g_wvh);
    cudaGetSymbolAddress((void**)&wvl, g_wvl);
    cudaGetSymbolAddress((void**)&woh, g_woh);
    cudaGetSymbolAddress((void**)&wol, g_wol);

    cudaFuncSetAttribute(gemm3_tf32, cudaFuncAttributeMaxDynamicSharedMemorySize,
                         G2_SMEM);
    cudaFuncSetAttribute(attn_mma, cudaFuncAttributeMaxDynamicSharedMemorySize,
                         A_SMEM);

    // hi/lo tf32 splits
    {
        const int nx4 = (MROWS * DMODEL) / 4;
        const int nw4 = (DMODEL * DMODEL) / 4;
        round_split_kernel<<<(nx4 + 255) / 256, 256>>>(x,  gxh, gxl, nx4);
        round_split_kernel<<<(nw4 + 255) / 256, 256>>>(Wq, wqh, wql, nw4);
        round_split_kernel<<<(nw4 + 255) / 256, 256>>>(Wk, wkh, wkl, nw4);
        round_split_kernel<<<(nw4 + 255) / 256, 256>>>(Wv, wvh, wvl, nw4);
        round_split_kernel<<<(nw4 + 255) / 256, 256>>>(Wo, woh, wol, nw4);
    }

    dim3 gp(DMODEL / 128, MROWS / 128);   // (8, 32)
    gemm3_tf32<<<gp, 256, G2_SMEM>>>(gxh, gxl, wqh, wql, bq, gq, 1);
    gemm3_tf32<<<gp, 256, G2_SMEM>>>(gxh, gxl, wkh, wkl, bk, gk, 1);
    gemm3_tf32<<<gp, 256, G2_SMEM>>>(gxh, gxl, wvh, wvl, bv, gv, 1);

    attn_mma<<<dim3(SEQ / 128, BATCH * NHEAD), 256, A_SMEM>>>(gq, gk, gv, gah, gal);

    gemm3_tf32<<<gp, 256, G2_SMEM>>>(gah, gal, woh, wol, bo, out, 0);
}

// round 5
// speedup vs baseline: 1.9892x; 1.0330x over previous
#include <cuda_runtime.h>
#include <cstdint>
#include <cstddef>

// ---------------- problem constants ----------------
#define BATCH  2
#define SEQ    2048
#define DMODEL 1024
#define NHEAD  16
#define DK     64
#define MROWS  (BATCH * SEQ)   // 4096
#define KDIM   1024

// ---------------- scratch (no cudaMalloc allowed) ----------------
__device__ float g_q[BATCH * NHEAD * SEQ * DK];
__device__ float g_k[BATCH * NHEAD * SEQ * DK];
__device__ float g_v[BATCH * NHEAD * SEQ * DK];
__device__ float g_ahi[MROWS * DMODEL];
__device__ float g_alo[MROWS * DMODEL];
__device__ float g_xhi[MROWS * DMODEL];
__device__ float g_xlo[MROWS * DMODEL];
__device__ float g_wqh[DMODEL * DMODEL];
__device__ float g_wql[DMODEL * DMODEL];
__device__ float g_wkh[DMODEL * DMODEL];
__device__ float g_wkl[DMODEL * DMODEL];
__device__ float g_wvh[DMODEL * DMODEL];
__device__ float g_wvl[DMODEL * DMODEL];
__device__ float g_woh[DMODEL * DMODEL];
__device__ float g_wol[DMODEL * DMODEL];

// ---------------- helpers ----------------
__device__ __forceinline__ uint32_t smem_u32(const void* p) {
    uint32_t a;
    asm("{ .reg .u64 t; cvta.to.shared.u64 t, %1; cvt.u32.u64 %0, t; }"
        : "=r"(a) : "l"(p));
    return a;
}

__device__ __forceinline__ float tf32_round(float x) {
    uint32_t u;
    asm("cvt.rna.tf32.f32 %0, %1;" : "=r"(u) : "f"(x));
    return __uint_as_float(u);
}

#define CP_ASYNC16(dst_u32, src_ptr) \
    asm volatile("cp.async.cg.shared.global [%0], [%1], 16;" \
        :: "r"(dst_u32), "l"((const void*)(src_ptr)) : "memory")
#define CP_COMMIT() asm volatile("cp.async.commit_group;" ::: "memory")
#define CP_WAIT(n)  asm volatile("cp.async.wait_group %0;" :: "n"(n) : "memory")

__device__ __forceinline__ void mma_tf32(float c[4], uint32_t a0, uint32_t a1,
                                         uint32_t a2, uint32_t a3,
                                         uint32_t b0, uint32_t b1) {
    asm volatile(
        "mma.sync.aligned.m16n8k8.row.col.f32.tf32.tf32.f32 "
        "{%0,%1,%2,%3}, {%4,%5,%6,%7}, {%8,%9}, {%0,%1,%2,%3};"
        : "+f"(c[0]), "+f"(c[1]), "+f"(c[2]), "+f"(c[3])
        : "r"(a0), "r"(a1), "r"(a2), "r"(a3), "r"(b0), "r"(b1));
}

// ---------------- hi/lo tf32 split pre-pass ----------------
__global__ void round_split_kernel(const float* __restrict__ in,
                                   float* __restrict__ hi,
                                   float* __restrict__ lo, int n4) {
    int i = blockIdx.x * blockDim.x + threadIdx.x;
    if (i < n4) {
        float4 v = ((const float4*)in)[i];
        float4 h, l;
        h.x = tf32_round(v.x); l.x = tf32_round(v.x - h.x);
        h.y = tf32_round(v.y); l.y = tf32_round(v.y - h.y);
        h.z = tf32_round(v.z); l.z = tf32_round(v.z - h.z);
        h.w = tf32_round(v.w); l.w = tf32_round(v.w - h.w);
        ((float4*)hi)[i] = h;
        ((float4*)lo)[i] = l;
    }
}

// ---------------- 3xTF32 GEMM: C = A(4096xK) * W(NxK)^T + bias --------------
// C = Ah*Bh + Al*Bh + Ah*Bl. 128x128x16 CTA tile, 256 threads, warp tile 64x32.
// blockIdx.z selects one of up to 3 (W,bias,C) sets (fused QKV).
#define GBK2 16
#define GRS2 20
#define G2_TILE (128 * GRS2)
#define G2_STAGE (4 * G2_TILE)
#define G2_SMEM (2 * G2_STAGE * 4)    // 81920 B

__device__ __forceinline__ void gemm3_load(
    const float* __restrict__ Ah, const float* __restrict__ Al,
    const float* __restrict__ Wh, const float* __restrict__ Wl,
    int bm, int bn, uint32_t base, int tid, int k0, int s)
{
    const int c = tid & 3;
    const int r = tid >> 2;
    const uint32_t st = base + (uint32_t)(s * G2_STAGE) * 4;
    const uint32_t so = (uint32_t)(r * GRS2 + c * 4) * 4;
    const uint32_t rowskip = (uint32_t)(64 * GRS2) * 4;
    const float* srcs[4] = {
        Ah + (size_t)(bm + r) * KDIM + k0 + c * 4,
        Al + (size_t)(bm + r) * KDIM + k0 + c * 4,
        Wh + (size_t)(bn + r) * KDIM + k0 + c * 4,
        Wl + (size_t)(bn + r) * KDIM + k0 + c * 4 };
#pragma unroll
    for (int t = 0; t < 4; t++) {
        const uint32_t dst = st + (uint32_t)(t * G2_TILE) * 4 + so;
        CP_ASYNC16(dst, srcs[t]);
        CP_ASYNC16(dst + rowskip, srcs[t] + (size_t)64 * KDIM);
    }
}

__global__ void __launch_bounds__(256) gemm3_tf32(
    const float* __restrict__ Ah, const float* __restrict__ Al,
    const float* __restrict__ Wh0, const float* __restrict__ Wl0,
    const float* __restrict__ b0v, float* __restrict__ C0,
    const float* __restrict__ Wh1, const float* __restrict__ Wl1,
    const float* __restrict__ b1v, float* __restrict__ C1,
    const float* __restrict__ Wh2, const float* __restrict__ Wl2,
    const float* __restrict__ b2v, float* __restrict__ C2,
    int headLayout)
{
    extern __shared__ float smem[];
    const uint32_t base = smem_u32(smem);
    const int tid = threadIdx.x;
    const int wid = tid >> 5;
    const int lane = tid & 31;
    const int G = lane >> 2;
    const int T = lane & 3;
    const int wm = (wid >> 2) * 64;
    const int wn = (wid & 3) * 32;
    const int bm = blockIdx.y * 128;
    const int bn = blockIdx.x * 128;
    const int z = blockIdx.z;

    const float* Wh = (z == 0) ? Wh0 : (z == 1) ? Wh1 : Wh2;
    const float* Wl = (z == 0) ? Wl0 : (z == 1) ? Wl1 : Wl2;
    const float* bias = (z == 0) ? b0v : (z == 1) ? b1v : b2v;
    float* C = (z == 0) ? C0 : (z == 1) ? C1 : C2;

    float c[4][4][4];
#pragma unroll
    for (int mt = 0; mt < 4; mt++)
#pragma unroll
        for (int nt = 0; nt < 4; nt++)
#pragma unroll
            for (int i = 0; i < 4; i++) c[mt][nt][i] = 0.0f;

    gemm3_load(Ah, Al, Wh, Wl, bm, bn, base, tid, 0, 0);
    CP_COMMIT();

    const int NIT = KDIM / GBK2;   // 64
    for (int k = 0; k < NIT; k++) {
        if (k + 1 < NIT) {
            gemm3_load(Ah, Al, Wh, Wl, bm, bn, base, tid, (k + 1) * GBK2, (k + 1) & 1);
            CP_COMMIT();
            CP_WAIT(1);
        } else {
            CP_WAIT(0);
        }
        __syncthreads();

        const float* Ahs = smem + (k & 1) * G2_STAGE;
        const float* Als = Ahs + G2_TILE;
        const float* Bhs = Als + G2_TILE;
        const float* Bls = Bhs + G2_TILE;

#pragma unroll
        for (int ko = 0; ko < GBK2; ko += 8) {
            uint32_t bh_[4][2], bl_[4][2];
#pragma unroll
            for (int nt = 0; nt < 4; nt++) {
                const int n0 = (wn + nt * 8 + G) * GRS2 + ko + T;
                bh_[nt][0] = __float_as_uint(Bhs[n0]);
                bh_[nt][1] = __float_as_uint(Bhs[n0 + 4]);
                bl_[nt][0] = __float_as_uint(Bls[n0]);
                bl_[nt][1] = __float_as_uint(Bls[n0 + 4]);
            }
#pragma unroll
            for (int mt = 0; mt < 4; mt++) {
                const int r0 = (wm + mt * 16 + G) * GRS2 + ko + T;
                const int r1 = (wm + mt * 16 + G + 8) * GRS2 + ko + T;
                uint32_t ah0 = __float_as_uint(Ahs[r0]);
                uint32_t ah1 = __float_as_uint(Ahs[r1]);
                uint32_t ah2 = __float_as_uint(Ahs[r0 + 4]);
                uint32_t ah3 = __float_as_uint(Ahs[r1 + 4]);
                uint32_t al0 = __float_as_uint(Als[r0]);
                uint32_t al1 = __float_as_uint(Als[r1]);
                uint32_t al2 = __float_as_uint(Als[r0 + 4]);
                uint32_t al3 = __float_as_uint(Als[r1 + 4]);
#pragma unroll
                for (int nt = 0; nt < 4; nt++) {
                    mma_tf32(c[mt][nt], ah0, ah1, ah2, ah3, bh_[nt][0], bh_[nt][1]);
                    mma_tf32(c[mt][nt], al0, al1, al2, al3, bh_[nt][0], bh_[nt][1]);
                    mma_tf32(c[mt][nt], ah0, ah1, ah2, ah3, bl_[nt][0], bl_[nt][1]);
                }
            }
        }
        __syncthreads();
    }

#pragma unroll
    for (int mt = 0; mt < 4; mt++) {
#pragma unroll
        for (int half = 0; half < 2; half++) {
            const int gm = bm + wm + mt * 16 + G + half * 8;
            const int b_ = gm >> 11;
            const int s_ = gm & 2047;
#pragma unroll
            for (int nt = 0; nt < 4; nt++) {
                const int gn = bn + wn + nt * 8 + 2 * T;
                float2 bv = *(const float2*)&bias[gn];
                float2 v;
                v.x = c[mt][nt][half * 2 + 0] + bv.x;
                v.y = c[mt][nt][half * 2 + 1] + bv.y;
                if (headLayout) {
                    const int h = gn >> 6, d = gn & 63;
                    *(float2*)&C[(((size_t)(b_ * NHEAD + h) * SEQ) + s_) * DK + d] = v;
                } else {
                    *(float2*)&C[(size_t)gm * DMODEL + gn] = v;
                }
            }
        }
    }
}

// ---------------- TF32 mma flash attention (4 warps x 32 rows) --------------
// grid (SEQ/128, B*H), 128 threads. Warp w: rows [w*32, w*32+32) = two m16
// tiles. 1.5 LDS per HMMA; softmax stats quad-local. 2 CTAs/SM.
#define AST 68
#define A_QS 0
#define A_KS (128 * AST)
#define A_VS (A_KS + 64 * AST)
#define A_PS (A_VS + 64 * AST)
#define A_SMEM ((A_PS + 128 * AST) * 4)   // 104448 B

__global__ void __launch_bounds__(128, 2) attn_mma(
    const float* __restrict__ Qg, const float* __restrict__ Kg,
    const float* __restrict__ Vg, float* __restrict__ Ohi,
    float* __restrict__ Olo)
{
    extern __shared__ float sm[];
    float* Qs = sm + A_QS;    // [128][AST] q rows, pre-scaled 1/8, tf32
    float* Ks = sm + A_KS;    // [64][AST]  kv rows x d, tf32
    float* Vs = sm + A_VS;    // [64][AST]  d rows x kv (transposed), tf32
    float* Ps = sm + A_PS;    // [128][AST] probabilities, tf32

    const int tid = threadIdx.x;
    const int w = tid >> 5;
    const int lane = tid & 31;
    const int G = lane >> 2;
    const int T = lane & 3;
    const int bh = blockIdx.y;
    const int q0 = blockIdx.x * 128;
    const int wrow = w * 32;

    const float* Qb = Qg + ((size_t)bh * SEQ + q0) * DK;
    const float* Kb = Kg + (size_t)bh * SEQ * DK;
    const float* Vb = Vg + (size_t)bh * SEQ * DK;

    // Q load: one row per thread, scaled by 0.125, tf32-rounded
    {
        const float* p = Qb + (size_t)tid * DK;
#pragma unroll
        for (int i = 0; i < DK; i += 4) {
            float4 v = *(const float4*)(p + i);
            float4 o;
            o.x = tf32_round(v.x * 0.125f);
            o.y = tf32_round(v.y * 0.125f);
            o.z = tf32_round(v.z * 0.125f);
            o.w = tf32_round(v.w * 0.125f);
            *(float4*)&Qs[tid * AST + i] = o;
        }
    }

    float m_i[4] = {-1e30f, -1e30f, -1e30f, -1e30f};
    float l_i[4] = {0.0f, 0.0f, 0.0f, 0.0f};
    float acc[2][8][4];
#pragma unroll
    for (int mt = 0; mt < 2; mt++)
#pragma unroll
        for (int dt = 0; dt < 8; dt++)
#pragma unroll
            for (int i = 0; i < 4; i++) acc[mt][dt][i] = 0.0f;

    for (int kt = 0; kt < SEQ; kt += 64) {
        __syncthreads();
        // K loader: Ks[kv][d]; thread d = tid&63, 32 rows each
        {
            const int d = tid & 63;
            const int kv0 = (tid >> 6) * 32;
            const float* kp = Kb + (size_t)(kt + kv0) * DK + d;
#pragma unroll
            for (int j = 0; j < 32; j++)
                Ks[(kv0 + j) * AST + d] = tf32_round(kp[(size_t)j * DK]);
        }
        // V loader (transposed): Vs[d][kv]; thread kv = tid&63, 32 d each
        {
            const int kv = tid & 63;
            const int d0 = (tid >> 6) * 32;
            const float* vp = Vb + (size_t)(kt + kv) * DK + d0;
#pragma unroll
            for (int j = 0; j < 32; j += 4) {
                float4 v = *(const float4*)(vp + j);
                Vs[(d0 + j + 0) * AST + kv] = tf32_round(v.x);
                Vs[(d0 + j + 1) * AST + kv] = tf32_round(v.y);
                Vs[(d0 + j + 2) * AST + kv] = tf32_round(v.z);
                Vs[(d0 + j + 3) * AST + kv] = tf32_round(v.w);
            }
        }
        __syncthreads();

        // ---- QK^T: s[mt][nt][4]
        float s[2][8][4];
#pragma unroll
        for (int mt = 0; mt < 2; mt++)
#pragma unroll
            for (int nt = 0; nt < 8; nt++)
#pragma unroll
                for (int i = 0; i < 4; i++) s[mt][nt][i] = 0.0f;

#pragma unroll
        for (int ko = 0; ko < DK; ko += 8) {
            uint32_t a[2][4];
#pragma unroll
            for (int mt = 0; mt < 2; mt++) {
                const int r0 = (wrow + mt * 16 + G) * AST + ko + T;
                const int r1 = r0 + 8 * AST;
                a[mt][0] = __float_as_uint(Qs[r0]);
                a[mt][1] = __float_as_uint(Qs[r1]);
                a[mt][2] = __float_as_uint(Qs[r0 + 4]);
                a[mt][3] = __float_as_uint(Qs[r1 + 4]);
            }
#pragma unroll
            for (int nt = 0; nt < 8; nt++) {
                const int n0 = (nt * 8 + G) * AST + ko + T;
                uint32_t b0 = __float_as_uint(Ks[n0]);
                uint32_t b1 = __float_as_uint(Ks[n0 + 4]);
                mma_tf32(s[0][nt], a[0][0], a[0][1], a[0][2], a[0][3], b0, b1);
                mma_tf32(s[1][nt], a[1][0], a[1][1], a[1][2], a[1][3], b0, b1);
            }
        }

        // ---- online softmax (4 stats rows per thread: mt*2 + r)
        float fac[4];
#pragma unroll
        for (int mt = 0; mt < 2; mt++) {
#pragma unroll
            for (int r = 0; r < 2; r++) {
                const int ix = mt * 2 + r;
                float mx = -1e30f;
#pragma unroll
                for (int nt = 0; nt < 8; nt++)
                    mx = fmaxf(mx, fmaxf(s[mt][nt][2 * r], s[mt][nt][2 * r + 1]));
                mx = fmaxf(mx, __shfl_xor_sync(0xffffffffu, mx, 1));
                mx = fmaxf(mx, __shfl_xor_sync(0xffffffffu, mx, 2));
                const float mn = fmaxf(m_i[ix], mx);
                fac[ix] = __expf(m_i[ix] - mn);
                m_i[ix] = mn;
                float ls = 0.0f;
#pragma unroll
                for (int nt = 0; nt < 8; nt++) {
                    float p0 = tf32_round(__expf(s[mt][nt][2 * r + 0] - mn));
                    float p1 = tf32_round(__expf(s[mt][nt][2 * r + 1] - mn));
                    s[mt][nt][2 * r + 0] = p0;
                    s[mt][nt][2 * r + 1] = p1;
                    ls += p0 + p1;
                }
                ls += __shfl_xor_sync(0xffffffffu, ls, 1);
                ls += __shfl_xor_sync(0xffffffffu, ls, 2);
                l_i[ix] = l_i[ix] * fac[ix] + ls;
            }
        }

        // ---- store P (warp-private rows)
#pragma unroll
        for (int mt = 0; mt < 2; mt++)
#pragma unroll
            for (int nt = 0; nt < 8; nt++) {
                *(float2*)&Ps[(wrow + mt * 16 + G) * AST + nt * 8 + 2 * T] =
                    make_float2(s[mt][nt][0], s[mt][nt][1]);
                *(float2*)&Ps[(wrow + mt * 16 + G + 8) * AST + nt * 8 + 2 * T] =
                    make_float2(s[mt][nt][2], s[mt][nt][3]);
            }
        __syncwarp();

        // ---- rescale accumulators
#pragma unroll
        for (int mt = 0; mt < 2; mt++)
#pragma unroll
            for (int dt = 0; dt < 8; dt++) {
                acc[mt][dt][0] *= fac[mt * 2 + 0];
                acc[mt][dt][1] *= fac[mt * 2 + 0];
                acc[mt][dt][2] *= fac[mt * 2 + 1];
                acc[mt][dt][3] *= fac[mt * 2 + 1];
            }

        // ---- PV: acc += P[32x64] * V^T
#pragma unroll
        for (int ko = 0; ko < 64; ko += 8) {
            uint32_t a[2][4];
#pragma unroll
            for (int mt = 0; mt < 2; mt++) {
                const int r0 = (wrow + mt * 16 + G) * AST + ko + T;
                const int r1 = r0 + 8 * AST;
                a[mt][0] = __float_as_uint(Ps[r0]);
                a[mt][1] = __float_as_uint(Ps[r1]);
                a[mt][2] = __float_as_uint(Ps[r0 + 4]);
                a[mt][3] = __float_as_uint(Ps[r1 + 4]);
            }
#pragma unroll
            for (int dt = 0; dt < 8; dt++) {
                const int n0 = (dt * 8 + G) * AST + ko + T;
                uint32_t b0 = __float_as_uint(Vs[n0]);
                uint32_t b1 = __float_as_uint(Vs[n0 + 4]);
                mma_tf32(acc[0][dt], a[0][0], a[0][1], a[0][2], a[0][3], b0, b1);
                mma_tf32(acc[1][dt], a[1][0], a[1][1], a[1][2], a[1][3], b0, b1);
            }
        }
    }

    // ---- epilogue: normalize, split hi/lo
    const int b = bh >> 4;
    const int h = bh & 15;
#pragma unroll
    for (int mt = 0; mt < 2; mt++) {
        const float inv0 = 1.0f / l_i[mt * 2 + 0];
        const float inv1 = 1.0f / l_i[mt * 2 + 1];
        const int r0 = q0 + wrow + mt * 16 + G;
        const int r1 = r0 + 8;
        const size_t o0 = ((size_t)b * SEQ + r0) * DMODEL + h * DK;
        const size_t o1 = ((size_t)b * SEQ + r1) * DMODEL + h * DK;
#pragma unroll
        for (int dt = 0; dt < 8; dt++) {
            const int d = dt * 8 + 2 * T;
            float x0 = acc[mt][dt][0] * inv0, y0 = acc[mt][dt][1] * inv0;
            float x1 = acc[mt][dt][2] * inv1, y1 = acc[mt][dt][3] * inv1;
            float2 h0, l0, h1, l1;
            h0.x = tf32_round(x0); l0.x = tf32_round(x0 - h0.x);
            h0.y = tf32_round(y0); l0.y = tf32_round(y0 - h0.y);
            h1.x = tf32_round(x1); l1.x = tf32_round(x1 - h1.x);
            h1.y = tf32_round(y1); l1.y = tf32_round(y1 - h1.y);
            *(float2*)&Ohi[o0 + d] = h0;
            *(float2*)&Olo[o0 + d] = l0;
            *(float2*)&Ohi[o1 + d] = h1;
            *(float2*)&Olo[o1 + d] = l1;
        }
    }
}

// ---------------- launch ----------------
extern "C" void kernel_launch(void* const* d_in, const int* in_sizes, int n_in,
                              void* d_out, int out_size)
{
    const float* x  = (const float*)d_in[0];
    const float* Wq = (const float*)d_in[1];
    const float* bq = (const float*)d_in[2];
    const float* Wk = (const float*)d_in[3];
    const float* bk = (const float*)d_in[4];
    const float* Wv = (const float*)d_in[5];
    const float* bv = (const float*)d_in[6];
    const float* Wo = (const float*)d_in[7];
    const float* bo = (const float*)d_in[8];
    float* out = (float*)d_out;

    float *gq, *gk, *gv, *gah, *gal, *gxh, *gxl;
    float *wqh, *wql, *wkh, *wkl, *wvh, *wvl, *woh, *wol;
    cudaGetSymbolAddress((void**)&gq,  g_q);
    cudaGetSymbolAddress((void**)&gk,  g_k);
    cudaGetSymbolAddress((void**)&gv,  g_v);
    cudaGetSymbolAddress((void**)&gah, g_ahi);
    cudaGetSymbolAddress((void**)&gal, g_alo);
    cudaGetSymbolAddress((void**)&gxh, g_xhi);
    cudaGetSymbolAddress((void**)&gxl, g_xlo);
    cudaGetSymbolAddress((void**)&wqh, g_wqh);
    cudaGetSymbolAddress((void**)&wql, g_wql);
    cudaGetSymbolAddress((void**)&wkh, g_wkh);
    cudaGetSymbolAddress((void**)&wkl, g_wkl);
    cudaGetSymbolAddress((void**)&wvh, g_wvh);
    cudaGetSymbolAddress((void**)&wvl, g_wvl);
    cudaGetSymbolAddress((void**)&woh, g_woh);
    cudaGetSymbolAddress((void**)&wol, g_wol);

    cudaFuncSetAttribute(gemm3_tf32, cudaFuncAttributeMaxDynamicSharedMemorySize,
                         G2_SMEM);
    cudaFuncSetAttribute(attn_mma, cudaFuncAttributeMaxDynamicSharedMemorySize,
                         A_SMEM);

    // hi/lo tf32 splits
    {
        const int nx4 = (MROWS * DMODEL) / 4;
        const int nw4 = (DMODEL * DMODEL) / 4;
        round_split_kernel<<<(nx4 + 255) / 256, 256>>>(x,  gxh, gxl, nx4);
        round_split_kernel<<<(nw4 + 255) / 256, 256>>>(Wq, wqh, wql, nw4);
        round_split_kernel<<<(nw4 + 255) / 256, 256>>>(Wk, wkh, wkl, nw4);
        round_split_kernel<<<(nw4 + 255) / 256, 256>>>(Wv, wvh, wvl, nw4);
        round_split_kernel<<<(nw4 + 255) / 256, 256>>>(Wo, woh, wol, nw4);
    }

    // fused QKV projection (grid z = 3)
    dim3 gqkv(DMODEL / 128, MROWS / 128, 3);
    gemm3_tf32<<<gqkv, 256, G2_SMEM>>>(gxh, gxl,
                                       wqh, wql, bq, gq,
                                       wkh, wkl, bk, gk,
                                       wvh, wvl, bv, gv, 1);

    attn_mma<<<dim3(SEQ / 128, BATCH * NHEAD), 128, A_SMEM>>>(gq, gk, gv, gah, gal);

    // output projection
    dim3 go(DMODEL / 128, MROWS / 128, 1);
    gemm3_tf32<<<go, 256, G2_SMEM>>>(gah, gal,
                                     woh, wol, bo, out,
                                     woh, wol, bo, out,
                                     woh, wol, bo, out, 0);
}

// round 6
// speedup vs baseline: 2.8762x; 1.4459x over previous
#include <cuda_runtime.h>
#include <cuda_bf16.h>
#include <cstdint>
#include <cstddef>

// ---------------- problem constants ----------------
#define BATCH  2
#define SEQ    2048
#define DMODEL 1024
#define NHEAD  16
#define DK     64
#define MROWS  (BATCH * SEQ)   // 4096
#define KDIM   1024

typedef __nv_bfloat16 bf16;

// ---------------- scratch (no cudaMalloc allowed) ----------------
__device__ float g_q[BATCH * NHEAD * SEQ * DK];
__device__ float g_k[BATCH * NHEAD * SEQ * DK];
__device__ float g_v[BATCH * NHEAD * SEQ * DK];
__device__ bf16  g_xh[MROWS * DMODEL];
__device__ bf16  g_xl[MROWS * DMODEL];
__device__ bf16  g_aoh[MROWS * DMODEL];
__device__ bf16  g_aol[MROWS * DMODEL];
__device__ bf16  g_wqh[DMODEL * DMODEL];
__device__ bf16  g_wql[DMODEL * DMODEL];
__device__ bf16  g_wkh[DMODEL * DMODEL];
__device__ bf16  g_wkl[DMODEL * DMODEL];
__device__ bf16  g_wvh[DMODEL * DMODEL];
__device__ bf16  g_wvl[DMODEL * DMODEL];
__device__ bf16  g_woh[DMODEL * DMODEL];
__device__ bf16  g_wol[DMODEL * DMODEL];

// ---------------- helpers ----------------
__device__ __forceinline__ uint32_t smem_u32(const void* p) {
    uint32_t a;
    asm("{ .reg .u64 t; cvta.to.shared.u64 t, %1; cvt.u32.u64 %0, t; }"
        : "=r"(a) : "l"(p));
    return a;
}

__device__ __forceinline__ float tf32_round(float x) {
    uint32_t u;
    asm("cvt.rna.tf32.f32 %0, %1;" : "=r"(u) : "f"(x));
    return __uint_as_float(u);
}

#define CP_ASYNC16(dst_u32, src_ptr) \
    asm volatile("cp.async.cg.shared.global [%0], [%1], 16;" \
        :: "r"(dst_u32), "l"((const void*)(src_ptr)) : "memory")
#define CP_COMMIT() asm volatile("cp.async.commit_group;" ::: "memory")
#define CP_WAIT(n)  asm volatile("cp.async.wait_group %0;" :: "n"(n) : "memory")

__device__ __forceinline__ void mma_tf32(float c[4], uint32_t a0, uint32_t a1,
                                         uint32_t a2, uint32_t a3,
                                         uint32_t b0, uint32_t b1) {
    asm volatile(
        "mma.sync.aligned.m16n8k8.row.col.f32.tf32.tf32.f32 "
        "{%0,%1,%2,%3}, {%4,%5,%6,%7}, {%8,%9}, {%0,%1,%2,%3};"
        : "+f"(c[0]), "+f"(c[1]), "+f"(c[2]), "+f"(c[3])
        : "r"(a0), "r"(a1), "r"(a2), "r"(a3), "r"(b0), "r"(b1));
}

__device__ __forceinline__ void mma_bf16(float c[4], uint32_t a0, uint32_t a1,
                                         uint32_t a2, uint32_t a3,
                                         uint32_t b0, uint32_t b1) {
    asm volatile(
        "mma.sync.aligned.m16n8k16.row.col.f32.bf16.bf16.f32 "
        "{%0,%1,%2,%3}, {%4,%5,%6,%7}, {%8,%9}, {%0,%1,%2,%3};"
        : "+f"(c[0]), "+f"(c[1]), "+f"(c[2]), "+f"(c[3])
        : "r"(a0), "r"(a1), "r"(a2), "r"(a3), "r"(b0), "r"(b1));
}

__device__ __forceinline__ void bf16_split(float v, bf16& h, bf16& l) {
    h = __float2bfloat16_rn(v);
    l = __float2bfloat16_rn(v - __bfloat162float(h));
}

// ---------------- fused hi/lo bf16 split pre-pass (ONE launch) --------------
// tasks: [0, NX4) -> x ; then 4 weight blocks of NW4 each.
#define NX4 ((MROWS * DMODEL) / 4)    // 1048576
#define NW4 ((DMODEL * DMODEL) / 4)   // 262144
#define NTASK (NX4 + 4 * NW4)         // 2097152

__global__ void split_all_kernel(
    const float* __restrict__ x,
    const float* __restrict__ Wq, const float* __restrict__ Wk,
    const float* __restrict__ Wv, const float* __restrict__ Wo,
    bf16* __restrict__ xh, bf16* __restrict__ xl,
    bf16* __restrict__ wqh, bf16* __restrict__ wql,
    bf16* __restrict__ wkh, bf16* __restrict__ wkl,
    bf16* __restrict__ wvh, bf16* __restrict__ wvl,
    bf16* __restrict__ woh, bf16* __restrict__ wol)
{
    int i = blockIdx.x * blockDim.x + threadIdx.x;
    if (i >= NTASK) return;
    const float* in;
    bf16 *oh, *ol;
    int o;
    if (i < NX4) {
        in = x; oh = xh; ol = xl; o = i;
    } else {
        int j = i - NX4;
        int t = j / NW4;
        o = j - t * NW4;
        in = (t == 0) ? Wq : (t == 1) ? Wk : (t == 2) ? Wv : Wo;
        oh = (t == 0) ? wqh : (t == 1) ? wkh : (t == 2) ? wvh : woh;
        ol = (t == 0) ? wql : (t == 1) ? wkl : (t == 2) ? wvl : wol;
    }
    float4 v = ((const float4*)in)[o];
    __nv_bfloat162 h0, h1, l0, l1;
    bf16 h, l;
    bf16_split(v.x, h, l); h0.x = h; l0.x = l;
    bf16_split(v.y, h, l); h0.y = h; l0.y = l;
    bf16_split(v.z, h, l); h1.x = h; l1.x = l;
    bf16_split(v.w, h, l); h1.y = h; l1.y = l;
    ((__nv_bfloat162*)oh)[2 * o + 0] = h0;
    ((__nv_bfloat162*)oh)[2 * o + 1] = h1;
    ((__nv_bfloat162*)ol)[2 * o + 0] = l0;
    ((__nv_bfloat162*)ol)[2 * o + 1] = l1;
}

// ---------------- 3xBF16 GEMM: C = A(4096xK) * W(NxK)^T + bias --------------
// C = Ah*Bh + Al*Bh + Ah*Bl  (bf16 hi/lo, fp32 accum, m16n8k16)
// 128x128x32 CTA tile, 256 threads (8 warps 2x4), warp tile 64x32.
// smem row stride 40 bf16 (80B) -> fragment LDS banks = (20G+T)%32, distinct.
#define BBK 32
#define BRS 40
#define B_TILE (128 * BRS)            // bf16 elems (10240 B)
#define B_STAGE (4 * B_TILE)          // Ah, Al, Bh, Bl
#define B_SMEM (2 * B_STAGE * 2)      // 81920 B

__device__ __forceinline__ void gemmb_load(
    const bf16* __restrict__ Ah, const bf16* __restrict__ Al,
    const bf16* __restrict__ Wh, const bf16* __restrict__ Wl,
    int bm, int bn, uint32_t base, int tid, int k0, int s)
{
    const bf16* bases[4] = {
        Ah + (size_t)bm * KDIM, Al + (size_t)bm * KDIM,
        Wh + (size_t)bn * KDIM, Wl + (size_t)bn * KDIM };
    const uint32_t st = base + (uint32_t)(s * B_STAGE) * 2;
#pragma unroll
    for (int i = 0; i < 8; i++) {
        const int task = tid + 256 * i;     // 0..2047
        const int t = task >> 9;
        const int rem = task & 511;
        const int r = rem >> 2;
        const int seg = rem & 3;
        const bf16* src = bases[t] + (size_t)r * KDIM + k0 + seg * 8;
        const uint32_t dst = st + (uint32_t)(t * B_TILE + r * BRS + seg * 8) * 2;
        CP_ASYNC16(dst, src);
    }
}

__global__ void __launch_bounds__(256) gemm3_bf16(
    const bf16* __restrict__ Ah, const bf16* __restrict__ Al,
    const bf16* __restrict__ Wh0, const bf16* __restrict__ Wl0,
    const float* __restrict__ b0v, float* __restrict__ C0,
    const bf16* __restrict__ Wh1, const bf16* __restrict__ Wl1,
    const float* __restrict__ b1v, float* __restrict__ C1,
    const bf16* __restrict__ Wh2, const bf16* __restrict__ Wl2,
    const float* __restrict__ b2v, float* __restrict__ C2,
    int headLayout)
{
    extern __shared__ char smem_raw[];
    bf16* smem = (bf16*)smem_raw;
    const uint32_t base = smem_u32(smem_raw);
    const int tid = threadIdx.x;
    const int wid = tid >> 5;
    const int lane = tid & 31;
    const int G = lane >> 2;
    const int T = lane & 3;
    const int wm = (wid >> 2) * 64;
    const int wn = (wid & 3) * 32;
    const int bm = blockIdx.y * 128;
    const int bn = blockIdx.x * 128;
    const int z = blockIdx.z;

    const bf16* Wh = (z == 0) ? Wh0 : (z == 1) ? Wh1 : Wh2;
    const bf16* Wl = (z == 0) ? Wl0 : (z == 1) ? Wl1 : Wl2;
    const float* bias = (z == 0) ? b0v : (z == 1) ? b1v : b2v;
    float* C = (z == 0) ? C0 : (z == 1) ? C1 : C2;

    float c[4][4][4];
#pragma unroll
    for (int mt = 0; mt < 4; mt++)
#pragma unroll
        for (int nt = 0; nt < 4; nt++)
#pragma unroll
            for (int i = 0; i < 4; i++) c[mt][nt][i] = 0.0f;

    gemmb_load(Ah, Al, Wh, Wl, bm, bn, base, tid, 0, 0);
    CP_COMMIT();

    const int NIT = KDIM / BBK;   // 32
    for (int k = 0; k < NIT; k++) {
        if (k + 1 < NIT) {
            gemmb_load(Ah, Al, Wh, Wl, bm, bn, base, tid, (k + 1) * BBK, (k + 1) & 1);
            CP_COMMIT();
            CP_WAIT(1);
        } else {
            CP_WAIT(0);
        }
        __syncthreads();

        const bf16* Ahs = smem + (k & 1) * B_STAGE;
        const bf16* Als = Ahs + B_TILE;
        const bf16* Bhs = Als + B_TILE;
        const bf16* Bls = Bhs + B_TILE;

#pragma unroll
        for (int ko = 0; ko < BBK; ko += 16) {
            uint32_t bh_[4][2], bl_[4][2];
#pragma unroll
            for (int nt = 0; nt < 4; nt++) {
                const bf16* pb = Bhs + (wn + nt * 8 + G) * BRS + ko + 2 * T;
                bh_[nt][0] = *(const uint32_t*)pb;
                bh_[nt][1] = *(const uint32_t*)(pb + 8);
                const bf16* pl = Bls + (wn + nt * 8 + G) * BRS + ko + 2 * T;
                bl_[nt][0] = *(const uint32_t*)pl;
                bl_[nt][1] = *(const uint32_t*)(pl + 8);
            }
#pragma unroll
            for (int mt = 0; mt < 4; mt++) {
                const int r0 = (wm + mt * 16 + G) * BRS + ko + 2 * T;
                const int r1 = (wm + mt * 16 + G + 8) * BRS + ko + 2 * T;
                uint32_t ah0 = *(const uint32_t*)(Ahs + r0);
                uint32_t ah1 = *(const uint32_t*)(Ahs + r1);
                uint32_t ah2 = *(const uint32_t*)(Ahs + r0 + 8);
                uint32_t ah3 = *(const uint32_t*)(Ahs + r1 + 8);
                uint32_t al0 = *(const uint32_t*)(Als + r0);
                uint32_t al1 = *(const uint32_t*)(Als + r1);
                uint32_t al2 = *(const uint32_t*)(Als + r0 + 8);
                uint32_t al3 = *(const uint32_t*)(Als + r1 + 8);
#pragma unroll
                for (int nt = 0; nt < 4; nt++) {
                    mma_bf16(c[mt][nt], ah0, ah1, ah2, ah3, bh_[nt][0], bh_[nt][1]);
                    mma_bf16(c[mt][nt], al0, al1, al2, al3, bh_[nt][0], bh_[nt][1]);
                    mma_bf16(c[mt][nt], ah0, ah1, ah2, ah3, bl_[nt][0], bl_[nt][1]);
                }
            }
        }
        __syncthreads();
    }

    // epilogue (fragment rows G, G+8; cols 2T, 2T+1 per n-tile)
#pragma unroll
    for (int mt = 0; mt < 4; mt++) {
#pragma unroll
        for (int half = 0; half < 2; half++) {
            const int gm = bm + wm + mt * 16 + G + half * 8;
            const int b_ = gm >> 11;
            const int s_ = gm & 2047;
#pragma unroll
            for (int nt = 0; nt < 4; nt++) {
                const int gn = bn + wn + nt * 8 + 2 * T;
                float2 bv = *(const float2*)&bias[gn];
                float2 v;
                v.x = c[mt][nt][half * 2 + 0] + bv.x;
                v.y = c[mt][nt][half * 2 + 1] + bv.y;
                if (headLayout) {
                    const int h = gn >> 6, d = gn & 63;
                    *(float2*)&C[(((size_t)(b_ * NHEAD + h) * SEQ) + s_) * DK + d] = v;
                } else {
                    *(float2*)&C[(size_t)gm * DMODEL + gn] = v;
                }
            }
        }
    }
}

// ---------------- TF32 mma flash attention (4 warps x 32 rows) --------------
#define AST 68
#define A_QS 0
#define A_KS (128 * AST)
#define A_VS (A_KS + 64 * AST)
#define A_PS (A_VS + 64 * AST)
#define A_SMEM ((A_PS + 128 * AST) * 4)   // 104448 B

__global__ void __launch_bounds__(128, 2) attn_mma(
    const float* __restrict__ Qg, const float* __restrict__ Kg,
    const float* __restrict__ Vg, bf16* __restrict__ Ohi,
    bf16* __restrict__ Olo)
{
    extern __shared__ float sm[];
    float* Qs = sm + A_QS;
    float* Ks = sm + A_KS;
    float* Vs = sm + A_VS;
    float* Ps = sm + A_PS;

    const int tid = threadIdx.x;
    const int w = tid >> 5;
    const int lane = tid & 31;
    const int G = lane >> 2;
    const int T = lane & 3;
    const int bh = blockIdx.y;
    const int q0 = blockIdx.x * 128;
    const int wrow = w * 32;

    const float* Qb = Qg + ((size_t)bh * SEQ + q0) * DK;
    const float* Kb = Kg + (size_t)bh * SEQ * DK;
    const float* Vb = Vg + (size_t)bh * SEQ * DK;

    {
        const float* p = Qb + (size_t)tid * DK;
#pragma unroll
        for (int i = 0; i < DK; i += 4) {
            float4 v = *(const float4*)(p + i);
            float4 o;
            o.x = tf32_round(v.x * 0.125f);
            o.y = tf32_round(v.y * 0.125f);
            o.z = tf32_round(v.z * 0.125f);
            o.w = tf32_round(v.w * 0.125f);
            *(float4*)&Qs[tid * AST + i] = o;
        }
    }

    float m_i[4] = {-1e30f, -1e30f, -1e30f, -1e30f};
    float l_i[4] = {0.0f, 0.0f, 0.0f, 0.0f};
    float acc[2][8][4];
#pragma unroll
    for (int mt = 0; mt < 2; mt++)
#pragma unroll
        for (int dt = 0; dt < 8; dt++)
#pragma unroll
            for (int i = 0; i < 4; i++) acc[mt][dt][i] = 0.0f;

    for (int kt = 0; kt < SEQ; kt += 64) {
        __syncthreads();
        {
            const int d = tid & 63;
            const int kv0 = (tid >> 6) * 32;
            const float* kp = Kb + (size_t)(kt + kv0) * DK + d;
#pragma unroll
            for (int j = 0; j < 32; j++)
                Ks[(kv0 + j) * AST + d] = tf32_round(kp[(size_t)j * DK]);
        }
        {
            const int kv = tid & 63;
            const int d0 = (tid >> 6) * 32;
            const float* vp = Vb + (size_t)(kt + kv) * DK + d0;
#pragma unroll
            for (int j = 0; j < 32; j += 4) {
                float4 v = *(const float4*)(vp + j);
                Vs[(d0 + j + 0) * AST + kv] = tf32_round(v.x);
                Vs[(d0 + j + 1) * AST + kv] = tf32_round(v.y);
                Vs[(d0 + j + 2) * AST + kv] = tf32_round(v.z);
                Vs[(d0 + j + 3) * AST + kv] = tf32_round(v.w);
            }
        }
        __syncthreads();

        float s[2][8][4];
#pragma unroll
        for (int mt = 0; mt < 2; mt++)
#pragma unroll
            for (int nt = 0; nt < 8; nt++)
#pragma unroll
                for (int i = 0; i < 4; i++) s[mt][nt][i] = 0.0f;

#pragma unroll
        for (int ko = 0; ko < DK; ko += 8) {
            uint32_t a[2][4];
#pragma unroll
            for (int mt = 0; mt < 2; mt++) {
                const int r0 = (wrow + mt * 16 + G) * AST + ko + T;
                const int r1 = r0 + 8 * AST;
                a[mt][0] = __float_as_uint(Qs[r0]);
                a[mt][1] = __float_as_uint(Qs[r1]);
                a[mt][2] = __float_as_uint(Qs[r0 + 4]);
                a[mt][3] = __float_as_uint(Qs[r1 + 4]);
            }
#pragma unroll
            for (int nt = 0; nt < 8; nt++) {
                const int n0 = (nt * 8 + G) * AST + ko + T;
                uint32_t b0 = __float_as_uint(Ks[n0]);
                uint32_t b1 = __float_as_uint(Ks[n0 + 4]);
                mma_tf32(s[0][nt], a[0][0], a[0][1], a[0][2], a[0][3], b0, b1);
                mma_tf32(s[1][nt], a[1][0], a[1][1], a[1][2], a[1][3], b0, b1);
            }
        }

        float fac[4];
#pragma unroll
        for (int mt = 0; mt < 2; mt++) {
#pragma unroll
            for (int r = 0; r < 2; r++) {
                const int ix = mt * 2 + r;
                float mx = -1e30f;
#pragma unroll
                for (int nt = 0; nt < 8; nt++)
                    mx = fmaxf(mx, fmaxf(s[mt][nt][2 * r], s[mt][nt][2 * r + 1]));
                mx = fmaxf(mx, __shfl_xor_sync(0xffffffffu, mx, 1));
                mx = fmaxf(mx, __shfl_xor_sync(0xffffffffu, mx, 2));
                const float mn = fmaxf(m_i[ix], mx);
                fac[ix] = __expf(m_i[ix] - mn);
                m_i[ix] = mn;
                float ls = 0.0f;
#pragma unroll
                for (int nt = 0; nt < 8; nt++) {
                    float p0 = tf32_round(__expf(s[mt][nt][2 * r + 0] - mn));
                    float p1 = tf32_round(__expf(s[mt][nt][2 * r + 1] - mn));
                    s[mt][nt][2 * r + 0] = p0;
                    s[mt][nt][2 * r + 1] = p1;
                    ls += p0 + p1;
                }
                ls += __shfl_xor_sync(0xffffffffu, ls, 1);
                ls += __shfl_xor_sync(0xffffffffu, ls, 2);
                l_i[ix] = l_i[ix] * fac[ix] + ls;
            }
        }

#pragma unroll
        for (int mt = 0; mt < 2; mt++)
#pragma unroll
            for (int nt = 0; nt < 8; nt++) {
                *(float2*)&Ps[(wrow + mt * 16 + G) * AST + nt * 8 + 2 * T] =
                    make_float2(s[mt][nt][0], s[mt][nt][1]);
                *(float2*)&Ps[(wrow + mt * 16 + G + 8) * AST + nt * 8 + 2 * T] =
                    make_float2(s[mt][nt][2], s[mt][nt][3]);
            }
        __syncwarp();

#pragma unroll
        for (int mt = 0; mt < 2; mt++)
#pragma unroll
            for (int dt = 0; dt < 8; dt++) {
                acc[mt][dt][0] *= fac[mt * 2 + 0];
                acc[mt][dt][1] *= fac[mt * 2 + 0];
                acc[mt][dt][2] *= fac[mt * 2 + 1];
                acc[mt][dt][3] *= fac[mt * 2 + 1];
            }

#pragma unroll
        for (int ko = 0; ko < 64; ko += 8) {
            uint32_t a[2][4];
#pragma unroll
            for (int mt = 0; mt < 2; mt++) {
                const int r0 = (wrow + mt * 16 + G) * AST + ko + T;
                const int r1 = r0 + 8 * AST;
                a[mt][0] = __float_as_uint(Ps[r0]);
                a[mt][1] = __float_as_uint(Ps[r1]);
                a[mt][2] = __float_as_uint(Ps[r0 + 4]);
                a[mt][3] = __float_as_uint(Ps[r1 + 4]);
            }
#pragma unroll
            for (int dt = 0; dt < 8; dt++) {
                const int n0 = (dt * 8 + G) * AST + ko + T;
                uint32_t b0 = __float_as_uint(Vs[n0]);
                uint32_t b1 = __float_as_uint(Vs[n0 + 4]);
                mma_tf32(acc[0][dt], a[0][0], a[0][1], a[0][2], a[0][3], b0, b1);
                mma_tf32(acc[1][dt], a[1][0], a[1][1], a[1][2], a[1][3], b0, b1);
            }
        }
    }

    // epilogue: normalize, bf16 hi/lo split (feeds 3xBF16 output GEMM)
    const int b = bh >> 4;
    const int h = bh & 15;
#pragma unroll
    for (int mt = 0; mt < 2; mt++) {
        const float inv0 = 1.0f / l_i[mt * 2 + 0];
        const float inv1 = 1.0f / l_i[mt * 2 + 1];
        const int r0 = q0 + wrow + mt * 16 + G;
        const int r1 = r0 + 8;
        const size_t o0 = ((size_t)b * SEQ + r0) * DMODEL + h * DK;
        const size_t o1 = ((size_t)b * SEQ + r1) * DMODEL + h * DK;
#pragma unroll
        for (int dt = 0; dt < 8; dt++) {
            const int d = dt * 8 + 2 * T;
            float x0 = acc[mt][dt][0] * inv0, y0 = acc[mt][dt][1] * inv0;
            float x1 = acc[mt][dt][2] * inv1, y1 = acc[mt][dt][3] * inv1;
            __nv_bfloat162 h0, l0, h1, l1;
            bf16 hh, ll;
            bf16_split(x0, hh, ll); h0.x = hh; l0.x = ll;
            bf16_split(y0, hh, ll); h0.y = hh; l0.y = ll;
            bf16_split(x1, hh, ll); h1.x = hh; l1.x = ll;
            bf16_split(y1, hh, ll); h1.y = hh; l1.y = ll;
            *(__nv_bfloat162*)&Ohi[o0 + d] = h0;
            *(__nv_bfloat162*)&Olo[o0 + d] = l0;
            *(__nv_bfloat162*)&Ohi[o1 + d] = h1;
            *(__nv_bfloat162*)&Olo[o1 + d] = l1;
        }
    }
}

// ---------------- launch ----------------
extern "C" void kernel_launch(void* const* d_in, const int* in_sizes, int n_in,
                              void* d_out, int out_size)
{
    const float* x  = (const float*)d_in[0];
    const float* Wq = (const float*)d_in[1];
    const float* bq = (const float*)d_in[2];
    const float* Wk = (const float*)d_in[3];
    const float* bk = (const float*)d_in[4];
    const float* Wv = (const float*)d_in[5];
    const float* bv = (const float*)d_in[6];
    const float* Wo = (const float*)d_in[7];
    const float* bo = (const float*)d_in[8];
    float* out = (float*)d_out;

    float *gq, *gk, *gv;
    bf16 *gxh, *gxl, *gah, *gal;
    bf16 *wqh, *wql, *wkh, *wkl, *wvh, *wvl, *woh, *wol;
    cudaGetSymbolAddress((void**)&gq,  g_q);
    cudaGetSymbolAddress((void**)&gk,  g_k);
    cudaGetSymbolAddress((void**)&gv,  g_v);
    cudaGetSymbolAddress((void**)&gxh, g_xh);
    cudaGetSymbolAddress((void**)&gxl, g_xl);
    cudaGetSymbolAddress((void**)&gah, g_aoh);
    cudaGetSymbolAddress((void**)&gal, g_aol);
    cudaGetSymbolAddress((void**)&wqh, g_wqh);
    cudaGetSymbolAddress((void**)&wql, g_wql);
    cudaGetSymbolAddress((void**)&wkh, g_wkh);
    cudaGetSymbolAddress((void**)&wkl, g_wkl);
    cudaGetSymbolAddress((void**)&wvh, g_wvh);
    cudaGetSymbolAddress((void**)&wvl, g_wvl);
    cudaGetSymbolAddress((void**)&woh, g_woh);
    cudaGetSymbolAddress((void**)&wol, g_wol);

    cudaFuncSetAttribute(gemm3_bf16, cudaFuncAttributeMaxDynamicSharedMemorySize,
                         B_SMEM);
    cudaFuncSetAttribute(attn_mma, cudaFuncAttributeMaxDynamicSharedMemorySize,
                         A_SMEM);

    // one fused split launch
    split_all_kernel<<<(NTASK + 255) / 256, 256>>>(
        x, Wq, Wk, Wv, Wo, gxh, gxl,
        wqh, wql, wkh, wkl, wvh, wvl, woh, wol);

    // fused QKV projection (grid z = 3)
    dim3 gqkv(DMODEL / 128, MROWS / 128, 3);
    gemm3_bf16<<<gqkv, 256, B_SMEM>>>(gxh, gxl,
                                      wqh, wql, bq, gq,
                                      wkh, wkl, bk, gk,
                                      wvh, wvl, bv, gv, 1);

    attn_mma<<<dim3(SEQ / 128, BATCH * NHEAD), 128, A_SMEM>>>(gq, gk, gv, gah, gal);

    // output projection
    dim3 go(DMODEL / 128, MROWS / 128, 1);
    gemm3_bf16<<<go, 256, B_SMEM>>>(gah, gal,
                                    woh, wol, bo, out,
                                    woh, wol, bo, out,
                                    woh, wol, bo, out, 0);
}

// round 7
// speedup vs baseline: 3.0918x; 1.0750x over previous
#include <cuda_runtime.h>
#include <cuda_bf16.h>
#include <cstdint>
#include <cstddef>

// ---------------- problem constants ----------------
#define BATCH  2
#define SEQ    2048
#define DMODEL 1024
#define NHEAD  16
#define DK     64
#define MROWS  (BATCH * SEQ)   // 4096
#define KDIM   1024

typedef __nv_bfloat16 bf16;

// ---------------- scratch ----------------
__device__ float g_q[BATCH * NHEAD * SEQ * DK];   // [B,H,s,d] scaled+tf32
__device__ float g_k[BATCH * NHEAD * DK * SEQ];   // [B,H,d,s] tf32
__device__ float g_v[BATCH * NHEAD * DK * SEQ];   // [B,H,d,s] tf32
__device__ bf16  g_xh[MROWS * DMODEL];
__device__ bf16  g_xl[MROWS * DMODEL];
__device__ bf16  g_aoh[MROWS * DMODEL];
__device__ bf16  g_aol[MROWS * DMODEL];
__device__ bf16  g_wqh[DMODEL * DMODEL];
__device__ bf16  g_wql[DMODEL * DMODEL];
__device__ bf16  g_wkh[DMODEL * DMODEL];
__device__ bf16  g_wkl[DMODEL * DMODEL];
__device__ bf16  g_wvh[DMODEL * DMODEL];
__device__ bf16  g_wvl[DMODEL * DMODEL];
__device__ bf16  g_woh[DMODEL * DMODEL];
__device__ bf16  g_wol[DMODEL * DMODEL];

// ---------------- helpers ----------------
__device__ __forceinline__ uint32_t smem_u32(const void* p) {
    uint32_t a;
    asm("{ .reg .u64 t; cvta.to.shared.u64 t, %1; cvt.u32.u64 %0, t; }"
        : "=r"(a) : "l"(p));
    return a;
}

__device__ __forceinline__ float tf32_round(float x) {
    uint32_t u;
    asm("cvt.rna.tf32.f32 %0, %1;" : "=r"(u) : "f"(x));
    return __uint_as_float(u);
}

#define CP_ASYNC16(dst_u32, src_ptr) \
    asm volatile("cp.async.cg.shared.global [%0], [%1], 16;" \
        :: "r"(dst_u32), "l"((const void*)(src_ptr)) : "memory")
#define CP_COMMIT() asm volatile("cp.async.commit_group;" ::: "memory")
#define CP_WAIT(n)  asm volatile("cp.async.wait_group %0;" :: "n"(n) : "memory")

__device__ __forceinline__ void mma_tf32(float c[4], uint32_t a0, uint32_t a1,
                                         uint32_t a2, uint32_t a3,
                                         uint32_t b0, uint32_t b1) {
    asm volatile(
        "mma.sync.aligned.m16n8k8.row.col.f32.tf32.tf32.f32 "
        "{%0,%1,%2,%3}, {%4,%5,%6,%7}, {%8,%9}, {%0,%1,%2,%3};"
        : "+f"(c[0]), "+f"(c[1]), "+f"(c[2]), "+f"(c[3])
        : "r"(a0), "r"(a1), "r"(a2), "r"(a3), "r"(b0), "r"(b1));
}

__device__ __forceinline__ void mma_bf16(float c[4], uint32_t a0, uint32_t a1,
                                         uint32_t a2, uint32_t a3,
                                         uint32_t b0, uint32_t b1) {
    asm volatile(
        "mma.sync.aligned.m16n8k16.row.col.f32.bf16.bf16.f32 "
        "{%0,%1,%2,%3}, {%4,%5,%6,%7}, {%8,%9}, {%0,%1,%2,%3};"
        : "+f"(c[0]), "+f"(c[1]), "+f"(c[2]), "+f"(c[3])
        : "r"(a0), "r"(a1), "r"(a2), "r"(a3), "r"(b0), "r"(b1));
}

__device__ __forceinline__ void bf16_split(float v, bf16& h, bf16& l) {
    h = __float2bfloat16_rn(v);
    l = __float2bfloat16_rn(v - __bfloat162float(h));
}

// ---------------- fused hi/lo bf16 split pre-pass ----------------
#define NX4 ((MROWS * DMODEL) / 4)
#define NW4 ((DMODEL * DMODEL) / 4)
#define NTASK (NX4 + 4 * NW4)

__global__ void split_all_kernel(
    const float* __restrict__ x,
    const float* __restrict__ Wq, const float* __restrict__ Wk,
    const float* __restrict__ Wv, const float* __restrict__ Wo,
    bf16* __restrict__ xh, bf16* __restrict__ xl,
    bf16* __restrict__ wqh, bf16* __restrict__ wql,
    bf16* __restrict__ wkh, bf16* __restrict__ wkl,
    bf16* __restrict__ wvh, bf16* __restrict__ wvl,
    bf16* __restrict__ woh, bf16* __restrict__ wol)
{
    int i = blockIdx.x * blockDim.x + threadIdx.x;
    if (i >= NTASK) return;
    const float* in;
    bf16 *oh, *ol;
    int o;
    if (i < NX4) {
        in = x; oh = xh; ol = xl; o = i;
    } else {
        int j = i - NX4;
        int t = j / NW4;
        o = j - t * NW4;
        in = (t == 0) ? Wq : (t == 1) ? Wk : (t == 2) ? Wv : Wo;
        oh = (t == 0) ? wqh : (t == 1) ? wkh : (t == 2) ? wvh : woh;
        ol = (t == 0) ? wql : (t == 1) ? wkl : (t == 2) ? wvl : wol;
    }
    float4 v = ((const float4*)in)[o];
    __nv_bfloat162 h0, h1, l0, l1;
    bf16 h, l;
    bf16_split(v.x, h, l); h0.x = h; l0.x = l;
    bf16_split(v.y, h, l); h0.y = h; l0.y = l;
    bf16_split(v.z, h, l); h1.x = h; l1.x = l;
    bf16_split(v.w, h, l); h1.y = h; l1.y = l;
    ((__nv_bfloat162*)oh)[2 * o + 0] = h0;
    ((__nv_bfloat162*)oh)[2 * o + 1] = h1;
    ((__nv_bfloat162*)ol)[2 * o + 0] = l0;
    ((__nv_bfloat162*)ol)[2 * o + 1] = l1;
}

// ---------------- 3xBF16 GEMM ----------------
// modes: 0 = row-major fp32+bias; 1 = Q [B,H,s,d] (bias, *0.125, tf32);
//        2 = K/V [B,H,d,s] transposed (bias, tf32)
#define BBK 32
#define BRS 40
#define B_TILE (128 * BRS)
#define B_STAGE (4 * B_TILE)
#define B_SMEM (2 * B_STAGE * 2)      // 81920 B

__device__ __forceinline__ void gemmb_load(
    const bf16* __restrict__ Ah, const bf16* __restrict__ Al,
    const bf16* __restrict__ Wh, const bf16* __restrict__ Wl,
    int bm, int bn, uint32_t base, int tid, int k0, int s)
{
    const bf16* bases[4] = {
        Ah + (size_t)bm * KDIM, Al + (size_t)bm * KDIM,
        Wh + (size_t)bn * KDIM, Wl + (size_t)bn * KDIM };
    const uint32_t st = base + (uint32_t)(s * B_STAGE) * 2;
#pragma unroll
    for (int i = 0; i < 8; i++) {
        const int task = tid + 256 * i;
        const int t = task >> 9;
        const int rem = task & 511;
        const int r = rem >> 2;
        const int seg = rem & 3;
        const bf16* src = bases[t] + (size_t)r * KDIM + k0 + seg * 8;
        const uint32_t dst = st + (uint32_t)(t * B_TILE + r * BRS + seg * 8) * 2;
        CP_ASYNC16(dst, src);
    }
}

__global__ void __launch_bounds__(256, 2) gemm3_bf16(
    const bf16* __restrict__ Ah, const bf16* __restrict__ Al,
    const bf16* __restrict__ Wh0, const bf16* __restrict__ Wl0,
    const float* __restrict__ b0v, float* __restrict__ C0,
    const bf16* __restrict__ Wh1, const bf16* __restrict__ Wl1,
    const float* __restrict__ b1v, float* __restrict__ C1,
    const bf16* __restrict__ Wh2, const bf16* __restrict__ Wl2,
    const float* __restrict__ b2v, float* __restrict__ C2,
    int m0, int m1, int m2)
{
    extern __shared__ char smem_raw[];
    bf16* smem = (bf16*)smem_raw;
    const uint32_t base = smem_u32(smem_raw);
    const int tid = threadIdx.x;
    const int wid = tid >> 5;
    const int lane = tid & 31;
    const int G = lane >> 2;
    const int T = lane & 3;
    const int wm = (wid >> 2) * 64;
    const int wn = (wid & 3) * 32;
    const int bm = blockIdx.y * 128;
    const int bn = blockIdx.x * 128;
    const int z = blockIdx.z;

    const bf16* Wh = (z == 0) ? Wh0 : (z == 1) ? Wh1 : Wh2;
    const bf16* Wl = (z == 0) ? Wl0 : (z == 1) ? Wl1 : Wl2;
    const float* bias = (z == 0) ? b0v : (z == 1) ? b1v : b2v;
    float* C = (z == 0) ? C0 : (z == 1) ? C1 : C2;
    const int mode = (z == 0) ? m0 : (z == 1) ? m1 : m2;

    float c[4][4][4];
#pragma unroll
    for (int mt = 0; mt < 4; mt++)
#pragma unroll
        for (int nt = 0; nt < 4; nt++)
#pragma unroll
            for (int i = 0; i < 4; i++) c[mt][nt][i] = 0.0f;

    gemmb_load(Ah, Al, Wh, Wl, bm, bn, base, tid, 0, 0);
    CP_COMMIT();

    const int NIT = KDIM / BBK;   // 32
    for (int k = 0; k < NIT; k++) {
        if (k + 1 < NIT) {
            gemmb_load(Ah, Al, Wh, Wl, bm, bn, base, tid, (k + 1) * BBK, (k + 1) & 1);
            CP_COMMIT();
            CP_WAIT(1);
        } else {
            CP_WAIT(0);
        }
        __syncthreads();

        const bf16* Ahs = smem + (k & 1) * B_STAGE;
        const bf16* Als = Ahs + B_TILE;
        const bf16* Bhs = Als + B_TILE;
        const bf16* Bls = Bhs + B_TILE;

#pragma unroll
        for (int ko = 0; ko < BBK; ko += 16) {
            uint32_t bh_[4][2], bl_[4][2];
#pragma unroll
            for (int nt = 0; nt < 4; nt++) {
                const bf16* pb = Bhs + (wn + nt * 8 + G) * BRS + ko + 2 * T;
                bh_[nt][0] = *(const uint32_t*)pb;
                bh_[nt][1] = *(const uint32_t*)(pb + 8);
                const bf16* pl = Bls + (wn + nt * 8 + G) * BRS + ko + 2 * T;
                bl_[nt][0] = *(const uint32_t*)pl;
                bl_[nt][1] = *(const uint32_t*)(pl + 8);
            }
#pragma unroll
            for (int mt = 0; mt < 4; mt++) {
                const int r0 = (wm + mt * 16 + G) * BRS + ko + 2 * T;
                const int r1 = (wm + mt * 16 + G + 8) * BRS + ko + 2 * T;
                uint32_t ah0 = *(const uint32_t*)(Ahs + r0);
                uint32_t ah1 = *(const uint32_t*)(Ahs + r1);
                uint32_t ah2 = *(const uint32_t*)(Ahs + r0 + 8);
                uint32_t ah3 = *(const uint32_t*)(Ahs + r1 + 8);
                uint32_t al0 = *(const uint32_t*)(Als + r0);
                uint32_t al1 = *(const uint32_t*)(Als + r1);
                uint32_t al2 = *(const uint32_t*)(Als + r0 + 8);
                uint32_t al3 = *(const uint32_t*)(Als + r1 + 8);
#pragma unroll
                for (int nt = 0; nt < 4; nt++) {
                    mma_bf16(c[mt][nt], ah0, ah1, ah2, ah3, bh_[nt][0], bh_[nt][1]);
                    mma_bf16(c[mt][nt], al0, al1, al2, al3, bh_[nt][0], bh_[nt][1]);
                    mma_bf16(c[mt][nt], ah0, ah1, ah2, ah3, bl_[nt][0], bl_[nt][1]);
                }
            }
        }
        __syncthreads();
    }

    // epilogue
#pragma unroll
    for (int mt = 0; mt < 4; mt++) {
#pragma unroll
        for (int half = 0; half < 2; half++) {
            const int gm = bm + wm + mt * 16 + G + half * 8;
            const int b_ = gm >> 11;
            const int s_ = gm & 2047;
#pragma unroll
            for (int nt = 0; nt < 4; nt++) {
                const int gn = bn + wn + nt * 8 + 2 * T;
                float2 bv = *(const float2*)&bias[gn];
                float vx = c[mt][nt][half * 2 + 0] + bv.x;
                float vy = c[mt][nt][half * 2 + 1] + bv.y;
                if (mode == 0) {
                    float2 v; v.x = vx; v.y = vy;
                    *(float2*)&C[(size_t)gm * DMODEL + gn] = v;
                } else if (mode == 1) {
                    const int h = gn >> 6, d = gn & 63;
                    float2 v;
                    v.x = tf32_round(vx * 0.125f);
                    v.y = tf32_round(vy * 0.125f);
                    *(float2*)&C[(((size_t)(b_ * NHEAD + h) * SEQ) + s_) * DK + d] = v;
                } else {
                    const int h = gn >> 6, d = gn & 63;
                    float* Cb = C + ((size_t)(b_ * NHEAD + h) * DK + d) * SEQ + s_;
                    Cb[0]   = tf32_round(vx);
                    Cb[SEQ] = tf32_round(vy);
                }
            }
        }
    }
}

// ---------------- TF32 mma flash attention (cp.async, 2-deep pipeline) ------
// grid (SEQ/128, B*H), 128 threads (4 warps x 32 q-rows).
// Qs/Ps share [128][68] (Q frags hoisted to regs). Ks2[d][kv] stride 72,
// Vs2[d][kv] stride 68, double buffered. All strides conflict-free.
#define AST 68
#define KST 72
#define A_PS   0                       // also Q staging (floats)
#define A_K0   (128 * AST)             // 8704
#define A_KBUF (64 * KST)              // 4608
#define A_V0   (A_K0 + 2 * A_KBUF)     // 17920
#define A_VBUF (64 * AST)              // 4352
#define A_SMEM ((A_V0 + 2 * A_VBUF) * 4)   // 106496 B

__global__ void __launch_bounds__(128, 2) attn_mma(
    const float* __restrict__ Qg, const float* __restrict__ Kg,
    const float* __restrict__ Vg, bf16* __restrict__ Ohi,
    bf16* __restrict__ Olo)
{
    extern __shared__ float sm[];
    const uint32_t base = smem_u32(sm);
    float* Ps = sm + A_PS;

    const int tid = threadIdx.x;
    const int w = tid >> 5;
    const int lane = tid & 31;
    const int G = lane >> 2;
    const int T = lane & 3;
    const int bh = blockIdx.y;
    const int q0 = blockIdx.x * 128;
    const int wrow = w * 32;

    const float* Qb = Qg + ((size_t)bh * SEQ + q0) * DK;
    const float* Kb = Kg + (size_t)bh * DK * SEQ;
    const float* Vb = Vg + (size_t)bh * DK * SEQ;

    const int ld = tid >> 1;          // 0..63 (kv-tile row = d)
    const int lh = (tid & 1) * 32;    // col half

    // prologue: Q + tile0 (group 0), tile1 (group 1)
    {
        const float* qsrc = Qb + (size_t)tid * DK;
        const uint32_t qdst = base + (uint32_t)(tid * AST) * 4;
#pragma unroll
        for (int c = 0; c < 16; c++) CP_ASYNC16(qdst + c * 16, qsrc + c * 4);
    }
    {
        const float* ks = Kb + (size_t)ld * SEQ + lh;
        const uint32_t kd = base + (uint32_t)(A_K0 + ld * KST + lh) * 4;
        const float* vs = Vb + (size_t)ld * SEQ + lh;
        const uint32_t vd = base + (uint32_t)(A_V0 + ld * AST + lh) * 4;
#pragma unroll
        for (int j = 0; j < 8; j++) {
            CP_ASYNC16(kd + j * 16, ks + j * 4);
            CP_ASYNC16(vd + j * 16, vs + j * 4);
        }
    }
    CP_COMMIT();
    {
        const float* ks = Kb + (size_t)ld * SEQ + 64 + lh;
        const uint32_t kd = base + (uint32_t)(A_K0 + A_KBUF + ld * KST + lh) * 4;
        const float* vs = Vb + (size_t)ld * SEQ + 64 + lh;
        const uint32_t vd = base + (uint32_t)(A_V0 + A_VBUF + ld * AST + lh) * 4;
#pragma unroll
        for (int j = 0; j < 8; j++) {
            CP_ASYNC16(kd + j * 16, ks + j * 4);
            CP_ASYNC16(vd + j * 16, vs + j * 4);
        }
    }
    CP_COMMIT();
    CP_WAIT(1);
    __syncthreads();

    // hoist Q fragments (rows wrow.., from Ps region before it's overwritten)
    uint32_t qa[2][8][4];
#pragma unroll
    for (int mt = 0; mt < 2; mt++)
#pragma unroll
        for (int ki = 0; ki < 8; ki++) {
            const int r0 = (wrow + mt * 16 + G) * AST + ki * 8 + T;
            const int r1 = r0 + 8 * AST;
            qa[mt][ki][0] = __float_as_uint(Ps[r0]);
            qa[mt][ki][1] = __float_as_uint(Ps[r1]);
            qa[mt][ki][2] = __float_as_uint(Ps[r0 + 4]);
            qa[mt][ki][3] = __float_as_uint(Ps[r1 + 4]);
        }

    float m_i[4] = {-1e30f, -1e30f, -1e30f, -1e30f};
    float l_i[4] = {0.0f, 0.0f, 0.0f, 0.0f};
    float acc[2][8][4];
#pragma unroll
    for (int mt = 0; mt < 2; mt++)
#pragma unroll
        for (int dt = 0; dt < 8; dt++)
#pragma unroll
            for (int i = 0; i < 4; i++) acc[mt][dt][i] = 0.0f;

    const int NKT = SEQ / 64;   // 32
    for (int it = 0; it < NKT; it++) {
        if (it) { CP_WAIT(1); __syncthreads(); }

        const float* Ks2 = sm + A_K0 + (it & 1) * A_KBUF;
        const float* Vs2 = sm + A_V0 + (it & 1) * A_VBUF;

        // ---- QK^T
        float s[2][8][4];
#pragma unroll
        for (int mt = 0; mt < 2; mt++)
#pragma unroll
            for (int nt = 0; nt < 8; nt++)
#pragma unroll
                for (int i = 0; i < 4; i++) s[mt][nt][i] = 0.0f;

#pragma unroll
        for (int ki = 0; ki < 8; ki++) {
            const int ko = ki * 8;
#pragma unroll
            for (int nt = 0; nt < 8; nt++) {
                uint32_t b0 = __float_as_uint(Ks2[(ko + T) * KST + nt * 8 + G]);
                uint32_t b1 = __float_as_uint(Ks2[(ko + T + 4) * KST + nt * 8 + G]);
                mma_tf32(s[0][nt], qa[0][ki][0], qa[0][ki][1], qa[0][ki][2],
                         qa[0][ki][3], b0, b1);
                mma_tf32(s[1][nt], qa[1][ki][0], qa[1][ki][1], qa[1][ki][2],
                         qa[1][ki][3], b0, b1);
            }
        }

        // ---- online softmax
        float fac[4];
#pragma unroll
        for (int mt = 0; mt < 2; mt++) {
#pragma unroll
            for (int r = 0; r < 2; r++) {
                const int ix = mt * 2 + r;
                float mx = -1e30f;
#pragma unroll
                for (int nt = 0; nt < 8; nt++)
                    mx = fmaxf(mx, fmaxf(s[mt][nt][2 * r], s[mt][nt][2 * r + 1]));
                mx = fmaxf(mx, __shfl_xor_sync(0xffffffffu, mx, 1));
                mx = fmaxf(mx, __shfl_xor_sync(0xffffffffu, mx, 2));
                const float mn = fmaxf(m_i[ix], mx);
                fac[ix] = __expf(m_i[ix] - mn);
                m_i[ix] = mn;
                float ls = 0.0f;
#pragma unroll
                for (int nt = 0; nt < 8; nt++) {
                    float p0 = tf32_round(__expf(s[mt][nt][2 * r + 0] - mn));
                    float p1 = tf32_round(__expf(s[mt][nt][2 * r + 1] - mn));
                    s[mt][nt][2 * r + 0] = p0;
                    s[mt][nt][2 * r + 1] = p1;
                    ls += p0 + p1;
                }
                ls += __shfl_xor_sync(0xffffffffu, ls, 1);
                ls += __shfl_xor_sync(0xffffffffu, ls, 2);
                l_i[ix] = l_i[ix] * fac[ix] + ls;
            }
        }

        // ---- store P (warp-private rows)
#pragma unroll
        for (int mt = 0; mt < 2; mt++)
#pragma unroll
            for (int nt = 0; nt < 8; nt++) {
                *(float2*)&Ps[(wrow + mt * 16 + G) * AST + nt * 8 + 2 * T] =
                    make_float2(s[mt][nt][0], s[mt][nt][1]);
                *(float2*)&Ps[(wrow + mt * 16 + G + 8) * AST + nt * 8 + 2 * T] =
                    make_float2(s[mt][nt][2], s[mt][nt][3]);
            }
        __syncwarp();

        // ---- rescale accumulators
#pragma unroll
        for (int mt = 0; mt < 2; mt++)
#pragma unroll
            for (int dt = 0; dt < 8; dt++) {
                acc[mt][dt][0] *= fac[mt * 2 + 0];
                acc[mt][dt][1] *= fac[mt * 2 + 0];
                acc[mt][dt][2] *= fac[mt * 2 + 1];
                acc[mt][dt][3] *= fac[mt * 2 + 1];
            }

        // ---- PV
#pragma unroll
        for (int ki = 0; ki < 8; ki++) {
            const int ko = ki * 8;
            uint32_t a[2][4];
#pragma unroll
            for (int mt = 0; mt < 2; mt++) {
                const int r0 = (wrow + mt * 16 + G) * AST + ko + T;
                const int r1 = r0 + 8 * AST;
                a[mt][0] = __float_as_uint(Ps[r0]);
                a[mt][1] = __float_as_uint(Ps[r1]);
                a[mt][2] = __float_as_uint(Ps[r0 + 4]);
                a[mt][3] = __float_as_uint(Ps[r1 + 4]);
            }
#pragma unroll
            for (int dt = 0; dt < 8; dt++) {
                const int n0 = (dt * 8 + G) * AST + ko + T;
                uint32_t b0 = __float_as_uint(Vs2[n0]);
                uint32_t b1 = __float_as_uint(Vs2[n0 + 4]);
                mma_tf32(acc[0][dt], a[0][0], a[0][1], a[0][2], a[0][3], b0, b1);
                mma_tf32(acc[1][dt], a[1][0], a[1][1], a[1][2], a[1][3], b0, b1);
            }
        }

        __syncthreads();   // all warps done with buffer (it&1)
        // prefetch tile it+2 into buffer (it&1)
        if (it + 2 < NKT) {
            const int kt2 = (it + 2) * 64;
            const float* ks = Kb + (size_t)ld * SEQ + kt2 + lh;
            const uint32_t kd = base + (uint32_t)(A_K0 + (it & 1) * A_KBUF + ld * KST + lh) * 4;
            const float* vs = Vb + (size_t)ld * SEQ + kt2 + lh;
            const uint32_t vd = base + (uint32_t)(A_V0 + (it & 1) * A_VBUF + ld * AST + lh) * 4;
#pragma unroll
            for (int j = 0; j < 8; j++) {
                CP_ASYNC16(kd + j * 16, ks + j * 4);
                CP_ASYNC16(vd + j * 16, vs + j * 4);
            }
        }
        CP_COMMIT();
    }

    // ---- epilogue: normalize, bf16 hi/lo split
    const int b = bh >> 4;
    const int h = bh & 15;
#pragma unroll
    for (int mt = 0; mt < 2; mt++) {
        const float inv0 = 1.0f / l_i[mt * 2 + 0];
        const float inv1 = 1.0f / l_i[mt * 2 + 1];
        const int r0 = q0 + wrow + mt * 16 + G;
        const int r1 = r0 + 8;
        const size_t o0 = ((size_t)b * SEQ + r0) * DMODEL + h * DK;
        const size_t o1 = ((size_t)b * SEQ + r1) * DMODEL + h * DK;
#pragma unroll
        for (int dt = 0; dt < 8; dt++) {
            const int d = dt * 8 + 2 * T;
            float x0 = acc[mt][dt][0] * inv0, y0 = acc[mt][dt][1] * inv0;
            float x1 = acc[mt][dt][2] * inv1, y1 = acc[mt][dt][3] * inv1;
            __nv_bfloat162 h0, l0, h1, l1;
            bf16 hh, ll;
            bf16_split(x0, hh, ll); h0.x = hh; l0.x = ll;
            bf16_split(y0, hh, ll); h0.y = hh; l0.y = ll;
            bf16_split(x1, hh, ll); h1.x = hh; l1.x = ll;
            bf16_split(y1, hh, ll); h1.y = hh; l1.y = ll;
            *(__nv_bfloat162*)&Ohi[o0 + d] = h0;
            *(__nv_bfloat162*)&Olo[o0 + d] = l0;
            *(__nv_bfloat162*)&Ohi[o1 + d] = h1;
            *(__nv_bfloat162*)&Olo[o1 + d] = l1;
        }
    }
}

// ---------------- launch ----------------
extern "C" void kernel_launch(void* const* d_in, const int* in_sizes, int n_in,
                              void* d_out, int out_size)
{
    const float* x  = (const float*)d_in[0];
    const float* Wq = (const float*)d_in[1];
    const float* bq = (const float*)d_in[2];
    const float* Wk = (const float*)d_in[3];
    const float* bk = (const float*)d_in[4];
    const float* Wv = (const float*)d_in[5];
    const float* bv = (const float*)d_in[6];
    const float* Wo = (const float*)d_in[7];
    const float* bo = (const float*)d_in[8];
    float* out = (float*)d_out;

    float *gq, *gk, *gv;
    bf16 *gxh, *gxl, *gah, *gal;
    bf16 *wqh, *wql, *wkh, *wkl, *wvh, *wvl, *woh, *wol;
    cudaGetSymbolAddress((void**)&gq,  g_q);
    cudaGetSymbolAddress((void**)&gk,  g_k);
    cudaGetSymbolAddress((void**)&gv,  g_v);
    cudaGetSymbolAddress((void**)&gxh, g_xh);
    cudaGetSymbolAddress((void**)&gxl, g_xl);
    cudaGetSymbolAddress((void**)&gah, g_aoh);
    cudaGetSymbolAddress((void**)&gal, g_aol);
    cudaGetSymbolAddress((void**)&wqh, g_wqh);
    cudaGetSymbolAddress((void**)&wql, g_wql);
    cudaGetSymbolAddress((void**)&wkh, g_wkh);
    cudaGetSymbolAddress((void**)&wkl, g_wkl);
    cudaGetSymbolAddress((void**)&wvh, g_wvh);
    cudaGetSymbolAddress((void**)&wvl, g_wvl);
    cudaGetSymbolAddress((void**)&woh, g_woh);
    cudaGetSymbolAddress((void**)&wol, g_wol);

    cudaFuncSetAttribute(gemm3_bf16, cudaFuncAttributeMaxDynamicSharedMemorySize,
                         B_SMEM);
    cudaFuncSetAttribute(attn_mma, cudaFuncAttributeMaxDynamicSharedMemorySize,
                         A_SMEM);

    split_all_kernel<<<(NTASK + 255) / 256, 256>>>(
        x, Wq, Wk, Wv, Wo, gxh, gxl,
        wqh, wql, wkh, wkl, wvh, wvl, woh, wol);

    // fused QKV projection: Q -> mode 1, K/V -> mode 2
    dim3 gqkv(DMODEL / 128, MROWS / 128, 3);
    gemm3_bf16<<<gqkv, 256, B_SMEM>>>(gxh, gxl,
                                      wqh, wql, bq, gq,
                                      wkh, wkl, bk, gk,
                                      wvh, wvl, bv, gv, 1, 2, 2);

    attn_mma<<<dim3(SEQ / 128, BATCH * NHEAD), 128, A_SMEM>>>(gq, gk, gv, gah, gal);

    // output projection (mode 0)
    dim3 go(DMODEL / 128, MROWS / 128, 1);
    gemm3_bf16<<<go, 256, B_SMEM>>>(gah, gal,
                                    woh, wol, bo, out,
                                    woh, wol, bo, out,
                                    woh, wol, bo, out, 0, 0, 0);
}

// round 8
// speedup vs baseline: 3.1426x; 1.0164x over previous
#include <cuda_runtime.h>
#include <cuda_bf16.h>
#include <cstdint>
#include <cstddef>

// ---------------- problem constants ----------------
#define BATCH  2
#define SEQ    2048
#define DMODEL 1024
#define NHEAD  16
#define DK     64
#define MROWS  (BATCH * SEQ)   // 4096
#define KDIM   1024

typedef __nv_bfloat16 bf16;

// ---------------- scratch ----------------
__device__ float g_q[BATCH * NHEAD * SEQ * DK];   // [B,H,s,d] scaled+tf32
__device__ float g_k[BATCH * NHEAD * DK * SEQ];   // [B,H,d,s] tf32
__device__ float g_v[BATCH * NHEAD * DK * SEQ];   // [B,H,d,s] tf32
__device__ bf16  g_xh[MROWS * DMODEL];
__device__ bf16  g_xl[MROWS * DMODEL];
__device__ bf16  g_aoh[MROWS * DMODEL];
__device__ bf16  g_aol[MROWS * DMODEL];
__device__ bf16  g_wqh[DMODEL * DMODEL];
__device__ bf16  g_wql[DMODEL * DMODEL];
__device__ bf16  g_wkh[DMODEL * DMODEL];
__device__ bf16  g_wkl[DMODEL * DMODEL];
__device__ bf16  g_wvh[DMODEL * DMODEL];
__device__ bf16  g_wvl[DMODEL * DMODEL];
__device__ bf16  g_woh[DMODEL * DMODEL];
__device__ bf16  g_wol[DMODEL * DMODEL];

// ---------------- helpers ----------------
__device__ __forceinline__ uint32_t smem_u32(const void* p) {
    uint32_t a;
    asm("{ .reg .u64 t; cvta.to.shared.u64 t, %1; cvt.u32.u64 %0, t; }"
        : "=r"(a) : "l"(p));
    return a;
}

__device__ __forceinline__ float tf32_round(float x) {
    uint32_t u;
    asm("cvt.rna.tf32.f32 %0, %1;" : "=r"(u) : "f"(x));
    return __uint_as_float(u);
}

#define CP_ASYNC16(dst_u32, src_ptr) \
    asm volatile("cp.async.cg.shared.global [%0], [%1], 16;" \
        :: "r"(dst_u32), "l"((const void*)(src_ptr)) : "memory")
#define CP_COMMIT() asm volatile("cp.async.commit_group;" ::: "memory")
#define CP_WAIT(n)  asm volatile("cp.async.wait_group %0;" :: "n"(n) : "memory")

__device__ __forceinline__ void mma_tf32(float c[4], uint32_t a0, uint32_t a1,
                                         uint32_t a2, uint32_t a3,
                                         uint32_t b0, uint32_t b1) {
    asm volatile(
        "mma.sync.aligned.m16n8k8.row.col.f32.tf32.tf32.f32 "
        "{%0,%1,%2,%3}, {%4,%5,%6,%7}, {%8,%9}, {%0,%1,%2,%3};"
        : "+f"(c[0]), "+f"(c[1]), "+f"(c[2]), "+f"(c[3])
        : "r"(a0), "r"(a1), "r"(a2), "r"(a3), "r"(b0), "r"(b1));
}

__device__ __forceinline__ void mma_bf16(float c[4], uint32_t a0, uint32_t a1,
                                         uint32_t a2, uint32_t a3,
                                         uint32_t b0, uint32_t b1) {
    asm volatile(
        "mma.sync.aligned.m16n8k16.row.col.f32.bf16.bf16.f32 "
        "{%0,%1,%2,%3}, {%4,%5,%6,%7}, {%8,%9}, {%0,%1,%2,%3};"
        : "+f"(c[0]), "+f"(c[1]), "+f"(c[2]), "+f"(c[3])
        : "r"(a0), "r"(a1), "r"(a2), "r"(a3), "r"(b0), "r"(b1));
}

__device__ __forceinline__ void bf16_split(float v, bf16& h, bf16& l) {
    h = __float2bfloat16_rn(v);
    l = __float2bfloat16_rn(v - __bfloat162float(h));
}

// ---------------- fused hi/lo bf16 split pre-pass ----------------
#define NX4 ((MROWS * DMODEL) / 4)
#define NW4 ((DMODEL * DMODEL) / 4)
#define NTASK (NX4 + 4 * NW4)

__global__ void split_all_kernel(
    const float* __restrict__ x,
    const float* __restrict__ Wq, const float* __restrict__ Wk,
    const float* __restrict__ Wv, const float* __restrict__ Wo,
    bf16* __restrict__ xh, bf16* __restrict__ xl,
    bf16* __restrict__ wqh, bf16* __restrict__ wql,
    bf16* __restrict__ wkh, bf16* __restrict__ wkl,
    bf16* __restrict__ wvh, bf16* __restrict__ wvl,
    bf16* __restrict__ woh, bf16* __restrict__ wol)
{
    int i = blockIdx.x * blockDim.x + threadIdx.x;
    if (i >= NTASK) return;
    const float* in;
    bf16 *oh, *ol;
    int o;
    if (i < NX4) {
        in = x; oh = xh; ol = xl; o = i;
    } else {
        int j = i - NX4;
        int t = j / NW4;
        o = j - t * NW4;
        in = (t == 0) ? Wq : (t == 1) ? Wk : (t == 2) ? Wv : Wo;
        oh = (t == 0) ? wqh : (t == 1) ? wkh : (t == 2) ? wvh : woh;
        ol = (t == 0) ? wql : (t == 1) ? wkl : (t == 2) ? wvl : wol;
    }
    float4 v = ((const float4*)in)[o];
    __nv_bfloat162 h0, h1, l0, l1;
    bf16 h, l;
    bf16_split(v.x, h, l); h0.x = h; l0.x = l;
    bf16_split(v.y, h, l); h0.y = h; l0.y = l;
    bf16_split(v.z, h, l); h1.x = h; l1.x = l;
    bf16_split(v.w, h, l); h1.y = h; l1.y = l;
    ((__nv_bfloat162*)oh)[2 * o + 0] = h0;
    ((__nv_bfloat162*)oh)[2 * o + 1] = h1;
    ((__nv_bfloat162*)ol)[2 * o + 0] = l0;
    ((__nv_bfloat162*)ol)[2 * o + 1] = l1;
}

// ---------------- 3xBF16 GEMM (unchanged from round 7) ----------------
#define BBK 32
#define BRS 40
#define B_TILE (128 * BRS)
#define B_STAGE (4 * B_TILE)
#define B_SMEM (2 * B_STAGE * 2)      // 81920 B

__device__ __forceinline__ void gemmb_load(
    const bf16* __restrict__ Ah, const bf16* __restrict__ Al,
    const bf16* __restrict__ Wh, const bf16* __restrict__ Wl,
    int bm, int bn, uint32_t base, int tid, int k0, int s)
{
    const bf16* bases[4] = {
        Ah + (size_t)bm * KDIM, Al + (size_t)bm * KDIM,
        Wh + (size_t)bn * KDIM, Wl + (size_t)bn * KDIM };
    const uint32_t st = base + (uint32_t)(s * B_STAGE) * 2;
#pragma unroll
    for (int i = 0; i < 8; i++) {
        const int task = tid + 256 * i;
        const int t = task >> 9;
        const int rem = task & 511;
        const int r = rem >> 2;
        const int seg = rem & 3;
        const bf16* src = bases[t] + (size_t)r * KDIM + k0 + seg * 8;
        const uint32_t dst = st + (uint32_t)(t * B_TILE + r * BRS + seg * 8) * 2;
        CP_ASYNC16(dst, src);
    }
}

__global__ void __launch_bounds__(256, 2) gemm3_bf16(
    const bf16* __restrict__ Ah, const bf16* __restrict__ Al,
    const bf16* __restrict__ Wh0, const bf16* __restrict__ Wl0,
    const float* __restrict__ b0v, float* __restrict__ C0,
    const bf16* __restrict__ Wh1, const bf16* __restrict__ Wl1,
    const float* __restrict__ b1v, float* __restrict__ C1,
    const bf16* __restrict__ Wh2, const bf16* __restrict__ Wl2,
    const float* __restrict__ b2v, float* __restrict__ C2,
    int m0, int m1, int m2)
{
    extern __shared__ char smem_raw[];
    bf16* smem = (bf16*)smem_raw;
    const uint32_t base = smem_u32(smem_raw);
    const int tid = threadIdx.x;
    const int wid = tid >> 5;
    const int lane = tid & 31;
    const int G = lane >> 2;
    const int T = lane & 3;
    const int wm = (wid >> 2) * 64;
    const int wn = (wid & 3) * 32;
    const int bm = blockIdx.y * 128;
    const int bn = blockIdx.x * 128;
    const int z = blockIdx.z;

    const bf16* Wh = (z == 0) ? Wh0 : (z == 1) ? Wh1 : Wh2;
    const bf16* Wl = (z == 0) ? Wl0 : (z == 1) ? Wl1 : Wl2;
    const float* bias = (z == 0) ? b0v : (z == 1) ? b1v : b2v;
    float* C = (z == 0) ? C0 : (z == 1) ? C1 : C2;
    const int mode = (z == 0) ? m0 : (z == 1) ? m1 : m2;

    float c[4][4][4];
#pragma unroll
    for (int mt = 0; mt < 4; mt++)
#pragma unroll
        for (int nt = 0; nt < 4; nt++)
#pragma unroll
            for (int i = 0; i < 4; i++) c[mt][nt][i] = 0.0f;

    gemmb_load(Ah, Al, Wh, Wl, bm, bn, base, tid, 0, 0);
    CP_COMMIT();

    const int NIT = KDIM / BBK;   // 32
    for (int k = 0; k < NIT; k++) {
        if (k + 1 < NIT) {
            gemmb_load(Ah, Al, Wh, Wl, bm, bn, base, tid, (k + 1) * BBK, (k + 1) & 1);
            CP_COMMIT();
            CP_WAIT(1);
        } else {
            CP_WAIT(0);
        }
        __syncthreads();

        const bf16* Ahs = smem + (k & 1) * B_STAGE;
        const bf16* Als = Ahs + B_TILE;
        const bf16* Bhs = Als + B_TILE;
        const bf16* Bls = Bhs + B_TILE;

#pragma unroll
        for (int ko = 0; ko < BBK; ko += 16) {
            uint32_t bh_[4][2], bl_[4][2];
#pragma unroll
            for (int nt = 0; nt < 4; nt++) {
                const bf16* pb = Bhs + (wn + nt * 8 + G) * BRS + ko + 2 * T;
                bh_[nt][0] = *(const uint32_t*)pb;
                bh_[nt][1] = *(const uint32_t*)(pb + 8);
                const bf16* pl = Bls + (wn + nt * 8 + G) * BRS + ko + 2 * T;
                bl_[nt][0] = *(const uint32_t*)pl;
                bl_[nt][1] = *(const uint32_t*)(pl + 8);
            }
#pragma unroll
            for (int mt = 0; mt < 4; mt++) {
                const int r0 = (wm + mt * 16 + G) * BRS + ko + 2 * T;
                const int r1 = (wm + mt * 16 + G + 8) * BRS + ko + 2 * T;
                uint32_t ah0 = *(const uint32_t*)(Ahs + r0);
                uint32_t ah1 = *(const uint32_t*)(Ahs + r1);
                uint32_t ah2 = *(const uint32_t*)(Ahs + r0 + 8);
                uint32_t ah3 = *(const uint32_t*)(Ahs + r1 + 8);
                uint32_t al0 = *(const uint32_t*)(Als + r0);
                uint32_t al1 = *(const uint32_t*)(Als + r1);
                uint32_t al2 = *(const uint32_t*)(Als + r0 + 8);
                uint32_t al3 = *(const uint32_t*)(Als + r1 + 8);
#pragma unroll
                for (int nt = 0; nt < 4; nt++) {
                    mma_bf16(c[mt][nt], ah0, ah1, ah2, ah3, bh_[nt][0], bh_[nt][1]);
                    mma_bf16(c[mt][nt], al0, al1, al2, al3, bh_[nt][0], bh_[nt][1]);
                    mma_bf16(c[mt][nt], ah0, ah1, ah2, ah3, bl_[nt][0], bl_[nt][1]);
                }
            }
        }
        __syncthreads();
    }

#pragma unroll
    for (int mt = 0; mt < 4; mt++) {
#pragma unroll
        for (int half = 0; half < 2; half++) {
            const int gm = bm + wm + mt * 16 + G + half * 8;
            const int b_ = gm >> 11;
            const int s_ = gm & 2047;
#pragma unroll
            for (int nt = 0; nt < 4; nt++) {
                const int gn = bn + wn + nt * 8 + 2 * T;
                float2 bv = *(const float2*)&bias[gn];
                float vx = c[mt][nt][half * 2 + 0] + bv.x;
                float vy = c[mt][nt][half * 2 + 1] + bv.y;
                if (mode == 0) {
                    float2 v; v.x = vx; v.y = vy;
                    *(float2*)&C[(size_t)gm * DMODEL + gn] = v;
                } else if (mode == 1) {
                    const int h = gn >> 6, d = gn & 63;
                    float2 v;
                    v.x = tf32_round(vx * 0.125f);
                    v.y = tf32_round(vy * 0.125f);
                    *(float2*)&C[(((size_t)(b_ * NHEAD + h) * SEQ) + s_) * DK + d] = v;
                } else {
                    const int h = gn >> 6, d = gn & 63;
                    float* Cb = C + ((size_t)(b_ * NHEAD + h) * DK + d) * SEQ + s_;
                    Cb[0]   = tf32_round(vx);
                    Cb[SEQ] = tf32_round(vy);
                }
            }
        }
    }
}

// ---------------- TF32 mma flash attention: 8 warps x 16 q-rows -------------
// grid (SEQ/128, B*H), 256 threads, 2 CTAs/SM -> 16 warps/SM.
// Same smem layout / per-row math as round 7 (bit-identical numerics).
#define AST 68
#define KST 72
#define A_PS   0                       // also Q staging
#define A_K0   (128 * AST)
#define A_KBUF (64 * KST)
#define A_V0   (A_K0 + 2 * A_KBUF)
#define A_VBUF (64 * AST)
#define A_SMEM ((A_V0 + 2 * A_VBUF) * 4)   // 106496 B

__global__ void __launch_bounds__(256, 2) attn_mma(
    const float* __restrict__ Qg, const float* __restrict__ Kg,
    const float* __restrict__ Vg, bf16* __restrict__ Ohi,
    bf16* __restrict__ Olo)
{
    extern __shared__ float sm[];
    const uint32_t base = smem_u32(sm);
    float* Ps = sm + A_PS;

    const int tid = threadIdx.x;
    const int w = tid >> 5;
    const int lane = tid & 31;
    const int G = lane >> 2;
    const int T = lane & 3;
    const int bh = blockIdx.y;
    const int q0 = blockIdx.x * 128;
    const int wrow = w * 16;          // 8 warps x 16 rows

    const float* Qb = Qg + ((size_t)bh * SEQ + q0) * DK;
    const float* Kb = Kg + (size_t)bh * DK * SEQ;
    const float* Vb = Vg + (size_t)bh * DK * SEQ;

    const int ld = tid >> 2;          // 0..63 (kv-tile row = d)
    const int lh = (tid & 3) * 16;    // col quarter

    // prologue: Q + tile0, tile1
    {
        const int qr = tid >> 1;
        const int qh = (tid & 1) * 32;
        const float* qsrc = Qb + (size_t)qr * DK + qh;
        const uint32_t qdst = base + (uint32_t)(qr * AST + qh) * 4;
#pragma unroll
        for (int c = 0; c < 8; c++) CP_ASYNC16(qdst + c * 16, qsrc + c * 4);
    }
    {
        const float* ks = Kb + (size_t)ld * SEQ + lh;
        const uint32_t kd = base + (uint32_t)(A_K0 + ld * KST + lh) * 4;
        const float* vs = Vb + (size_t)ld * SEQ + lh;
        const uint32_t vd = base + (uint32_t)(A_V0 + ld * AST + lh) * 4;
#pragma unroll
        for (int j = 0; j < 4; j++) {
            CP_ASYNC16(kd + j * 16, ks + j * 4);
            CP_ASYNC16(vd + j * 16, vs + j * 4);
        }
    }
    CP_COMMIT();
    {
        const float* ks = Kb + (size_t)ld * SEQ + 64 + lh;
        const uint32_t kd = base + (uint32_t)(A_K0 + A_KBUF + ld * KST + lh) * 4;
        const float* vs = Vb + (size_t)ld * SEQ + 64 + lh;
        const uint32_t vd = base + (uint32_t)(A_V0 + A_VBUF + ld * AST + lh) * 4;
#pragma unroll
        for (int j = 0; j < 4; j++) {
            CP_ASYNC16(kd + j * 16, ks + j * 4);
            CP_ASYNC16(vd + j * 16, vs + j * 4);
        }
    }
    CP_COMMIT();
    CP_WAIT(1);
    __syncthreads();

    // hoist Q fragments (warp-private 16 rows)
    uint32_t qa[8][4];
#pragma unroll
    for (int ki = 0; ki < 8; ki++) {
        const int r0 = (wrow + G) * AST + ki * 8 + T;
        const int r1 = r0 + 8 * AST;
        qa[ki][0] = __float_as_uint(Ps[r0]);
        qa[ki][1] = __float_as_uint(Ps[r1]);
        qa[ki][2] = __float_as_uint(Ps[r0 + 4]);
        qa[ki][3] = __float_as_uint(Ps[r1 + 4]);
    }

    float m_i[2] = {-1e30f, -1e30f};
    float l_i[2] = {0.0f, 0.0f};
    float acc[8][4];
#pragma unroll
    for (int dt = 0; dt < 8; dt++)
#pragma unroll
        for (int i = 0; i < 4; i++) acc[dt][i] = 0.0f;

    const int NKT = SEQ / 64;   // 32
    for (int it = 0; it < NKT; it++) {
        if (it) { CP_WAIT(1); __syncthreads(); }

        const float* Ks2 = sm + A_K0 + (it & 1) * A_KBUF;
        const float* Vs2 = sm + A_V0 + (it & 1) * A_VBUF;

        // ---- QK^T
        float s[8][4];
#pragma unroll
        for (int nt = 0; nt < 8; nt++)
#pragma unroll
            for (int i = 0; i < 4; i++) s[nt][i] = 0.0f;

#pragma unroll
        for (int ki = 0; ki < 8; ki++) {
            const int ko = ki * 8;
#pragma unroll
            for (int nt = 0; nt < 8; nt++) {
                uint32_t b0 = __float_as_uint(Ks2[(ko + T) * KST + nt * 8 + G]);
                uint32_t b1 = __float_as_uint(Ks2[(ko + T + 4) * KST + nt * 8 + G]);
                mma_tf32(s[nt], qa[ki][0], qa[ki][1], qa[ki][2], qa[ki][3], b0, b1);
            }
        }

        // ---- online softmax (2 stats rows per thread)
        float fac[2];
#pragma unroll
        for (int r = 0; r < 2; r++) {
            float mx = -1e30f;
#pragma unroll
            for (int nt = 0; nt < 8; nt++)
                mx = fmaxf(mx, fmaxf(s[nt][2 * r], s[nt][2 * r + 1]));
            mx = fmaxf(mx, __shfl_xor_sync(0xffffffffu, mx, 1));
            mx = fmaxf(mx, __shfl_xor_sync(0xffffffffu, mx, 2));
            const float mn = fmaxf(m_i[r], mx);
            fac[r] = __expf(m_i[r] - mn);
            m_i[r] = mn;
            float ls = 0.0f;
#pragma unroll
            for (int nt = 0; nt < 8; nt++) {
                float p0 = tf32_round(__expf(s[nt][2 * r + 0] - mn));
                float p1 = tf32_round(__expf(s[nt][2 * r + 1] - mn));
                s[nt][2 * r + 0] = p0;
                s[nt][2 * r + 1] = p1;
                ls += p0 + p1;
            }
            ls += __shfl_xor_sync(0xffffffffu, ls, 1);
            ls += __shfl_xor_sync(0xffffffffu, ls, 2);
            l_i[r] = l_i[r] * fac[r] + ls;
        }

        // ---- store P (warp-private rows)
#pragma unroll
        for (int nt = 0; nt < 8; nt++) {
            *(float2*)&Ps[(wrow + G) * AST + nt * 8 + 2 * T] =
                make_float2(s[nt][0], s[nt][1]);
            *(float2*)&Ps[(wrow + G + 8) * AST + nt * 8 + 2 * T] =
                make_float2(s[nt][2], s[nt][3]);
        }
        __syncwarp();

        // ---- rescale accumulators
#pragma unroll
        for (int dt = 0; dt < 8; dt++) {
            acc[dt][0] *= fac[0];
            acc[dt][1] *= fac[0];
            acc[dt][2] *= fac[1];
            acc[dt][3] *= fac[1];
        }

        // ---- PV
#pragma unroll
        for (int ki = 0; ki < 8; ki++) {
            const int ko = ki * 8;
            const int r0 = (wrow + G) * AST + ko + T;
            const int r1 = r0 + 8 * AST;
            uint32_t a0 = __float_as_uint(Ps[r0]);
            uint32_t a1 = __float_as_uint(Ps[r1]);
            uint32_t a2 = __float_as_uint(Ps[r0 + 4]);
            uint32_t a3 = __float_as_uint(Ps[r1 + 4]);
#pragma unroll
            for (int dt = 0; dt < 8; dt++) {
                const int n0 = (dt * 8 + G) * AST + ko + T;
                uint32_t b0 = __float_as_uint(Vs2[n0]);
                uint32_t b1 = __float_as_uint(Vs2[n0 + 4]);
                mma_tf32(acc[dt], a0, a1, a2, a3, b0, b1);
            }
        }

        __syncthreads();
        if (it + 2 < NKT) {
            const int kt2 = (it + 2) * 64;
            const float* ks = Kb + (size_t)ld * SEQ + kt2 + lh;
            const uint32_t kd = base + (uint32_t)(A_K0 + (it & 1) * A_KBUF + ld * KST + lh) * 4;
            const float* vs = Vb + (size_t)ld * SEQ + kt2 + lh;
            const uint32_t vd = base + (uint32_t)(A_V0 + (it & 1) * A_VBUF + ld * AST + lh) * 4;
#pragma unroll
            for (int j = 0; j < 4; j++) {
                CP_ASYNC16(kd + j * 16, ks + j * 4);
                CP_ASYNC16(vd + j * 16, vs + j * 4);
            }
        }
        CP_COMMIT();
    }

    // ---- epilogue: normalize, bf16 hi/lo split
    const int b = bh >> 4;
    const int h = bh & 15;
    const float inv0 = 1.0f / l_i[0];
    const float inv1 = 1.0f / l_i[1];
    const int r0 = q0 + wrow + G;
    const int r1 = r0 + 8;
    const size_t o0 = ((size_t)b * SEQ + r0) * DMODEL + h * DK;
    const size_t o1 = ((size_t)b * SEQ + r1) * DMODEL + h * DK;
#pragma unroll
    for (int dt = 0; dt < 8; dt++) {
        const int d = dt * 8 + 2 * T;
        float x0 = acc[dt][0] * inv0, y0 = acc[dt][1] * inv0;
        float x1 = acc[dt][2] * inv1, y1 = acc[dt][3] * inv1;
        __nv_bfloat162 h0, l0, h1, l1;
        bf16 hh, ll;
        bf16_split(x0, hh, ll); h0.x = hh; l0.x = ll;
        bf16_split(y0, hh, ll); h0.y = hh; l0.y = ll;
        bf16_split(x1, hh, ll); h1.x = hh; l1.x = ll;
        bf16_split(y1, hh, ll); h1.y = hh; l1.y = ll;
        *(__nv_bfloat162*)&Ohi[o0 + d] = h0;
        *(__nv_bfloat162*)&Olo[o0 + d] = l0;
        *(__nv_bfloat162*)&Ohi[o1 + d] = h1;
        *(__nv_bfloat162*)&Olo[o1 + d] = l1;
    }
}

// ---------------- launch ----------------
extern "C" void kernel_launch(void* const* d_in, const int* in_sizes, int n_in,
                              void* d_out, int out_size)
{
    const float* x  = (const float*)d_in[0];
    const float* Wq = (const float*)d_in[1];
    const float* bq = (const float*)d_in[2];
    const float* Wk = (const float*)d_in[3];
    const float* bk = (const float*)d_in[4];
    const float* Wv = (const float*)d_in[5];
    const float* bv = (const float*)d_in[6];
    const float* Wo = (const float*)d_in[7];
    const float* bo = (const float*)d_in[8];
    float* out = (float*)d_out;

    float *gq, *gk, *gv;
    bf16 *gxh, *gxl, *gah, *gal;
    bf16 *wqh, *wql, *wkh, *wkl, *wvh, *wvl, *woh, *wol;
    cudaGetSymbolAddress((void**)&gq,  g_q);
    cudaGetSymbolAddress((void**)&gk,  g_k);
    cudaGetSymbolAddress((void**)&gv,  g_v);
    cudaGetSymbolAddress((void**)&gxh, g_xh);
    cudaGetSymbolAddress((void**)&gxl, g_xl);
    cudaGetSymbolAddress((void**)&gah, g_aoh);
    cudaGetSymbolAddress((void**)&gal, g_aol);
    cudaGetSymbolAddress((void**)&wqh, g_wqh);
    cudaGetSymbolAddress((void**)&wql, g_wql);
    cudaGetSymbolAddress((void**)&wkh, g_wkh);
    cudaGetSymbolAddress((void**)&wkl, g_wkl);
    cudaGetSymbolAddress((void**)&wvh, g_wvh);
    cudaGetSymbolAddress((void**)&wvl, g_wvl);
    cudaGetSymbolAddress((void**)&woh, g_woh);
    cudaGetSymbolAddress((void**)&wol, g_wol);

    cudaFuncSetAttribute(gemm3_bf16, cudaFuncAttributeMaxDynamicSharedMemorySize,
                         B_SMEM);
    cudaFuncSetAttribute(attn_mma, cudaFuncAttributeMaxDynamicSharedMemorySize,
                         A_SMEM);

    split_all_kernel<<<(NTASK + 255) / 256, 256>>>(
        x, Wq, Wk, Wv, Wo, gxh, gxl,
        wqh, wql, wkh, wkl, wvh, wvl, woh, wol);

    dim3 gqkv(DMODEL / 128, MROWS / 128, 3);
    gemm3_bf16<<<gqkv, 256, B_SMEM>>>(gxh, gxl,
                                      wqh, wql, bq, gq,
                                      wkh, wkl, bk, gk,
                                      wvh, wvl, bv, gv, 1, 2, 2);

    attn_mma<<<dim3(SEQ / 128, BATCH * NHEAD), 256, A_SMEM>>>(gq, gk, gv, gah, gal);

    dim3 go(DMODEL / 128, MROWS / 128, 1);
    gemm3_bf16<<<go, 256, B_SMEM>>>(gah, gal,
                                    woh, wol, bo, out,
                                    woh, wol, bo, out,
                                    woh, wol, bo, out, 0, 0, 0);
}

// round 9
// speedup vs baseline: 3.1467x; 1.0013x over previous
#include <cuda_runtime.h>
#include <cuda_bf16.h>
#include <cstdint>
#include <cstddef>

// ---------------- problem constants ----------------
#define BATCH  2
#define SEQ    2048
#define DMODEL 1024
#define NHEAD  16
#define DK     64
#define MROWS  (BATCH * SEQ)   // 4096
#define KDIM   1024

typedef __nv_bfloat16 bf16;

// ---------------- scratch ----------------
__device__ float g_q[BATCH * NHEAD * SEQ * DK];   // [B,H,s,d] scaled+tf32
__device__ float g_k[BATCH * NHEAD * DK * SEQ];   // [B,H,d,s] tf32
__device__ float g_v[BATCH * NHEAD * DK * SEQ];   // [B,H,d,s] tf32
__device__ bf16  g_xh[MROWS * DMODEL];
__device__ bf16  g_xl[MROWS * DMODEL];
__device__ bf16  g_aoh[MROWS * DMODEL];
__device__ bf16  g_aol[MROWS * DMODEL];
__device__ bf16  g_wqh[DMODEL * DMODEL];
__device__ bf16  g_wql[DMODEL * DMODEL];
__device__ bf16  g_wkh[DMODEL * DMODEL];
__device__ bf16  g_wkl[DMODEL * DMODEL];
__device__ bf16  g_wvh[DMODEL * DMODEL];
__device__ bf16  g_wvl[DMODEL * DMODEL];
__device__ bf16  g_woh[DMODEL * DMODEL];
__device__ bf16  g_wol[DMODEL * DMODEL];

// ---------------- helpers ----------------
__device__ __forceinline__ uint32_t smem_u32(const void* p) {
    uint32_t a;
    asm("{ .reg .u64 t; cvta.to.shared.u64 t, %1; cvt.u32.u64 %0, t; }"
        : "=r"(a) : "l"(p));
    return a;
}

__device__ __forceinline__ float tf32_round(float x) {
    uint32_t u;
    asm("cvt.rna.tf32.f32 %0, %1;" : "=r"(u) : "f"(x));
    return __uint_as_float(u);
}

#define CP_ASYNC16(dst_u32, src_ptr) \
    asm volatile("cp.async.cg.shared.global [%0], [%1], 16;" \
        :: "r"(dst_u32), "l"((const void*)(src_ptr)) : "memory")
#define CP_COMMIT() asm volatile("cp.async.commit_group;" ::: "memory")
#define CP_WAIT(n)  asm volatile("cp.async.wait_group %0;" :: "n"(n) : "memory")

__device__ __forceinline__ void mma_tf32(float c[4], uint32_t a0, uint32_t a1,
                                         uint32_t a2, uint32_t a3,
                                         uint32_t b0, uint32_t b1) {
    asm volatile(
        "mma.sync.aligned.m16n8k8.row.col.f32.tf32.tf32.f32 "
        "{%0,%1,%2,%3}, {%4,%5,%6,%7}, {%8,%9}, {%0,%1,%2,%3};"
        : "+f"(c[0]), "+f"(c[1]), "+f"(c[2]), "+f"(c[3])
        : "r"(a0), "r"(a1), "r"(a2), "r"(a3), "r"(b0), "r"(b1));
}

__device__ __forceinline__ void mma_bf16(float c[4], uint32_t a0, uint32_t a1,
                                         uint32_t a2, uint32_t a3,
                                         uint32_t b0, uint32_t b1) {
    asm volatile(
        "mma.sync.aligned.m16n8k16.row.col.f32.bf16.bf16.f32 "
        "{%0,%1,%2,%3}, {%4,%5,%6,%7}, {%8,%9}, {%0,%1,%2,%3};"
        : "+f"(c[0]), "+f"(c[1]), "+f"(c[2]), "+f"(c[3])
        : "r"(a0), "r"(a1), "r"(a2), "r"(a3), "r"(b0), "r"(b1));
}

__device__ __forceinline__ void bf16_split(float v, bf16& h, bf16& l) {
    h = __float2bfloat16_rn(v);
    l = __float2bfloat16_rn(v - __bfloat162float(h));
}

// ---------------- fused hi/lo bf16 split pre-pass ----------------
#define NX4 ((MROWS * DMODEL) / 4)
#define NW4 ((DMODEL * DMODEL) / 4)
#define NTASK (NX4 + 4 * NW4)

__global__ void split_all_kernel(
    const float* __restrict__ x,
    const float* __restrict__ Wq, const float* __restrict__ Wk,
    const float* __restrict__ Wv, const float* __restrict__ Wo,
    bf16* __restrict__ xh, bf16* __restrict__ xl,
    bf16* __restrict__ wqh, bf16* __restrict__ wql,
    bf16* __restrict__ wkh, bf16* __restrict__ wkl,
    bf16* __restrict__ wvh, bf16* __restrict__ wvl,
    bf16* __restrict__ woh, bf16* __restrict__ wol)
{
    int i = blockIdx.x * blockDim.x + threadIdx.x;
    if (i >= NTASK) return;
    const float* in;
    bf16 *oh, *ol;
    int o;
    if (i < NX4) {
        in = x; oh = xh; ol = xl; o = i;
    } else {
        int j = i - NX4;
        int t = j / NW4;
        o = j - t * NW4;
        in = (t == 0) ? Wq : (t == 1) ? Wk : (t == 2) ? Wv : Wo;
        oh = (t == 0) ? wqh : (t == 1) ? wkh : (t == 2) ? wvh : woh;
        ol = (t == 0) ? wql : (t == 1) ? wkl : (t == 2) ? wvl : wol;
    }
    float4 v = ((const float4*)in)[o];
    __nv_bfloat162 h0, h1, l0, l1;
    bf16 h, l;
    bf16_split(v.x, h, l); h0.x = h; l0.x = l;
    bf16_split(v.y, h, l); h0.y = h; l0.y = l;
    bf16_split(v.z, h, l); h1.x = h; l1.x = l;
    bf16_split(v.w, h, l); h1.y = h; l1.y = l;
    ((__nv_bfloat162*)oh)[2 * o + 0] = h0;
    ((__nv_bfloat162*)oh)[2 * o + 1] = h1;
    ((__nv_bfloat162*)ol)[2 * o + 0] = l0;
    ((__nv_bfloat162*)ol)[2 * o + 1] = l1;
}

// ---------------- 3xBF16 GEMM (unchanged from round 7) ----------------
#define BBK 32
#define BRS 40
#define B_TILE (128 * BRS)
#define B_STAGE (4 * B_TILE)
#define B_SMEM (2 * B_STAGE * 2)      // 81920 B

__device__ __forceinline__ void gemmb_load(
    const bf16* __restrict__ Ah, const bf16* __restrict__ Al,
    const bf16* __restrict__ Wh, const bf16* __restrict__ Wl,
    int bm, int bn, uint32_t base, int tid, int k0, int s)
{
    const bf16* bases[4] = {
        Ah + (size_t)bm * KDIM, Al + (size_t)bm * KDIM,
        Wh + (size_t)bn * KDIM, Wl + (size_t)bn * KDIM };
    const uint32_t st = base + (uint32_t)(s * B_STAGE) * 2;
#pragma unroll
    for (int i = 0; i < 8; i++) {
        const int task = tid + 256 * i;
        const int t = task >> 9;
        const int rem = task & 511;
        const int r = rem >> 2;
        const int seg = rem & 3;
        const bf16* src = bases[t] + (size_t)r * KDIM + k0 + seg * 8;
        const uint32_t dst = st + (uint32_t)(t * B_TILE + r * BRS + seg * 8) * 2;
        CP_ASYNC16(dst, src);
    }
}

__global__ void __launch_bounds__(256, 2) gemm3_bf16(
    const bf16* __restrict__ Ah, const bf16* __restrict__ Al,
    const bf16* __restrict__ Wh0, const bf16* __restrict__ Wl0,
    const float* __restrict__ b0v, float* __restrict__ C0,
    const bf16* __restrict__ Wh1, const bf16* __restrict__ Wl1,
    const float* __restrict__ b1v, float* __restrict__ C1,
    const bf16* __restrict__ Wh2, const bf16* __restrict__ Wl2,
    const float* __restrict__ b2v, float* __restrict__ C2,
    int m0, int m1, int m2)
{
    extern __shared__ char smem_raw[];
    bf16* smem = (bf16*)smem_raw;
    const uint32_t base = smem_u32(smem_raw);
    const int tid = threadIdx.x;
    const int wid = tid >> 5;
    const int lane = tid & 31;
    const int G = lane >> 2;
    const int T = lane & 3;
    const int wm = (wid >> 2) * 64;
    const int wn = (wid & 3) * 32;
    const int bm = blockIdx.y * 128;
    const int bn = blockIdx.x * 128;
    const int z = blockIdx.z;

    const bf16* Wh = (z == 0) ? Wh0 : (z == 1) ? Wh1 : Wh2;
    const bf16* Wl = (z == 0) ? Wl0 : (z == 1) ? Wl1 : Wl2;
    const float* bias = (z == 0) ? b0v : (z == 1) ? b1v : b2v;
    float* C = (z == 0) ? C0 : (z == 1) ? C1 : C2;
    const int mode = (z == 0) ? m0 : (z == 1) ? m1 : m2;

    float c[4][4][4];
#pragma unroll
    for (int mt = 0; mt < 4; mt++)
#pragma unroll
        for (int nt = 0; nt < 4; nt++)
#pragma unroll
            for (int i = 0; i < 4; i++) c[mt][nt][i] = 0.0f;

    gemmb_load(Ah, Al, Wh, Wl, bm, bn, base, tid, 0, 0);
    CP_COMMIT();

    const int NIT = KDIM / BBK;   // 32
    for (int k = 0; k < NIT; k++) {
        if (k + 1 < NIT) {
            gemmb_load(Ah, Al, Wh, Wl, bm, bn, base, tid, (k + 1) * BBK, (k + 1) & 1);
            CP_COMMIT();
            CP_WAIT(1);
        } else {
            CP_WAIT(0);
        }
        __syncthreads();

        const bf16* Ahs = smem + (k & 1) * B_STAGE;
        const bf16* Als = Ahs + B_TILE;
        const bf16* Bhs = Als + B_TILE;
        const bf16* Bls = Bhs + B_TILE;

#pragma unroll
        for (int ko = 0; ko < BBK; ko += 16) {
            uint32_t bh_[4][2], bl_[4][2];
#pragma unroll
            for (int nt = 0; nt < 4; nt++) {
                const bf16* pb = Bhs + (wn + nt * 8 + G) * BRS + ko + 2 * T;
                bh_[nt][0] = *(const uint32_t*)pb;
                bh_[nt][1] = *(const uint32_t*)(pb + 8);
                const bf16* pl = Bls + (wn + nt * 8 + G) * BRS + ko + 2 * T;
                bl_[nt][0] = *(const uint32_t*)pl;
                bl_[nt][1] = *(const uint32_t*)(pl + 8);
            }
#pragma unroll
            for (int mt = 0; mt < 4; mt++) {
                const int r0 = (wm + mt * 16 + G) * BRS + ko + 2 * T;
                const int r1 = (wm + mt * 16 + G + 8) * BRS + ko + 2 * T;
                uint32_t ah0 = *(const uint32_t*)(Ahs + r0);
                uint32_t ah1 = *(const uint32_t*)(Ahs + r1);
                uint32_t ah2 = *(const uint32_t*)(Ahs + r0 + 8);
                uint32_t ah3 = *(const uint32_t*)(Ahs + r1 + 8);
                uint32_t al0 = *(const uint32_t*)(Als + r0);
                uint32_t al1 = *(const uint32_t*)(Als + r1);
                uint32_t al2 = *(const uint32_t*)(Als + r0 + 8);
                uint32_t al3 = *(const uint32_t*)(Als + r1 + 8);
#pragma unroll
                for (int nt = 0; nt < 4; nt++) {
                    mma_bf16(c[mt][nt], ah0, ah1, ah2, ah3, bh_[nt][0], bh_[nt][1]);
                    mma_bf16(c[mt][nt], al0, al1, al2, al3, bh_[nt][0], bh_[nt][1]);
                    mma_bf16(c[mt][nt], ah0, ah1, ah2, ah3, bl_[nt][0], bl_[nt][1]);
                }
            }
        }
        __syncthreads();
    }

#pragma unroll
    for (int mt = 0; mt < 4; mt++) {
#pragma unroll
        for (int half = 0; half < 2; half++) {
            const int gm = bm + wm + mt * 16 + G + half * 8;
            const int b_ = gm >> 11;
            const int s_ = gm & 2047;
#pragma unroll
            for (int nt = 0; nt < 4; nt++) {
                const int gn = bn + wn + nt * 8 + 2 * T;
                float2 bv = *(const float2*)&bias[gn];
                float vx = c[mt][nt][half * 2 + 0] + bv.x;
                float vy = c[mt][nt][half * 2 + 1] + bv.y;
                if (mode == 0) {
                    float2 v; v.x = vx; v.y = vy;
                    *(float2*)&C[(size_t)gm * DMODEL + gn] = v;
                } else if (mode == 1) {
                    const int h = gn >> 6, d = gn & 63;
                    float2 v;
                    v.x = tf32_round(vx * 0.125f);
                    v.y = tf32_round(vy * 0.125f);
                    *(float2*)&C[(((size_t)(b_ * NHEAD + h) * SEQ) + s_) * DK + d] = v;
                } else {
                    const int h = gn >> 6, d = gn & 63;
                    float* Cb = C + ((size_t)(b_ * NHEAD + h) * DK + d) * SEQ + s_;
                    Cb[0]   = tf32_round(vx);
                    Cb[SEQ] = tf32_round(vy);
                }
            }
        }
    }
}

// ---------------- TF32 mma flash attention: 8 warps x 16 q-rows -------------
// grid (SEQ/128, B*H), 256 threads, 2 CTAs/SM -> 16 warps/SM.
// Same smem layout / per-row math as round 7 (bit-identical numerics).
#define AST 68
#define KST 72
#define A_PS   0                       // also Q staging
#define A_K0   (128 * AST)
#define A_KBUF (64 * KST)
#define A_V0   (A_K0 + 2 * A_KBUF)
#define A_VBUF (64 * AST)
#define A_SMEM ((A_V0 + 2 * A_VBUF) * 4)   // 106496 B

__global__ void __launch_bounds__(256, 2) attn_mma(
    const float* __restrict__ Qg, const float* __restrict__ Kg,
    const float* __restrict__ Vg, bf16* __restrict__ Ohi,
    bf16* __restrict__ Olo)
{
    extern __shared__ float sm[];
    const uint32_t base = smem_u32(sm);
    float* Ps = sm + A_PS;

    const int tid = threadIdx.x;
    const int w = tid >> 5;
    const int lane = tid & 31;
    const int G = lane >> 2;
    const int T = lane & 3;
    const int bh = blockIdx.y;
    const int q0 = blockIdx.x * 128;
    const int wrow = w * 16;          // 8 warps x 16 rows

    const float* Qb = Qg + ((size_t)bh * SEQ + q0) * DK;
    const float* Kb = Kg + (size_t)bh * DK * SEQ;
    const float* Vb = Vg + (size_t)bh * DK * SEQ;

    const int ld = tid >> 2;          // 0..63 (kv-tile row = d)
    const int lh = (tid & 3) * 16;    // col quarter

    // prologue: Q + tile0, tile1
    {
        const int qr = tid >> 1;
        const int qh = (tid & 1) * 32;
        const float* qsrc = Qb + (size_t)qr * DK + qh;
        const uint32_t qdst = base + (uint32_t)(qr * AST + qh) * 4;
#pragma unroll
        for (int c = 0; c < 8; c++) CP_ASYNC16(qdst + c * 16, qsrc + c * 4);
    }
    {
        const float* ks = Kb + (size_t)ld * SEQ + lh;
        const uint32_t kd = base + (uint32_t)(A_K0 + ld * KST + lh) * 4;
        const float* vs = Vb + (size_t)ld * SEQ + lh;
        const uint32_t vd = base + (uint32_t)(A_V0 + ld * AST + lh) * 4;
#pragma unroll
        for (int j = 0; j < 4; j++) {
            CP_ASYNC16(kd + j * 16, ks + j * 4);
            CP_ASYNC16(vd + j * 16, vs + j * 4);
        }
    }
    CP_COMMIT();
    {
        const float* ks = Kb + (size_t)ld * SEQ + 64 + lh;
        const uint32_t kd = base + (uint32_t)(A_K0 + A_KBUF + ld * KST + lh) * 4;
        const float* vs = Vb + (size_t)ld * SEQ + 64 + lh;
        const uint32_t vd = base + (uint32_t)(A_V0 + A_VBUF + ld * AST + lh) * 4;
#pragma unroll
        for (int j = 0; j < 4; j++) {
            CP_ASYNC16(kd + j * 16, ks + j * 4);
            CP_ASYNC16(vd + j * 16, vs + j * 4);
        }
    }
    CP_COMMIT();
    CP_WAIT(1);
    __syncthreads();

    // hoist Q fragments (warp-private 16 rows)
    uint32_t qa[8][4];
#pragma unroll
    for (int ki = 0; ki < 8; ki++) {
        const int r0 = (wrow + G) * AST + ki * 8 + T;
        const int r1 = r0 + 8 * AST;
        qa[ki][0] = __float_as_uint(Ps[r0]);
        qa[ki][1] = __float_as_uint(Ps[r1]);
        qa[ki][2] = __float_as_uint(Ps[r0 + 4]);
        qa[ki][3] = __float_as_uint(Ps[r1 + 4]);
    }

    float m_i[2] = {-1e30f, -1e30f};
    float l_i[2] = {0.0f, 0.0f};
    float acc[8][4];
#pragma unroll
    for (int dt = 0; dt < 8; dt++)
#pragma unroll
        for (int i = 0; i < 4; i++) acc[dt][i] = 0.0f;

    const int NKT = SEQ / 64;   // 32
    for (int it = 0; it < NKT; it++) {
        if (it) { CP_WAIT(1); __syncthreads(); }

        const float* Ks2 = sm + A_K0 + (it & 1) * A_KBUF;
        const float* Vs2 = sm + A_V0 + (it & 1) * A_VBUF;

        // ---- QK^T
        float s[8][4];
#pragma unroll
        for (int nt = 0; nt < 8; nt++)
#pragma unroll
            for (int i = 0; i < 4; i++) s[nt][i] = 0.0f;

#pragma unroll
        for (int ki = 0; ki < 8; ki++) {
            const int ko = ki * 8;
#pragma unroll
            for (int nt = 0; nt < 8; nt++) {
                uint32_t b0 = __float_as_uint(Ks2[(ko + T) * KST + nt * 8 + G]);
                uint32_t b1 = __float_as_uint(Ks2[(ko + T + 4) * KST + nt * 8 + G]);
                mma_tf32(s[nt], qa[ki][0], qa[ki][1], qa[ki][2], qa[ki][3], b0, b1);
            }
        }

        // ---- online softmax (2 stats rows per thread)
        float fac[2];
#pragma unroll
        for (int r = 0; r < 2; r++) {
            float mx = -1e30f;
#pragma unroll
            for (int nt = 0; nt < 8; nt++)
                mx = fmaxf(mx, fmaxf(s[nt][2 * r], s[nt][2 * r + 1]));
            mx = fmaxf(mx, __shfl_xor_sync(0xffffffffu, mx, 1));
            mx = fmaxf(mx, __shfl_xor_sync(0xffffffffu, mx, 2));
            const float mn = fmaxf(m_i[r], mx);
            fac[r] = __expf(m_i[r] - mn);
            m_i[r] = mn;
            float ls = 0.0f;
#pragma unroll
            for (int nt = 0; nt < 8; nt++) {
                float p0 = tf32_round(__expf(s[nt][2 * r + 0] - mn));
                float p1 = tf32_round(__expf(s[nt][2 * r + 1] - mn));
                s[nt][2 * r + 0] = p0;
                s[nt][2 * r + 1] = p1;
                ls += p0 + p1;
            }
            ls += __shfl_xor_sync(0xffffffffu, ls, 1);
            ls += __shfl_xor_sync(0xffffffffu, ls, 2);
            l_i[r] = l_i[r] * fac[r] + ls;
        }

        // ---- store P (warp-private rows)
#pragma unroll
        for (int nt = 0; nt < 8; nt++) {
            *(float2*)&Ps[(wrow + G) * AST + nt * 8 + 2 * T] =
                make_float2(s[nt][0], s[nt][1]);
            *(float2*)&Ps[(wrow + G + 8) * AST + nt * 8 + 2 * T] =
                make_float2(s[nt][2], s[nt][3]);
        }
        __syncwarp();

        // ---- rescale accumulators
#pragma unroll
        for (int dt = 0; dt < 8; dt++) {
            acc[dt][0] *= fac[0];
            acc[dt][1] *= fac[0];
            acc[dt][2] *= fac[1];
            acc[dt][3] *= fac[1];
        }

        // ---- PV
#pragma unroll
        for (int ki = 0; ki < 8; ki++) {
            const int ko = ki * 8;
            const int r0 = (wrow + G) * AST + ko + T;
            const int r1 = r0 + 8 * AST;
            uint32_t a0 = __float_as_uint(Ps[r0]);
            uint32_t a1 = __float_as_uint(Ps[r1]);
            uint32_t a2 = __float_as_uint(Ps[r0 + 4]);
            uint32_t a3 = __float_as_uint(Ps[r1 + 4]);
#pragma unroll
            for (int dt = 0; dt < 8; dt++) {
                const int n0 = (dt * 8 + G) * AST + ko + T;
                uint32_t b0 = __float_as_uint(Vs2[n0]);
                uint32_t b1 = __float_as_uint(Vs2[n0 + 4]);
                mma_tf32(acc[dt], a0, a1, a2, a3, b0, b1);
            }
        }

        __syncthreads();
        if (it + 2 < NKT) {
            const int kt2 = (it + 2) * 64;
            const float* ks = Kb + (size_t)ld * SEQ + kt2 + lh;
            const uint32_t kd = base + (uint32_t)(A_K0 + (it & 1) * A_KBUF + ld * KST + lh) * 4;
            const float* vs = Vb + (size_t)ld * SEQ + kt2 + lh;
            const uint32_t vd = base + (uint32_t)(A_V0 + (it & 1) * A_VBUF + ld * AST + lh) * 4;
#pragma unroll
            for (int j = 0; j < 4; j++) {
                CP_ASYNC16(kd + j * 16, ks + j * 4);
                CP_ASYNC16(vd + j * 16, vs + j * 4);
            }
        }
        CP_COMMIT();
    }

    // ---- epilogue: normalize, bf16 hi/lo split
    const int b = bh >> 4;
    const int h = bh & 15;
    const float inv0 = 1.0f / l_i[0];
    const float inv1 = 1.0f / l_i[1];
    const int r0 = q0 + wrow + G;
    const int r1 = r0 + 8;
    const size_t o0 = ((size_t)b * SEQ + r0) * DMODEL + h * DK;
    const size_t o1 = ((size_t)b * SEQ + r1) * DMODEL + h * DK;
#pragma unroll
    for (int dt = 0; dt < 8; dt++) {
        const int d = dt * 8 + 2 * T;
        float x0 = acc[dt][0] * inv0, y0 = acc[dt][1] * inv0;
        float x1 = acc[dt][2] * inv1, y1 = acc[dt][3] * inv1;
        __nv_bfloat162 h0, l0, h1, l1;
        bf16 hh, ll;
        bf16_split(x0, hh, ll); h0.x = hh; l0.x = ll;
        bf16_split(y0, hh, ll); h0.y = hh; l0.y = ll;
        bf16_split(x1, hh, ll); h1.x = hh; l1.x = ll;
        bf16_split(y1, hh, ll); h1.y = hh; l1.y = ll;
        *(__nv_bfloat162*)&Ohi[o0 + d] = h0;
        *(__nv_bfloat162*)&Olo[o0 + d] = l0;
        *(__nv_bfloat162*)&Ohi[o1 + d] = h1;
        *(__nv_bfloat162*)&Olo[o1 + d] = l1;
    }
}

// ---------------- launch ----------------
extern "C" void kernel_launch(void* const* d_in, const int* in_sizes, int n_in,
                              void* d_out, int out_size)
{
    const float* x  = (const float*)d_in[0];
    const float* Wq = (const float*)d_in[1];
    const float* bq = (const float*)d_in[2];
    const float* Wk = (const float*)d_in[3];
    const float* bk = (const float*)d_in[4];
    const float* Wv = (const float*)d_in[5];
    const float* bv = (const float*)d_in[6];
    const float* Wo = (const float*)d_in[7];
    const float* bo = (const float*)d_in[8];
    float* out = (float*)d_out;

    float *gq, *gk, *gv;
    bf16 *gxh, *gxl, *gah, *gal;
    bf16 *wqh, *wql, *wkh, *wkl, *wvh, *wvl, *woh, *wol;
    cudaGetSymbolAddress((void**)&gq,  g_q);
    cudaGetSymbolAddress((void**)&gk,  g_k);
    cudaGetSymbolAddress((void**)&gv,  g_v);
    cudaGetSymbolAddress((void**)&gxh, g_xh);
    cudaGetSymbolAddress((void**)&gxl, g_xl);
    cudaGetSymbolAddress((void**)&gah, g_aoh);
    cudaGetSymbolAddress((void**)&gal, g_aol);
    cudaGetSymbolAddress((void**)&wqh, g_wqh);
    cudaGetSymbolAddress((void**)&wql, g_wql);
    cudaGetSymbolAddress((void**)&wkh, g_wkh);
    cudaGetSymbolAddress((void**)&wkl, g_wkl);
    cudaGetSymbolAddress((void**)&wvh, g_wvh);
    cudaGetSymbolAddress((void**)&wvl, g_wvl);
    cudaGetSymbolAddress((void**)&woh, g_woh);
    cudaGetSymbolAddress((void**)&wol, g_wol);

    cudaFuncSetAttribute(gemm3_bf16, cudaFuncAttributeMaxDynamicSharedMemorySize,
                         B_SMEM);
    cudaFuncSetAttribute(attn_mma, cudaFuncAttributeMaxDynamicSharedMemorySize,
                         A_SMEM);

    split_all_kernel<<<(NTASK + 255) / 256, 256>>>(
        x, Wq, Wk, Wv, Wo, gxh, gxl,
        wqh, wql, wkh, wkl, wvh, wvl, woh, wol);

    dim3 gqkv(DMODEL / 128, MROWS / 128, 3);
    gemm3_bf16<<<gqkv, 256, B_SMEM>>>(gxh, gxl,
                                      wqh, wql, bq, gq,
                                      wkh, wkl, bk, gk,
                                      wvh, wvl, bv, gv, 1, 2, 2);

    attn_mma<<<dim3(SEQ / 128, BATCH * NHEAD), 256, A_SMEM>>>(gq, gk, gv, gah, gal);

    dim3 go(DMODEL / 128, MROWS / 128, 1);
    gemm3_bf16<<<go, 256, B_SMEM>>>(gah, gal,
                                    woh, wol, bo, out,
                                    woh, wol, bo, out,
                                    woh, wol, bo, out, 0, 0, 0);
}

// round 10
// speedup vs baseline: 4.1646x; 1.3235x over previous
#include <cuda_runtime.h>
#include <cuda_bf16.h>
#include <cuda_fp16.h>
#include <cstdint>
#include <cstddef>

#define BATCH  2
#define SEQ    2048
#define DMODEL 1024
#define NHEAD  16
#define DK     64
#define MROWS  (BATCH * SEQ)
#define KDIM   1024

typedef __nv_bfloat16 bf16;

// ---------------- scratch ----------------
__device__ __half g_q[BATCH * NHEAD * SEQ * DK];   // [B,H,s,d] *0.125 fp16
__device__ __half g_k[BATCH * NHEAD * SEQ * DK];   // [B,H,s,d] fp16
__device__ __half g_v[BATCH * NHEAD * DK * SEQ];   // [B,H,d,s] fp16
__device__ bf16  g_xh[MROWS * DMODEL];
__device__ bf16  g_xl[MROWS * DMODEL];
__device__ bf16  g_aoh[MROWS * DMODEL];
__device__ bf16  g_aol[MROWS * DMODEL];
__device__ bf16  g_wqh[DMODEL * DMODEL];
__device__ bf16  g_wql[DMODEL * DMODEL];
__device__ bf16  g_wkh[DMODEL * DMODEL];
__device__ bf16  g_wkl[DMODEL * DMODEL];
__device__ bf16  g_wvh[DMODEL * DMODEL];
__device__ bf16  g_wvl[DMODEL * DMODEL];
__device__ bf16  g_woh[DMODEL * DMODEL];
__device__ bf16  g_wol[DMODEL * DMODEL];

// ---------------- helpers ----------------
__device__ __forceinline__ uint32_t smem_u32(const void* p) {
    uint32_t a;
    asm("{ .reg .u64 t; cvta.to.shared.u64 t, %1; cvt.u32.u64 %0, t; }"
        : "=r"(a) : "l"(p));
    return a;
}

#define CP_ASYNC16(dst_u32, src_ptr) \
    asm volatile("cp.async.cg.shared.global [%0], [%1], 16;" \
        :: "r"(dst_u32), "l"((const void*)(src_ptr)) : "memory")
#define CP_COMMIT() asm volatile("cp.async.commit_group;" ::: "memory")
#define CP_WAIT(n)  asm volatile("cp.async.wait_group %0;" :: "n"(n) : "memory")

__device__ __forceinline__ void mma_bf16(float c[4], uint32_t a0, uint32_t a1,
                                         uint32_t a2, uint32_t a3,
                                         uint32_t b0, uint32_t b1) {
    asm volatile(
        "mma.sync.aligned.m16n8k16.row.col.f32.bf16.bf16.f32 "
        "{%0,%1,%2,%3}, {%4,%5,%6,%7}, {%8,%9}, {%0,%1,%2,%3};"
        : "+f"(c[0]), "+f"(c[1]), "+f"(c[2]), "+f"(c[3])
        : "r"(a0), "r"(a1), "r"(a2), "r"(a3), "r"(b0), "r"(b1));
}

__device__ __forceinline__ void mma_f16(float c[4], uint32_t a0, uint32_t a1,
                                        uint32_t a2, uint32_t a3,
                                        uint32_t b0, uint32_t b1) {
    asm volatile(
        "mma.sync.aligned.m16n8k16.row.col.f32.f16.f16.f32 "
        "{%0,%1,%2,%3}, {%4,%5,%6,%7}, {%8,%9}, {%0,%1,%2,%3};"
        : "+f"(c[0]), "+f"(c[1]), "+f"(c[2]), "+f"(c[3])
        : "r"(a0), "r"(a1), "r"(a2), "r"(a3), "r"(b0), "r"(b1));
}

__device__ __forceinline__ void bf16_split(float v, bf16& h, bf16& l) {
    h = __float2bfloat16_rn(v);
    l = __float2bfloat16_rn(v - __bfloat162float(h));
}

// ---------------- fused hi/lo bf16 split pre-pass ----------------
#define NX4 ((MROWS * DMODEL) / 4)
#define NW4 ((DMODEL * DMODEL) / 4)
#define NTASK (NX4 + 4 * NW4)

__global__ void split_all_kernel(
    const float* __restrict__ x,
    const float* __restrict__ Wq, const float* __restrict__ Wk,
    const float* __restrict__ Wv, const float* __restrict__ Wo,
    bf16* __restrict__ xh, bf16* __restrict__ xl,
    bf16* __restrict__ wqh, bf16* __restrict__ wql,
    bf16* __restrict__ wkh, bf16* __restrict__ wkl,
    bf16* __restrict__ wvh, bf16* __restrict__ wvl,
    bf16* __restrict__ woh, bf16* __restrict__ wol)
{
    int i = blockIdx.x * blockDim.x + threadIdx.x;
    if (i >= NTASK) return;
    const float* in;
    bf16 *oh, *ol;
    int o;
    if (i < NX4) {
        in = x; oh = xh; ol = xl; o = i;
    } else {
        int j = i - NX4;
        int t = j / NW4;
        o = j - t * NW4;
        in = (t == 0) ? Wq : (t == 1) ? Wk : (t == 2) ? Wv : Wo;
        oh = (t == 0) ? wqh : (t == 1) ? wkh : (t == 2) ? wvh : woh;
        ol = (t == 0) ? wql : (t == 1) ? wkl : (t == 2) ? wvl : wol;
    }
    float4 v = ((const float4*)in)[o];
    __nv_bfloat162 h0, h1, l0, l1;
    bf16 h, l;
    bf16_split(v.x, h, l); h0.x = h; l0.x = l;
    bf16_split(v.y, h, l); h0.y = h; l0.y = l;
    bf16_split(v.z, h, l); h1.x = h; l1.x = l;
    bf16_split(v.w, h, l); h1.y = h; l1.y = l;
    ((__nv_bfloat162*)oh)[2 * o + 0] = h0;
    ((__nv_bfloat162*)oh)[2 * o + 1] = h1;
    ((__nv_bfloat162*)ol)[2 * o + 0] = l0;
    ((__nv_bfloat162*)ol)[2 * o + 1] = l1;
}

// ---------------- 3xBF16 GEMM ----------------
// modes: 0 = fp32 row-major+bias; 1 = Q fp16 [B,H,s,d]*0.125;
//        2 = K fp16 [B,H,s,d]; 3 = V fp16 [B,H,d,s]
#define BBK 32
#define BRS 40
#define B_TILE (128 * BRS)
#define B_STAGE (4 * B_TILE)
#define B_SMEM (2 * B_STAGE * 2)

__device__ __forceinline__ void gemmb_load(
    const bf16* __restrict__ Ah, const bf16* __restrict__ Al,
    const bf16* __restrict__ Wh, const bf16* __restrict__ Wl,
    int bm, int bn, uint32_t base, int tid, int k0, int s)
{
    const bf16* bases[4] = {
        Ah + (size_t)bm * KDIM, Al + (size_t)bm * KDIM,
        Wh + (size_t)bn * KDIM, Wl + (size_t)bn * KDIM };
    const uint32_t st = base + (uint32_t)(s * B_STAGE) * 2;
#pragma unroll
    for (int i = 0; i < 8; i++) {
        const int task = tid + 256 * i;
        const int t = task >> 9;
        const int rem = task & 511;
        const int r = rem >> 2;
        const int seg = rem & 3;
        const bf16* src = bases[t] + (size_t)r * KDIM + k0 + seg * 8;
        const uint32_t dst = st + (uint32_t)(t * B_TILE + r * BRS + seg * 8) * 2;
        CP_ASYNC16(dst, src);
    }
}

__global__ void __launch_bounds__(256, 2) gemm3_bf16(
    const bf16* __restrict__ Ah, const bf16* __restrict__ Al,
    const bf16* __restrict__ Wh0, const bf16* __restrict__ Wl0,
    const float* __restrict__ b0v, void* __restrict__ C0,
    const bf16* __restrict__ Wh1, const bf16* __restrict__ Wl1,
    const float* __restrict__ b1v, void* __restrict__ C1,
    const bf16* __restrict__ Wh2, const bf16* __restrict__ Wl2,
    const float* __restrict__ b2v, void* __restrict__ C2,
    int m0, int m1, int m2)
{
    extern __shared__ char smem_raw[];
    bf16* smem = (bf16*)smem_raw;
    const uint32_t base = smem_u32(smem_raw);
    const int tid = threadIdx.x;
    const int wid = tid >> 5;
    const int lane = tid & 31;
    const int G = lane >> 2;
    const int T = lane & 3;
    const int wm = (wid >> 2) * 64;
    const int wn = (wid & 3) * 32;
    const int bm = blockIdx.y * 128;
    const int bn = blockIdx.x * 128;
    const int z = blockIdx.z;

    const bf16* Wh = (z == 0) ? Wh0 : (z == 1) ? Wh1 : Wh2;
    const bf16* Wl = (z == 0) ? Wl0 : (z == 1) ? Wl1 : Wl2;
    const float* bias = (z == 0) ? b0v : (z == 1) ? b1v : b2v;
    void* C = (z == 0) ? C0 : (z == 1) ? C1 : C2;
    const int mode = (z == 0) ? m0 : (z == 1) ? m1 : m2;

    float c[4][4][4];
#pragma unroll
    for (int mt = 0; mt < 4; mt++)
#pragma unroll
        for (int nt = 0; nt < 4; nt++)
#pragma unroll
            for (int i = 0; i < 4; i++) c[mt][nt][i] = 0.0f;

    gemmb_load(Ah, Al, Wh, Wl, bm, bn, base, tid, 0, 0);
    CP_COMMIT();

    const int NIT = KDIM / BBK;
    for (int k = 0; k < NIT; k++) {
        if (k + 1 < NIT) {
            gemmb_load(Ah, Al, Wh, Wl, bm, bn, base, tid, (k + 1) * BBK, (k + 1) & 1);
            CP_COMMIT();
            CP_WAIT(1);
        } else {
            CP_WAIT(0);
        }
        __syncthreads();

        const bf16* Ahs = smem + (k & 1) * B_STAGE;
        const bf16* Als = Ahs + B_TILE;
        const bf16* Bhs = Als + B_TILE;
        const bf16* Bls = Bhs + B_TILE;

#pragma unroll
        for (int ko = 0; ko < BBK; ko += 16) {
            uint32_t bh_[4][2], bl_[4][2];
#pragma unroll
            for (int nt = 0; nt < 4; nt++) {
                const bf16* pb = Bhs + (wn + nt * 8 + G) * BRS + ko + 2 * T;
                bh_[nt][0] = *(const uint32_t*)pb;
                bh_[nt][1] = *(const uint32_t*)(pb + 8);
                const bf16* pl = Bls + (wn + nt * 8 + G) * BRS + ko + 2 * T;
                bl_[nt][0] = *(const uint32_t*)pl;
                bl_[nt][1] = *(const uint32_t*)(pl + 8);
            }
#pragma unroll
            for (int mt = 0; mt < 4; mt++) {
                const int r0 = (wm + mt * 16 + G) * BRS + ko + 2 * T;
                const int r1 = (wm + mt * 16 + G + 8) * BRS + ko + 2 * T;
                uint32_t ah0 = *(const uint32_t*)(Ahs + r0);
                uint32_t ah1 = *(const uint32_t*)(Ahs + r1);
                uint32_t ah2 = *(const uint32_t*)(Ahs + r0 + 8);
                uint32_t ah3 = *(const uint32_t*)(Ahs + r1 + 8);
                uint32_t al0 = *(const uint32_t*)(Als + r0);
                uint32_t al1 = *(const uint32_t*)(Als + r1);
                uint32_t al2 = *(const uint32_t*)(Als + r0 + 8);
                uint32_t al3 = *(const uint32_t*)(Als + r1 + 8);
#pragma unroll
                for (int nt = 0; nt < 4; nt++) {
                    mma_bf16(c[mt][nt], ah0, ah1, ah2, ah3, bh_[nt][0], bh_[nt][1]);
                    mma_bf16(c[mt][nt], al0, al1, al2, al3, bh_[nt][0], bh_[nt][1]);
                    mma_bf16(c[mt][nt], ah0, ah1, ah2, ah3, bl_[nt][0], bl_[nt][1]);
                }
            }
        }
        __syncthreads();
    }

#pragma unroll
    for (int mt = 0; mt < 4; mt++) {
#pragma unroll
        for (int half = 0; half < 2; half++) {
            const int gm = bm + wm + mt * 16 + G + half * 8;
            const int b_ = gm >> 11;
            const int s_ = gm & 2047;
#pragma unroll
            for (int nt = 0; nt < 4; nt++) {
                const int gn = bn + wn + nt * 8 + 2 * T;
                float2 bv = *(const float2*)&bias[gn];
                float vx = c[mt][nt][half * 2 + 0] + bv.x;
                float vy = c[mt][nt][half * 2 + 1] + bv.y;
                const int h = gn >> 6, d = gn & 63;
                if (mode == 0) {
                    float2 v; v.x = vx; v.y = vy;
                    *(float2*)((float*)C + (size_t)gm * DMODEL + gn) = v;
                } else if (mode == 1) {
                    __half2 v = __floats2half2_rn(vx * 0.125f, vy * 0.125f);
                    *(__half2*)((__half*)C + (((size_t)(b_ * NHEAD + h) * SEQ) + s_) * DK + d) = v;
                } else if (mode == 2) {
                    __half2 v = __floats2half2_rn(vx, vy);
                    *(__half2*)((__half*)C + (((size_t)(b_ * NHEAD + h) * SEQ) + s_) * DK + d) = v;
                } else {
                    __half* Cb = (__half*)C + ((size_t)(b_ * NHEAD + h) * DK + d) * SEQ + s_;
                    Cb[0]   = __float2half_rn(vx);
                    Cb[SEQ] = __float2half_rn(vy);
                }
            }
        }
    }
}

// ---------------- FP16 mma flash attention: 8 warps x 16 q-rows -------------
// Q,K fp16 [B,H,s,d]; V fp16 [B,H,d,s]. smem stride 72 fp16 -> conflict-free.
#define AST2 72
#define A_PS 0
#define A_K0 (128 * AST2)
#define A_KB (64 * AST2)
#define A_V0 (A_K0 + 2 * A_KB)
#define A_VB (64 * AST2)
#define A_SMEM ((A_V0 + 2 * A_VB) * 2)   // 55296 B

__global__ void __launch_bounds__(256, 2) attn_mma(
    const __half* __restrict__ Qg, const __half* __restrict__ Kg,
    const __half* __restrict__ Vg, bf16* __restrict__ Ohi,
    bf16* __restrict__ Olo)
{
    extern __shared__ __half sh[];
    const uint32_t base = smem_u32(sh);
    __half* Ps = sh + A_PS;

    const int tid = threadIdx.x;
    const int w = tid >> 5;
    const int lane = tid & 31;
    const int G = lane >> 2;
    const int T = lane & 3;
    const int bh = blockIdx.y;
    const int q0 = blockIdx.x * 128;
    const int wrow = w * 16;

    const __half* Qb = Qg + ((size_t)bh * SEQ + q0) * DK;
    const __half* Kb = Kg + (size_t)bh * SEQ * DK;
    const __half* Vb = Vg + (size_t)bh * DK * SEQ;

    const int ld = tid >> 2;          // 0..63
    const int lh = (tid & 3) * 16;    // fp16 col offset

    // prologue: Q (into Ps region) + KV tile0 | KV tile1
    {
        const int qr = tid >> 1;
        const int qh = (tid & 1) * 32;
        const __half* qsrc = Qb + (size_t)qr * DK + qh;
        const uint32_t qdst = base + (uint32_t)(qr * AST2 + qh) * 2;
#pragma unroll
        for (int c = 0; c < 4; c++) CP_ASYNC16(qdst + c * 16, qsrc + c * 8);
    }
    {
        const __half* ks = Kb + (size_t)ld * DK + lh;
        const uint32_t kd = base + (uint32_t)(A_K0 + ld * AST2 + lh) * 2;
        const __half* vs = Vb + (size_t)ld * SEQ + lh;
        const uint32_t vd = base + (uint32_t)(A_V0 + ld * AST2 + lh) * 2;
        CP_ASYNC16(kd, ks); CP_ASYNC16(kd + 16, ks + 8);
        CP_ASYNC16(vd, vs); CP_ASYNC16(vd + 16, vs + 8);
    }
    CP_COMMIT();
    {
        const __half* ks = Kb + (size_t)(64 + ld) * DK + lh;
        const uint32_t kd = base + (uint32_t)(A_K0 + A_KB + ld * AST2 + lh) * 2;
        const __half* vs = Vb + (size_t)ld * SEQ + 64 + lh;
        const uint32_t vd = base + (uint32_t)(A_V0 + A_VB + ld * AST2 + lh) * 2;
        CP_ASYNC16(kd, ks); CP_ASYNC16(kd + 16, ks + 8);
        CP_ASYNC16(vd, vs); CP_ASYNC16(vd + 16, vs + 8);
    }
    CP_COMMIT();
    CP_WAIT(1);
    __syncthreads();

    // hoist Q fragments (4 k16 slices over DK=64)
    uint32_t qa[4][4];
#pragma unroll
    for (int ki = 0; ki < 4; ki++) {
        const int r0 = (wrow + G) * AST2 + ki * 16 + 2 * T;
        const int r1 = r0 + 8 * AST2;
        qa[ki][0] = *(const uint32_t*)(Ps + r0);
        qa[ki][1] = *(const uint32_t*)(Ps + r1);
        qa[ki][2] = *(const uint32_t*)(Ps + r0 + 8);
        qa[ki][3] = *(const uint32_t*)(Ps + r1 + 8);
    }

    float m_i[2] = {-1e30f, -1e30f};
    float l_i[2] = {0.0f, 0.0f};
    float acc[8][4];
#pragma unroll
    for (int dt = 0; dt < 8; dt++)
#pragma unroll
        for (int i = 0; i < 4; i++) acc[dt][i] = 0.0f;

    const int NKT = SEQ / 64;   // 32
    for (int it = 0; it < NKT; it++) {
        if (it) { CP_WAIT(1); __syncthreads(); }

        const __half* Ks2 = sh + A_K0 + (it & 1) * A_KB;
        const __half* Vs2 = sh + A_V0 + (it & 1) * A_VB;

        // ---- QK^T (fp16 k16)
        float s[8][4];
#pragma unroll
        for (int nt = 0; nt < 8; nt++)
#pragma unroll
            for (int i = 0; i < 4; i++) s[nt][i] = 0.0f;

#pragma unroll
        for (int ki = 0; ki < 4; ki++) {
            const int ko = ki * 16;
#pragma unroll
            for (int nt = 0; nt < 8; nt++) {
                const __half* pb = Ks2 + (nt * 8 + G) * AST2 + ko + 2 * T;
                uint32_t b0 = *(const uint32_t*)pb;
                uint32_t b1 = *(const uint32_t*)(pb + 8);
                mma_f16(s[nt], qa[ki][0], qa[ki][1], qa[ki][2], qa[ki][3], b0, b1);
            }
        }

        // ---- online softmax (fp16-rounded P, consistent l)
        float fac[2];
#pragma unroll
        for (int r = 0; r < 2; r++) {
            float mx = -1e30f;
#pragma unroll
            for (int nt = 0; nt < 8; nt++)
                mx = fmaxf(mx, fmaxf(s[nt][2 * r], s[nt][2 * r + 1]));
            mx = fmaxf(mx, __shfl_xor_sync(0xffffffffu, mx, 1));
            mx = fmaxf(mx, __shfl_xor_sync(0xffffffffu, mx, 2));
            const float mn = fmaxf(m_i[r], mx);
            fac[r] = __expf(m_i[r] - mn);
            m_i[r] = mn;
            float ls = 0.0f;
#pragma unroll
            for (int nt = 0; nt < 8; nt++) {
                float p0 = __half2float(__float2half_rn(__expf(s[nt][2 * r + 0] - mn)));
                float p1 = __half2float(__float2half_rn(__expf(s[nt][2 * r + 1] - mn)));
                s[nt][2 * r + 0] = p0;
                s[nt][2 * r + 1] = p1;
                ls += p0 + p1;
            }
            ls += __shfl_xor_sync(0xffffffffu, ls, 1);
            ls += __shfl_xor_sync(0xffffffffu, ls, 2);
            l_i[r] = l_i[r] * fac[r] + ls;
        }

        // ---- store P as fp16 (warp-private rows)
#pragma unroll
        for (int nt = 0; nt < 8; nt++) {
            *(__half2*)(Ps + (wrow + G) * AST2 + nt * 8 + 2 * T) =
                __floats2half2_rn(s[nt][0], s[nt][1]);
            *(__half2*)(Ps + (wrow + G + 8) * AST2 + nt * 8 + 2 * T) =
                __floats2half2_rn(s[nt][2], s[nt][3]);
        }
        __syncwarp();

        // ---- rescale accumulators
#pragma unroll
        for (int dt = 0; dt < 8; dt++) {
            acc[dt][0] *= fac[0];
            acc[dt][1] *= fac[0];
            acc[dt][2] *= fac[1];
            acc[dt][3] *= fac[1];
        }

        // ---- PV (fp16 k16): A = P rows, B = Vs[d][kv]
#pragma unroll
        for (int ki = 0; ki < 4; ki++) {
            const int ko = ki * 16;
            const int r0 = (wrow + G) * AST2 + ko + 2 * T;
            const int r1 = r0 + 8 * AST2;
            uint32_t a0 = *(const uint32_t*)(Ps + r0);
            uint32_t a1 = *(const uint32_t*)(Ps + r1);
            uint32_t a2 = *(const uint32_t*)(Ps + r0 + 8);
            uint32_t a3 = *(const uint32_t*)(Ps + r1 + 8);
#pragma unroll
            for (int dt = 0; dt < 8; dt++) {
                const __half* pb = Vs2 + (dt * 8 + G) * AST2 + ko + 2 * T;
                uint32_t b0 = *(const uint32_t*)pb;
                uint32_t b1 = *(const uint32_t*)(pb + 8);
                mma_f16(acc[dt], a0, a1, a2, a3, b0, b1);
            }
        }

        __syncthreads();
        if (it + 2 < NKT) {
            const int kt2 = (it + 2) * 64;
            const __half* ks = Kb + (size_t)(kt2 + ld) * DK + lh;
            const uint32_t kd = base + (uint32_t)(A_K0 + (it & 1) * A_KB + ld * AST2 + lh) * 2;
            const __half* vs = Vb + (size_t)ld * SEQ + kt2 + lh;
            const uint32_t vd = base + (uint32_t)(A_V0 + (it & 1) * A_VB + ld * AST2 + lh) * 2;
            CP_ASYNC16(kd, ks); CP_ASYNC16(kd + 16, ks + 8);
            CP_ASYNC16(vd, vs); CP_ASYNC16(vd + 16, vs + 8);
        }
        CP_COMMIT();
    }

    // ---- epilogue: normalize, bf16 hi/lo split
    const int b = bh >> 4;
    const int h = bh & 15;
    const float inv0 = 1.0f / l_i[0];
    const float inv1 = 1.0f / l_i[1];
    const int r0 = q0 + wrow + G;
    const int r1 = r0 + 8;
    const size_t o0 = ((size_t)b * SEQ + r0) * DMODEL + h * DK;
    const size_t o1 = ((size_t)b * SEQ + r1) * DMODEL + h * DK;
#pragma unroll
    for (int dt = 0; dt < 8; dt++) {
        const int d = dt * 8 + 2 * T;
        float x0 = acc[dt][0] * inv0, y0 = acc[dt][1] * inv0;
        float x1 = acc[dt][2] * inv1, y1 = acc[dt][3] * inv1;
        __nv_bfloat162 h0, l0, h1, l1;
        bf16 hh, ll;
        bf16_split(x0, hh, ll); h0.x = hh; l0.x = ll;
        bf16_split(y0, hh, ll); h0.y = hh; l0.y = ll;
        bf16_split(x1, hh, ll); h1.x = hh; l1.x = ll;
        bf16_split(y1, hh, ll); h1.y = hh; l1.y = ll;
        *(__nv_bfloat162*)&Ohi[o0 + d] = h0;
        *(__nv_bfloat162*)&Olo[o0 + d] = l0;
        *(__nv_bfloat162*)&Ohi[o1 + d] = h1;
        *(__nv_bfloat162*)&Olo[o1 + d] = l1;
    }
}

// ---------------- launch ----------------
extern "C" void kernel_launch(void* const* d_in, const int* in_sizes, int n_in,
                              void* d_out, int out_size)
{
    const float* x  = (const float*)d_in[0];
    const float* Wq = (const float*)d_in[1];
    const float* bq = (const float*)d_in[2];
    const float* Wk = (const float*)d_in[3];
    const float* bk = (const float*)d_in[4];
    const float* Wv = (const float*)d_in[5];
    const float* bv = (const float*)d_in[6];
    const float* Wo = (const float*)d_in[7];
    const float* bo = (const float*)d_in[8];
    float* out = (float*)d_out;

    __half *gq, *gk, *gv;
    bf16 *gxh, *gxl, *gah, *gal;
    bf16 *wqh, *wql, *wkh, *wkl, *wvh, *wvl, *woh, *wol;
    cudaGetSymbolAddress((void**)&gq,  g_q);
    cudaGetSymbolAddress((void**)&gk,  g_k);
    cudaGetSymbolAddress((void**)&gv,  g_v);
    cudaGetSymbolAddress((void**)&gxh, g_xh);
    cudaGetSymbolAddress((void**)&gxl, g_xl);
    cudaGetSymbolAddress((void**)&gah, g_aoh);
    cudaGetSymbolAddress((void**)&gal, g_aol);
    cudaGetSymbolAddress((void**)&wqh, g_wqh);
    cudaGetSymbolAddress((void**)&wql, g_wql);
    cudaGetSymbolAddress((void**)&wkh, g_wkh);
    cudaGetSymbolAddress((void**)&wkl, g_wkl);
    cudaGetSymbolAddress((void**)&wvh, g_wvh);
    cudaGetSymbolAddress((void**)&wvl, g_wvl);
    cudaGetSymbolAddress((void**)&woh, g_woh);
    cudaGetSymbolAddress((void**)&wol, g_wol);

    cudaFuncSetAttribute(gemm3_bf16, cudaFuncAttributeMaxDynamicSharedMemorySize,
                         B_SMEM);
    cudaFuncSetAttribute(attn_mma, cudaFuncAttributeMaxDynamicSharedMemorySize,
                         A_SMEM);

    split_all_kernel<<<(NTASK + 255) / 256, 256>>>(
        x, Wq, Wk, Wv, Wo, gxh, gxl,
        wqh, wql, wkh, wkl, wvh, wvl, woh, wol);

    dim3 gqkv(DMODEL / 128, MROWS / 128, 3);
    gemm3_bf16<<<gqkv, 256, B_SMEM>>>(gxh, gxl,
                                      wqh, wql, bq, gq,
                                      wkh, wkl, bk, gk,
                                      wvh, wvl, bv, gv, 1, 2, 3);

    attn_mma<<<dim3(SEQ / 128, BATCH * NHEAD), 256, A_SMEM>>>(gq, gk, gv, gah, gal);

    dim3 go(DMODEL / 128, MROWS / 128, 1);
    gemm3_bf16<<<go, 256, B_SMEM>>>(gah, gal,
                                    woh, wol, bo, out,
                                    woh, wol, bo, out,
                                    woh, wol, bo, out, 0, 0, 0);
}

// round 11
// speedup vs baseline: 4.2862x; 1.0292x over previous
#include <cuda_runtime.h>
#include <cuda_bf16.h>
#include <cuda_fp16.h>
#include <cstdint>
#include <cstddef>

#define BATCH  2
#define SEQ    2048
#define DMODEL 1024
#define NHEAD  16
#define DK     64
#define MROWS  (BATCH * SEQ)
#define KDIM   1024

typedef __nv_bfloat16 bf16;

__device__ __half g_q[BATCH * NHEAD * SEQ * DK];
__device__ __half g_k[BATCH * NHEAD * SEQ * DK];
__device__ __half g_v[BATCH * NHEAD * DK * SEQ];
__device__ bf16  g_xh[MROWS * DMODEL];
__device__ bf16  g_xl[MROWS * DMODEL];
__device__ bf16  g_aoh[MROWS * DMODEL];
__device__ bf16  g_aol[MROWS * DMODEL];
__device__ bf16  g_wqh[DMODEL * DMODEL];
__device__ bf16  g_wql[DMODEL * DMODEL];
__device__ bf16  g_wkh[DMODEL * DMODEL];
__device__ bf16  g_wkl[DMODEL * DMODEL];
__device__ bf16  g_wvh[DMODEL * DMODEL];
__device__ bf16  g_wvl[DMODEL * DMODEL];
__device__ bf16  g_woh[DMODEL * DMODEL];
__device__ bf16  g_wol[DMODEL * DMODEL];

__device__ __forceinline__ uint32_t smem_u32(const void* p) {
    uint32_t a;
    asm("{ .reg .u64 t; cvta.to.shared.u64 t, %1; cvt.u32.u64 %0, t; }"
        : "=r"(a) : "l"(p));
    return a;
}

#define CP_ASYNC16(dst_u32, src_ptr) \
    asm volatile("cp.async.cg.shared.global [%0], [%1], 16;" \
        :: "r"(dst_u32), "l"((const void*)(src_ptr)) : "memory")
#define CP_COMMIT() asm volatile("cp.async.commit_group;" ::: "memory")
#define CP_WAIT(n)  asm volatile("cp.async.wait_group %0;" :: "n"(n) : "memory")

#define LDSM_X4(r0, r1, r2, r3, addr) \
    asm volatile("ldmatrix.sync.aligned.m8n8.x4.shared.b16 {%0,%1,%2,%3}, [%4];" \
        : "=r"(r0), "=r"(r1), "=r"(r2), "=r"(r3) : "r"(addr))

__device__ __forceinline__ void mma_bf16(float c[4], uint32_t a0, uint32_t a1,
                                         uint32_t a2, uint32_t a3,
                                         uint32_t b0, uint32_t b1) {
    asm volatile(
        "mma.sync.aligned.m16n8k16.row.col.f32.bf16.bf16.f32 "
        "{%0,%1,%2,%3}, {%4,%5,%6,%7}, {%8,%9}, {%0,%1,%2,%3};"
        : "+f"(c[0]), "+f"(c[1]), "+f"(c[2]), "+f"(c[3])
        : "r"(a0), "r"(a1), "r"(a2), "r"(a3), "r"(b0), "r"(b1));
}

__device__ __forceinline__ void mma_f16(float c[4], uint32_t a0, uint32_t a1,
                                        uint32_t a2, uint32_t a3,
                                        uint32_t b0, uint32_t b1) {
    asm volatile(
        "mma.sync.aligned.m16n8k16.row.col.f32.f16.f16.f32 "
        "{%0,%1,%2,%3}, {%4,%5,%6,%7}, {%8,%9}, {%0,%1,%2,%3};"
        : "+f"(c[0]), "+f"(c[1]), "+f"(c[2]), "+f"(c[3])
        : "r"(a0), "r"(a1), "r"(a2), "r"(a3), "r"(b0), "r"(b1));
}

__device__ __forceinline__ void bf16_split(float v, bf16& h, bf16& l) {
    h = __float2bfloat16_rn(v);
    l = __float2bfloat16_rn(v - __bfloat162float(h));
}

// ---------------- fused hi/lo bf16 split pre-pass ----------------
#define NX4 ((MROWS * DMODEL) / 4)
#define NW4 ((DMODEL * DMODEL) / 4)
#define NTASK (NX4 + 4 * NW4)

__global__ void split_all_kernel(
    const float* __restrict__ x,
    const float* __restrict__ Wq, const float* __restrict__ Wk,
    const float* __restrict__ Wv, const float* __restrict__ Wo,
    bf16* __restrict__ xh, bf16* __restrict__ xl,
    bf16* __restrict__ wqh, bf16* __restrict__ wql,
    bf16* __restrict__ wkh, bf16* __restrict__ wkl,
    bf16* __restrict__ wvh, bf16* __restrict__ wvl,
    bf16* __restrict__ woh, bf16* __restrict__ wol)
{
    int i = blockIdx.x * blockDim.x + threadIdx.x;
    if (i >= NTASK) return;
    const float* in;
    bf16 *oh, *ol;
    int o;
    if (i < NX4) {
        in = x; oh = xh; ol = xl; o = i;
    } else {
        int j = i - NX4;
        int t = j / NW4;
        o = j - t * NW4;
        in = (t == 0) ? Wq : (t == 1) ? Wk : (t == 2) ? Wv : Wo;
        oh = (t == 0) ? wqh : (t == 1) ? wkh : (t == 2) ? wvh : woh;
        ol = (t == 0) ? wql : (t == 1) ? wkl : (t == 2) ? wvl : wol;
    }
    float4 v = ((const float4*)in)[o];
    __nv_bfloat162 h0, h1, l0, l1;
    bf16 h, l;
    bf16_split(v.x, h, l); h0.x = h; l0.x = l;
    bf16_split(v.y, h, l); h0.y = h; l0.y = l;
    bf16_split(v.z, h, l); h1.x = h; l1.x = l;
    bf16_split(v.w, h, l); h1.y = h; l1.y = l;
    ((__nv_bfloat162*)oh)[2 * o + 0] = h0;
    ((__nv_bfloat162*)oh)[2 * o + 1] = h1;
    ((__nv_bfloat162*)ol)[2 * o + 0] = l0;
    ((__nv_bfloat162*)ol)[2 * o + 1] = l1;
}

// ---------------- 3xBF16 GEMM (ldmatrix fragments) ----------------
// modes: 0 fp32 row-major+bias; 1 Q fp16 [B,H,s,d]*0.125; 2 K fp16 [B,H,s,d];
//        3 V fp16 [B,H,d,s]
#define BBK 32
#define BRS 40
#define B_TILE (128 * BRS)
#define B_STAGE (4 * B_TILE)
#define B_SMEM (2 * B_STAGE * 2)

__device__ __forceinline__ void gemmb_load(
    const bf16* __restrict__ Ah, const bf16* __restrict__ Al,
    const bf16* __restrict__ Wh, const bf16* __restrict__ Wl,
    int bm, int bn, uint32_t base, int tid, int k0, int s)
{
    const bf16* bases[4] = {
        Ah + (size_t)bm * KDIM, Al + (size_t)bm * KDIM,
        Wh + (size_t)bn * KDIM, Wl + (size_t)bn * KDIM };
    const uint32_t st = base + (uint32_t)(s * B_STAGE) * 2;
#pragma unroll
    for (int i = 0; i < 8; i++) {
        const int task = tid + 256 * i;
        const int t = task >> 9;
        const int rem = task & 511;
        const int r = rem >> 2;
        const int seg = rem & 3;
        const bf16* src = bases[t] + (size_t)r * KDIM + k0 + seg * 8;
        const uint32_t dst = st + (uint32_t)(t * B_TILE + r * BRS + seg * 8) * 2;
        CP_ASYNC16(dst, src);
    }
}

__global__ void __launch_bounds__(256, 2) gemm3_bf16(
    const bf16* __restrict__ Ah, const bf16* __restrict__ Al,
    const bf16* __restrict__ Wh0, const bf16* __restrict__ Wl0,
    const float* __restrict__ b0v, void* __restrict__ C0,
    const bf16* __restrict__ Wh1, const bf16* __restrict__ Wl1,
    const float* __restrict__ b1v, void* __restrict__ C1,
    const bf16* __restrict__ Wh2, const bf16* __restrict__ Wl2,
    const float* __restrict__ b2v, void* __restrict__ C2,
    int m0, int m1, int m2)
{
    extern __shared__ char smem_raw[];
    const uint32_t base = smem_u32(smem_raw);
    const int tid = threadIdx.x;
    const int wid = tid >> 5;
    const int lane = tid & 31;
    const int G = lane >> 2;
    const int T = lane & 3;
    const int wm = (wid >> 2) * 64;
    const int wn = (wid & 3) * 32;
    const int bm = blockIdx.y * 128;
    const int bn = blockIdx.x * 128;
    const int z = blockIdx.z;

    const bf16* Wh = (z == 0) ? Wh0 : (z == 1) ? Wh1 : Wh2;
    const bf16* Wl = (z == 0) ? Wl0 : (z == 1) ? Wl1 : Wl2;
    const float* bias = (z == 0) ? b0v : (z == 1) ? b1v : b2v;
    void* C = (z == 0) ? C0 : (z == 1) ? C1 : C2;
    const int mode = (z == 0) ? m0 : (z == 1) ? m1 : m2;

    // ldmatrix lane offsets
    const int a_r = lane & 15;
    const int a_c = (lane & 16) ? 8 : 0;
    const int b_r = (lane & 7) + ((lane & 16) ? 8 : 0);
    const int b_c = (lane & 8) ? 8 : 0;
    const uint32_t a_addr0 = base + (uint32_t)((wm + a_r) * BRS + a_c) * 2;
    const uint32_t b_addr0 = base + (uint32_t)((wn + b_r) * BRS + b_c) * 2
                           + (uint32_t)(2 * B_TILE) * 2;

    float c[4][4][4];
#pragma unroll
    for (int mt = 0; mt < 4; mt++)
#pragma unroll
        for (int nt = 0; nt < 4; nt++)
#pragma unroll
            for (int i = 0; i < 4; i++) c[mt][nt][i] = 0.0f;

    gemmb_load(Ah, Al, Wh, Wl, bm, bn, base, tid, 0, 0);
    CP_COMMIT();

    const int NIT = KDIM / BBK;
    for (int k = 0; k < NIT; k++) {
        if (k + 1 < NIT) {
            gemmb_load(Ah, Al, Wh, Wl, bm, bn, base, tid, (k + 1) * BBK, (k + 1) & 1);
            CP_COMMIT();
            CP_WAIT(1);
        } else {
            CP_WAIT(0);
        }
        __syncthreads();

        const uint32_t sb = (uint32_t)((k & 1) * B_STAGE) * 2;
        const uint32_t tile2 = (uint32_t)B_TILE * 2;

#pragma unroll
        for (int ko = 0; ko < BBK; ko += 16) {
            uint32_t bh_[4][2], bl_[4][2];
#pragma unroll
            for (int ntp = 0; ntp < 2; ntp++) {
                const uint32_t ba = b_addr0 + sb + (uint32_t)(ntp * 16 * BRS + ko) * 2;
                LDSM_X4(bh_[2 * ntp][0], bh_[2 * ntp][1],
                        bh_[2 * ntp + 1][0], bh_[2 * ntp + 1][1], ba);
                LDSM_X4(bl_[2 * ntp][0], bl_[2 * ntp][1],
                        bl_[2 * ntp + 1][0], bl_[2 * ntp + 1][1], ba + tile2);
            }
#pragma unroll
            for (int mt = 0; mt < 4; mt++) {
                const uint32_t aa = a_addr0 + sb + (uint32_t)(mt * 16 * BRS + ko) * 2;
                uint32_t ah0, ah1, ah2, ah3, al0, al1, al2, al3;
                LDSM_X4(ah0, ah1, ah2, ah3, aa);
                LDSM_X4(al0, al1, al2, al3, aa + tile2);
#pragma unroll
                for (int nt = 0; nt < 4; nt++) {
                    mma_bf16(c[mt][nt], ah0, ah1, ah2, ah3, bh_[nt][0], bh_[nt][1]);
                    mma_bf16(c[mt][nt], al0, al1, al2, al3, bh_[nt][0], bh_[nt][1]);
                    mma_bf16(c[mt][nt], ah0, ah1, ah2, ah3, bl_[nt][0], bl_[nt][1]);
                }
            }
        }
        __syncthreads();
    }

#pragma unroll
    for (int mt = 0; mt < 4; mt++) {
#pragma unroll
        for (int half = 0; half < 2; half++) {
            const int gm = bm + wm + mt * 16 + G + half * 8;
            const int b_ = gm >> 11;
            const int s_ = gm & 2047;
#pragma unroll
            for (int nt = 0; nt < 4; nt++) {
                const int gn = bn + wn + nt * 8 + 2 * T;
                float2 bv = *(const float2*)&bias[gn];
                float vx = c[mt][nt][half * 2 + 0] + bv.x;
                float vy = c[mt][nt][half * 2 + 1] + bv.y;
                const int h = gn >> 6, d = gn & 63;
                if (mode == 0) {
                    float2 v; v.x = vx; v.y = vy;
                    *(float2*)((float*)C + (size_t)gm * DMODEL + gn) = v;
                } else if (mode == 1) {
                    __half2 v = __floats2half2_rn(vx * 0.125f, vy * 0.125f);
                    *(__half2*)((__half*)C + (((size_t)(b_ * NHEAD + h) * SEQ) + s_) * DK + d) = v;
                } else if (mode == 2) {
                    __half2 v = __floats2half2_rn(vx, vy);
                    *(__half2*)((__half*)C + (((size_t)(b_ * NHEAD + h) * SEQ) + s_) * DK + d) = v;
                } else {
                    __half* Cb = (__half*)C + ((size_t)(b_ * NHEAD + h) * DK + d) * SEQ + s_;
                    Cb[0]   = __float2half_rn(vx);
                    Cb[SEQ] = __float2half_rn(vy);
                }
            }
        }
    }
}

// ---------------- FP16 mma flash attention (ldmatrix fragments) -------------
#define AST2 72
#define A_PS 0
#define A_K0 (128 * AST2)
#define A_KB (64 * AST2)
#define A_V0 (A_K0 + 2 * A_KB)
#define A_VB (64 * AST2)
#define A_SMEM ((A_V0 + 2 * A_VB) * 2)   // 55296 B

__global__ void __launch_bounds__(256, 2) attn_mma(
    const __half* __restrict__ Qg, const __half* __restrict__ Kg,
    const __half* __restrict__ Vg, bf16* __restrict__ Ohi,
    bf16* __restrict__ Olo)
{
    extern __shared__ __half sh[];
    const uint32_t base = smem_u32(sh);
    __half* Ps = sh + A_PS;

    const int tid = threadIdx.x;
    const int w = tid >> 5;
    const int lane = tid & 31;
    const int G = lane >> 2;
    const int T = lane & 3;
    const int bh = blockIdx.y;
    const int q0 = blockIdx.x * 128;
    const int wrow = w * 16;

    const __half* Qb = Qg + ((size_t)bh * SEQ + q0) * DK;
    const __half* Kb = Kg + (size_t)bh * SEQ * DK;
    const __half* Vb = Vg + (size_t)bh * DK * SEQ;

    const int ld = tid >> 2;
    const int lh = (tid & 3) * 16;

    // ldmatrix lane offsets
    const int a_r = lane & 15;
    const int a_c = (lane & 16) ? 8 : 0;
    const int b_r = (lane & 7) + ((lane & 16) ? 8 : 0);
    const int b_c = (lane & 8) ? 8 : 0;
    const uint32_t pa0 = base + (uint32_t)((wrow + a_r) * AST2 + a_c) * 2;

    // prologue: Q + KV tile0 | KV tile1
    {
        const int qr = tid >> 1;
        const int qh = (tid & 1) * 32;
        const __half* qsrc = Qb + (size_t)qr * DK + qh;
        const uint32_t qdst = base + (uint32_t)(qr * AST2 + qh) * 2;
#pragma unroll
        for (int c = 0; c < 4; c++) CP_ASYNC16(qdst + c * 16, qsrc + c * 8);
    }
    {
        const __half* ks = Kb + (size_t)ld * DK + lh;
        const uint32_t kd = base + (uint32_t)(A_K0 + ld * AST2 + lh) * 2;
        const __half* vs = Vb + (size_t)ld * SEQ + lh;
        const uint32_t vd = base + (uint32_t)(A_V0 + ld * AST2 + lh) * 2;
        CP_ASYNC16(kd, ks); CP_ASYNC16(kd + 16, ks + 8);
        CP_ASYNC16(vd, vs); CP_ASYNC16(vd + 16, vs + 8);
    }
    CP_COMMIT();
    {
        const __half* ks = Kb + (size_t)(64 + ld) * DK + lh;
        const uint32_t kd = base + (uint32_t)(A_K0 + A_KB + ld * AST2 + lh) * 2;
        const __half* vs = Vb + (size_t)ld * SEQ + 64 + lh;
        const uint32_t vd = base + (uint32_t)(A_V0 + A_VB + ld * AST2 + lh) * 2;
        CP_ASYNC16(kd, ks); CP_ASYNC16(kd + 16, ks + 8);
        CP_ASYNC16(vd, vs); CP_ASYNC16(vd + 16, vs + 8);
    }
    CP_COMMIT();
    CP_WAIT(1);
    __syncthreads();

    // hoist Q fragments via ldmatrix
    uint32_t qa[4][4];
#pragma unroll
    for (int ki = 0; ki < 4; ki++)
        LDSM_X4(qa[ki][0], qa[ki][1], qa[ki][2], qa[ki][3],
                pa0 + (uint32_t)(ki * 16) * 2);

    float m_i[2] = {-1e30f, -1e30f};
    float l_i[2] = {0.0f, 0.0f};
    float acc[8][4];
#pragma unroll
    for (int dt = 0; dt < 8; dt++)
#pragma unroll
        for (int i = 0; i < 4; i++) acc[dt][i] = 0.0f;

    const int NKT = SEQ / 64;
    for (int it = 0; it < NKT; it++) {
        if (it) { CP_WAIT(1); __syncthreads(); }

        const uint32_t kbase = base + (uint32_t)(A_K0 + (it & 1) * A_KB) * 2
                             + (uint32_t)(b_r * AST2 + b_c) * 2;
        const uint32_t vbase = base + (uint32_t)(A_V0 + (it & 1) * A_VB) * 2
                             + (uint32_t)(b_r * AST2 + b_c) * 2;

        // ---- QK^T
        float s[8][4];
#pragma unroll
        for (int nt = 0; nt < 8; nt++)
#pragma unroll
            for (int i = 0; i < 4; i++) s[nt][i] = 0.0f;

#pragma unroll
        for (int ki = 0; ki < 4; ki++) {
            const int ko = ki * 16;
            uint32_t kb[8][2];
#pragma unroll
            for (int ntp = 0; ntp < 4; ntp++)
                LDSM_X4(kb[2 * ntp][0], kb[2 * ntp][1],
                        kb[2 * ntp + 1][0], kb[2 * ntp + 1][1],
                        kbase + (uint32_t)(ntp * 16 * AST2 + ko) * 2);
#pragma unroll
            for (int nt = 0; nt < 8; nt++)
                mma_f16(s[nt], qa[ki][0], qa[ki][1], qa[ki][2], qa[ki][3],
                        kb[nt][0], kb[nt][1]);
        }

        // ---- online softmax
        float fac[2];
#pragma unroll
        for (int r = 0; r < 2; r++) {
            float mx = -1e30f;
#pragma unroll
            for (int nt = 0; nt < 8; nt++)
                mx = fmaxf(mx, fmaxf(s[nt][2 * r], s[nt][2 * r + 1]));
            mx = fmaxf(mx, __shfl_xor_sync(0xffffffffu, mx, 1));
            mx = fmaxf(mx, __shfl_xor_sync(0xffffffffu, mx, 2));
            const float mn = fmaxf(m_i[r], mx);
            fac[r] = __expf(m_i[r] - mn);
            m_i[r] = mn;
            float ls = 0.0f;
#pragma unroll
            for (int nt = 0; nt < 8; nt++) {
                float p0 = __half2float(__float2half_rn(__expf(s[nt][2 * r + 0] - mn)));
                float p1 = __half2float(__float2half_rn(__expf(s[nt][2 * r + 1] - mn)));
                s[nt][2 * r + 0] = p0;
                s[nt][2 * r + 1] = p1;
                ls += p0 + p1;
            }
            ls += __shfl_xor_sync(0xffffffffu, ls, 1);
            ls += __shfl_xor_sync(0xffffffffu, ls, 2);
            l_i[r] = l_i[r] * fac[r] + ls;
        }

        // ---- store P (fp16, warp-private rows)
#pragma unroll
        for (int nt = 0; nt < 8; nt++) {
            *(__half2*)(Ps + (wrow + G) * AST2 + nt * 8 + 2 * T) =
                __floats2half2_rn(s[nt][0], s[nt][1]);
            *(__half2*)(Ps + (wrow + G + 8) * AST2 + nt * 8 + 2 * T) =
                __floats2half2_rn(s[nt][2], s[nt][3]);
        }
        __syncwarp();

        // ---- rescale accumulators
#pragma unroll
        for (int dt = 0; dt < 8; dt++) {
            acc[dt][0] *= fac[0];
            acc[dt][1] *= fac[0];
            acc[dt][2] *= fac[1];
            acc[dt][3] *= fac[1];
        }

        // ---- PV
#pragma unroll
        for (int ki = 0; ki < 4; ki++) {
            const int ko = ki * 16;
            uint32_t a0, a1, a2, a3;
            LDSM_X4(a0, a1, a2, a3, pa0 + (uint32_t)ko * 2);
            uint32_t vb[8][2];
#pragma unroll
            for (int dtp = 0; dtp < 4; dtp++)
                LDSM_X4(vb[2 * dtp][0], vb[2 * dtp][1],
                        vb[2 * dtp + 1][0], vb[2 * dtp + 1][1],
                        vbase + (uint32_t)(dtp * 16 * AST2 + ko) * 2);
#pragma unroll
            for (int dt = 0; dt < 8; dt++)
                mma_f16(acc[dt], a0, a1, a2, a3, vb[dt][0], vb[dt][1]);
        }

        __syncthreads();
        if (it + 2 < NKT) {
            const int kt2 = (it + 2) * 64;
            const __half* ks = Kb + (size_t)(kt2 + ld) * DK + lh;
            const uint32_t kd = base + (uint32_t)(A_K0 + (it & 1) * A_KB + ld * AST2 + lh) * 2;
            const __half* vs = Vb + (size_t)ld * SEQ + kt2 + lh;
            const uint32_t vd = base + (uint32_t)(A_V0 + (it & 1) * A_VB + ld * AST2 + lh) * 2;
            CP_ASYNC16(kd, ks); CP_ASYNC16(kd + 16, ks + 8);
            CP_ASYNC16(vd, vs); CP_ASYNC16(vd + 16, vs + 8);
        }
        CP_COMMIT();
    }

    // ---- epilogue: normalize, bf16 hi/lo split
    const int b = bh >> 4;
    const int h = bh & 15;
    const float inv0 = 1.0f / l_i[0];
    const float inv1 = 1.0f / l_i[1];
    const int r0 = q0 + wrow + G;
    const int r1 = r0 + 8;
    const size_t o0 = ((size_t)b * SEQ + r0) * DMODEL + h * DK;
    const size_t o1 = ((size_t)b * SEQ + r1) * DMODEL + h * DK;
#pragma unroll
    for (int dt = 0; dt < 8; dt++) {
        const int d = dt * 8 + 2 * T;
        float x0 = acc[dt][0] * inv0, y0 = acc[dt][1] * inv0;
        float x1 = acc[dt][2] * inv1, y1 = acc[dt][3] * inv1;
        __nv_bfloat162 h0, l0, h1, l1;
        bf16 hh, ll;
        bf16_split(x0, hh, ll); h0.x = hh; l0.x = ll;
        bf16_split(y0, hh, ll); h0.y = hh; l0.y = ll;
        bf16_split(x1, hh, ll); h1.x = hh; l1.x = ll;
        bf16_split(y1, hh, ll); h1.y = hh; l1.y = ll;
        *(__nv_bfloat162*)&Ohi[o0 + d] = h0;
        *(__nv_bfloat162*)&Olo[o0 + d] = l0;
        *(__nv_bfloat162*)&Ohi[o1 + d] = h1;
        *(__nv_bfloat162*)&Olo[o1 + d] = l1;
    }
}

// ---------------- launch ----------------
extern "C" void kernel_launch(void* const* d_in, const int* in_sizes, int n_in,
                              void* d_out, int out_size)
{
    const float* x  = (const float*)d_in[0];
    const float* Wq = (const float*)d_in[1];
    const float* bq = (const float*)d_in[2];
    const float* Wk = (const float*)d_in[3];
    const float* bk = (const float*)d_in[4];
    const float* Wv = (const float*)d_in[5];
    const float* bv = (const float*)d_in[6];
    const float* Wo = (const float*)d_in[7];
    const float* bo = (const float*)d_in[8];
    float* out = (float*)d_out;

    __half *gq, *gk, *gv;
    bf16 *gxh, *gxl, *gah, *gal;
    bf16 *wqh, *wql, *wkh, *wkl, *wvh, *wvl, *woh, *wol;
    cudaGetSymbolAddress((void**)&gq,  g_q);
    cudaGetSymbolAddress((void**)&gk,  g_k);
    cudaGetSymbolAddress((void**)&gv,  g_v);
    cudaGetSymbolAddress((void**)&gxh, g_xh);
    cudaGetSymbolAddress((void**)&gxl, g_xl);
    cudaGetSymbolAddress((void**)&gah, g_aoh);
    cudaGetSymbolAddress((void**)&gal, g_aol);
    cudaGetSymbolAddress((void**)&wqh, g_wqh);
    cudaGetSymbolAddress((void**)&wql, g_wql);
    cudaGetSymbolAddress((void**)&wkh, g_wkh);
    cudaGetSymbolAddress((void**)&wkl, g_wkl);
    cudaGetSymbolAddress((void**)&wvh, g_wvh);
    cudaGetSymbolAddress((void**)&wvl, g_wvl);
    cudaGetSymbolAddress((void**)&woh, g_woh);
    cudaGetSymbolAddress((void**)&wol, g_wol);

    cudaFuncSetAttribute(gemm3_bf16, cudaFuncAttributeMaxDynamicSharedMemorySize,
                         B_SMEM);
    cudaFuncSetAttribute(attn_mma, cudaFuncAttributeMaxDynamicSharedMemorySize,
                         A_SMEM);

    split_all_kernel<<<(NTASK + 255) / 256, 256>>>(
        x, Wq, Wk, Wv, Wo, gxh, gxl,
        wqh, wql, wkh, wkl, wvh, wvl, woh, wol);

    dim3 gqkv(DMODEL / 128, MROWS / 128, 3);
    gemm3_bf16<<<gqkv, 256, B_SMEM>>>(gxh, gxl,
                                      wqh, wql, bq, gq,
                                      wkh, wkl, bk, gk,
                                      wvh, wvl, bv, gv, 1, 2, 3);

    attn_mma<<<dim3(SEQ / 128, BATCH * NHEAD), 256, A_SMEM>>>(gq, gk, gv, gah, gal);

    dim3 go(DMODEL / 128, MROWS / 128, 1);
    gemm3_bf16<<<go, 256, B_SMEM>>>(gah, gal,
                                    woh, wol, bo, out,
                                    woh, wol, bo, out,
                                    woh, wol, bo, out, 0, 0, 0);
}